// round 2
// baseline (speedup 1.0000x reference)
#include <cuda_runtime.h>
#include <math.h>

// ---------------- problem constants ----------------
#define LNUM 4
#define BB   4
#define TT   2048
#define DD   1024
#define HH   1024
#define FF   256
#define MTOT (BB*TT)          // 8192
#define NCHUNK 16
#define CL   (TT/NCHUNK)      // 128

// ---------------- GEMM tile config ----------------
#define BM 128
#define BN 128
#define BK 16

// ---------------- scratch (device globals; no allocs allowed) ----------------
__device__ float g_xn[MTOT*DD];          // 32 MB
__device__ float g_bu[MTOT*2*HH];        // 64 MB
__device__ float g_hs[MTOT*2*HH];        // 64 MB
__device__ float g_y [MTOT*DD];          // 32 MB
__device__ float g_g [MTOT*2*DD];        // 64 MB
__device__ float g_lam_re[LNUM*HH];
__device__ float g_lam_im[LNUM*HH];
__device__ float g_gam  [LNUM*HH];
__device__ float g_sum_re[BB*NCHUNK*HH];
__device__ float g_sum_im[BB*NCHUNK*HH];
__device__ float g_car_re[BB*NCHUNK*HH];
__device__ float g_car_im[BB*NCHUNK*HH];

// ---------------- f32x2 helpers ----------------
__device__ __forceinline__ unsigned long long pk2(float x, float y) {
    unsigned long long r;
    asm("mov.b64 %0, {%1, %2};" : "=l"(r) : "f"(x), "f"(y));
    return r;
}
__device__ __forceinline__ unsigned long long fma2(unsigned long long a,
                                                   unsigned long long b,
                                                   unsigned long long c) {
    unsigned long long d;
    asm("fma.rn.f32x2 %0, %1, %2, %3;" : "=l"(d) : "l"(a), "l"(b), "l"(c));
    return d;
}

__device__ __forceinline__ float gelu_exact(float v) {
    return 0.5f * v * (1.0f + erff(v * 0.70710678118654752f));
}

// ---------------- parameter prep ----------------
__global__ void prep_kernel(const float* __restrict__ nu_log,
                            const float* __restrict__ theta_log) {
    int i = blockIdx.x * blockDim.x + threadIdx.x;   // L*H
    float nu = expf(nu_log[i]);
    float th = expf(theta_log[i]);
    float r  = expf(-nu);
    g_lam_re[i] = r * cosf(th);
    g_lam_im[i] = r * sinf(th);
    g_gam[i]    = sqrtf(1.0f - expf(-2.0f * nu) + 1e-5f);
}

// ---------------- layernorm ----------------
__global__ void ln_kernel(const float* __restrict__ x,
                          const float* __restrict__ sc,
                          const float* __restrict__ bi,
                          float* __restrict__ o) {
    __shared__ float red[16];
    int row = blockIdx.x;
    int tid = threadIdx.x;
    const float* xr = x + (size_t)row * DD;
    float4 v = *(const float4*)(xr + tid * 4);
    float s  = v.x + v.y + v.z + v.w;
    float ss = v.x*v.x + v.y*v.y + v.z*v.z + v.w*v.w;
    #pragma unroll
    for (int off = 16; off; off >>= 1) {
        s  += __shfl_xor_sync(0xffffffffu, s,  off);
        ss += __shfl_xor_sync(0xffffffffu, ss, off);
    }
    int wid = tid >> 5;
    if ((tid & 31) == 0) { red[wid] = s; red[8 + wid] = ss; }
    __syncthreads();
    float S = 0.f, SS = 0.f;
    #pragma unroll
    for (int w = 0; w < 8; w++) { S += red[w]; SS += red[8 + w]; }
    float mu  = S * (1.0f / DD);
    float var = SS * (1.0f / DD) - mu * mu;
    float rstd = rsqrtf(var + 1e-5f);
    float4 s4 = *(const float4*)(sc + tid * 4);
    float4 b4 = *(const float4*)(bi + tid * 4);
    float4 ov;
    ov.x = (v.x - mu) * rstd * s4.x + b4.x;
    ov.y = (v.y - mu) * rstd * s4.y + b4.y;
    ov.z = (v.z - mu) * rstd * s4.z + b4.z;
    ov.w = (v.w - mu) * rstd * s4.w + b4.w;
    *(float4*)(o + (size_t)row * DD + tid * 4) = ov;
}

// ---------------- generic fp32 GEMM:  C[m,n] = sum_k A[m,k] * W(n,k)  ----------------
// W(n,k) resolved via optional N-split (two weight matrices stacked over n) or
// K-split (two weight matrices concatenated over k, second multiplied by w1sign).
// epi: 0 = +bias (per-n, split like W)   1 = *epi_n[n & (HH-1)]   2 = gelu(acc + epi_m[m,n]*epi_n[n])
__global__ __launch_bounds__(256, 2)
void gemm_f32(const float* __restrict__ A, int lda,
              const float* __restrict__ W0, const float* __restrict__ W1,
              int ldw, int nsplit, int ksplit, float w1sign,
              const float* __restrict__ bias0, const float* __restrict__ bias1,
              float* __restrict__ C, int ldc,
              int K,
              int epi, const float* __restrict__ epi_m, const float* __restrict__ epi_n) {
    __shared__ float As[2][BK][BM + 4];
    __shared__ float Ws[2][BK][BN + 4];

    const int tid  = threadIdx.x;
    const int m0   = blockIdx.y * BM;
    const int n0   = blockIdx.x * BN;
    const int rowL = tid >> 2;          // 0..63
    const int col4 = (tid & 3) * 4;     // 0,4,8,12

    const float* biasb = nullptr;
    if (bias0)
        biasb = (nsplit && n0 >= nsplit) ? (bias1 + (n0 - nsplit)) : (bias0 + n0);

    const float* WbaseN = (nsplit && n0 >= nsplit)
                        ? (W1 + (size_t)(n0 - nsplit) * ldw)
                        : (W0 + (size_t)n0 * ldw);
    const float* Aptr = A + (size_t)m0 * lda;

    const int ntiles = K / BK;

    float4 ra[2], rw[2];
    float sgnS;
    {   // prefetch tile 0
        const float* wb; int keff;
        if (ksplit) {
            wb = W0 + (size_t)n0 * ldw; keff = 0; sgnS = 1.f;
        } else { wb = WbaseN; keff = 0; sgnS = 1.f; }
        #pragma unroll
        for (int p = 0; p < 2; p++) {
            ra[p] = *(const float4*)(Aptr + (size_t)(rowL + 64*p) * lda + col4);
            rw[p] = *(const float4*)(wb   + (size_t)(rowL + 64*p) * ldw + keff + col4);
        }
    }
    int buf = 0;
    #pragma unroll
    for (int p = 0; p < 2; p++) {
        int r = rowL + 64*p;
        As[0][col4+0][r] = ra[p].x;  As[0][col4+1][r] = ra[p].y;
        As[0][col4+2][r] = ra[p].z;  As[0][col4+3][r] = ra[p].w;
        Ws[0][col4+0][r] = sgnS*rw[p].x;  Ws[0][col4+1][r] = sgnS*rw[p].y;
        Ws[0][col4+2][r] = sgnS*rw[p].z;  Ws[0][col4+3][r] = sgnS*rw[p].w;
    }
    __syncthreads();

    unsigned long long acc[8][4];
    #pragma unroll
    for (int i = 0; i < 8; i++)
        #pragma unroll
        for (int j = 0; j < 4; j++) acc[i][j] = 0ULL;

    const int ty = tid >> 4, tx = tid & 15;

    for (int t = 0; t < ntiles; t++) {
        float sgn = 1.f;
        if (t + 1 < ntiles) {
            int k0 = (t + 1) * BK;
            const float* wb; int keff;
            if (ksplit && k0 >= ksplit) { wb = W1 + (size_t)n0 * ldw; keff = k0 - ksplit; sgn = w1sign; }
            else if (ksplit)            { wb = W0 + (size_t)n0 * ldw; keff = k0; }
            else                        { wb = WbaseN;                keff = k0; }
            #pragma unroll
            for (int p = 0; p < 2; p++) {
                ra[p] = *(const float4*)(Aptr + (size_t)(rowL + 64*p) * lda + k0 + col4);
                rw[p] = *(const float4*)(wb   + (size_t)(rowL + 64*p) * ldw + keff + col4);
            }
        }
        #pragma unroll
        for (int kk = 0; kk < BK; kk++) {
            float4 a0 = *(const float4*)&As[buf][kk][ty*8];
            float4 a1 = *(const float4*)&As[buf][kk][ty*8 + 4];
            ulonglong2 w01 = *(const ulonglong2*)&Ws[buf][kk][tx*8];
            ulonglong2 w23 = *(const ulonglong2*)&Ws[buf][kk][tx*8 + 4];
            unsigned long long bb0 = w01.x, bb1 = w01.y, bb2 = w23.x, bb3 = w23.y;
            float av[8] = {a0.x, a0.y, a0.z, a0.w, a1.x, a1.y, a1.z, a1.w};
            #pragma unroll
            for (int i = 0; i < 8; i++) {
                unsigned long long ai = pk2(av[i], av[i]);
                acc[i][0] = fma2(ai, bb0, acc[i][0]);
                acc[i][1] = fma2(ai, bb1, acc[i][1]);
                acc[i][2] = fma2(ai, bb2, acc[i][2]);
                acc[i][3] = fma2(ai, bb3, acc[i][3]);
            }
        }
        if (t + 1 < ntiles) {
            int nb = buf ^ 1;
            #pragma unroll
            for (int p = 0; p < 2; p++) {
                int r = rowL + 64*p;
                As[nb][col4+0][r] = ra[p].x;  As[nb][col4+1][r] = ra[p].y;
                As[nb][col4+2][r] = ra[p].z;  As[nb][col4+3][r] = ra[p].w;
                Ws[nb][col4+0][r] = sgn*rw[p].x;  Ws[nb][col4+1][r] = sgn*rw[p].y;
                Ws[nb][col4+2][r] = sgn*rw[p].z;  Ws[nb][col4+3][r] = sgn*rw[p].w;
            }
            __syncthreads();
            buf = nb;
        }
    }

    // ---- epilogue ----
    const int mrow = m0 + ty * 8;
    const int ncol = n0 + tx * 8;
    #pragma unroll
    for (int i = 0; i < 8; i++) {
        float c[8];
        #pragma unroll
        for (int j = 0; j < 4; j++) {
            union { unsigned long long u; float2 f; } cv;
            cv.u = acc[i][j];
            c[2*j]   = cv.f.x;
            c[2*j+1] = cv.f.y;
        }
        int gm = mrow + i;
        if (epi == 0) {
            if (biasb) {
                #pragma unroll
                for (int j = 0; j < 8; j++) c[j] += biasb[tx*8 + j];
            }
        } else if (epi == 1) {
            #pragma unroll
            for (int j = 0; j < 8; j++) c[j] *= epi_n[(ncol + j) & (HH - 1)];
        } else {
            #pragma unroll
            for (int j = 0; j < 8; j++) {
                float v = c[j] + epi_m[(size_t)gm * DD + ncol + j] * epi_n[ncol + j];
                c[j] = gelu_exact(v);
            }
        }
        *(float4*)(C + (size_t)gm * ldc + ncol)     = make_float4(c[0], c[1], c[2], c[3]);
        *(float4*)(C + (size_t)gm * ldc + ncol + 4) = make_float4(c[4], c[5], c[6], c[7]);
    }
}

// ---------------- scan: pass 1 (chunk-local summaries) ----------------
__global__ void scan_sum_kernel(const float* __restrict__ bu, int loff) {
    int h = blockIdx.x * blockDim.x + threadIdx.x;
    int c = blockIdx.y, b = blockIdx.z;
    float lre = g_lam_re[loff + h], lim = g_lam_im[loff + h];
    size_t base = ((size_t)(b * TT + c * CL)) * (2 * HH) + h;
    float are = 0.f, aim = 0.f;
    #pragma unroll 8
    for (int j = 0; j < CL; j++) {
        float ure = bu[base], uim = bu[base + HH];
        float nr = fmaf(are, lre, fmaf(-aim, lim, ure));
        float ni = fmaf(are, lim, fmaf(aim, lre, uim));
        are = nr; aim = ni;
        base += 2 * HH;
    }
    int o = (b * NCHUNK + c) * HH + h;
    g_sum_re[o] = are; g_sum_im[o] = aim;
}

// ---------------- scan: pass 2 (carry scan over chunks) ----------------
__global__ void scan_carry_kernel(int loff) {
    int idx = blockIdx.x * blockDim.x + threadIdx.x;  // B*H
    int b = idx >> 10, h = idx & (HH - 1);
    float lre = g_lam_re[loff + h], lim = g_lam_im[loff + h];
    float pre = lre, pim = lim;
    #pragma unroll
    for (int i = 0; i < 7; i++) {   // lam^128
        float nr = pre*pre - pim*pim;
        float ni = 2.f*pre*pim;
        pre = nr; pim = ni;
    }
    float cre = 0.f, cim = 0.f;
    #pragma unroll
    for (int c = 0; c < NCHUNK; c++) {
        int o = (b * NCHUNK + c) * HH + h;
        g_car_re[o] = cre; g_car_im[o] = cim;
        float sre = g_sum_re[o], sim = g_sum_im[o];
        float nr = cre*pre - cim*pim + sre;
        float ni = cre*pim + cim*pre + sim;
        cre = nr; cim = ni;
    }
}

// ---------------- scan: pass 3 (apply with correct carry, write hs) ----------------
__global__ void scan_apply_kernel(const float* __restrict__ bu,
                                  float* __restrict__ hs, int loff) {
    int h = blockIdx.x * blockDim.x + threadIdx.x;
    int c = blockIdx.y, b = blockIdx.z;
    float lre = g_lam_re[loff + h], lim = g_lam_im[loff + h];
    int o = (b * NCHUNK + c) * HH + h;
    float are = g_car_re[o], aim = g_car_im[o];
    size_t base = ((size_t)(b * TT + c * CL)) * (2 * HH) + h;
    #pragma unroll 8
    for (int j = 0; j < CL; j++) {
        float ure = bu[base], uim = bu[base + HH];
        float nr = fmaf(are, lre, fmaf(-aim, lim, ure));
        float ni = fmaf(are, lim, fmaf(aim, lre, uim));
        are = nr; aim = ni;
        hs[base]      = are;
        hs[base + HH] = aim;
        base += 2 * HH;
    }
}

// ---------------- GLU combine + residual:  x += g1 * sigmoid(g2) ----------------
__global__ void glu_combine_kernel(const float* __restrict__ g, float* __restrict__ x) {
    int i = blockIdx.x * blockDim.x + threadIdx.x;   // over MTOT*DD/4
    int m  = i / (DD / 4);
    int c4 = (i % (DD / 4)) * 4;
    const float* gr = g + (size_t)m * (2 * DD);
    float4 a  = *(const float4*)(gr + c4);
    float4 bq = *(const float4*)(gr + DD + c4);
    float4 xo = *(float4*)(x + (size_t)m * DD + c4);
    xo.x = fmaf(a.x, 1.f / (1.f + expf(-bq.x)), xo.x);
    xo.y = fmaf(a.y, 1.f / (1.f + expf(-bq.y)), xo.y);
    xo.z = fmaf(a.z, 1.f / (1.f + expf(-bq.z)), xo.z);
    xo.w = fmaf(a.w, 1.f / (1.f + expf(-bq.w)), xo.w);
    *(float4*)(x + (size_t)m * DD + c4) = xo;
}

// ---------------- launch ----------------
extern "C" void kernel_launch(void* const* d_in, const int* in_sizes, int n_in,
                              void* d_out, int out_size) {
    const float* inputs    = (const float*)d_in[0];
    const float* W_in      = (const float*)d_in[1];
    const float* b_in      = (const float*)d_in[2];
    const float* nu_log    = (const float*)d_in[3];
    const float* theta_log = (const float*)d_in[4];
    const float* B_re      = (const float*)d_in[5];
    const float* B_im      = (const float*)d_in[6];
    const float* C_re      = (const float*)d_in[7];
    const float* C_im      = (const float*)d_in[8];
    const float* D_diag    = (const float*)d_in[9];
    const float* ln_scale  = (const float*)d_in[10];
    const float* ln_bias   = (const float*)d_in[11];
    const float* w1        = (const float*)d_in[12];
    const float* b1        = (const float*)d_in[13];
    const float* w2        = (const float*)d_in[14];
    const float* b2        = (const float*)d_in[15];
    float* x = (float*)d_out;

    float *p_xn, *p_bu, *p_hs, *p_y, *p_g, *p_gam;
    cudaGetSymbolAddress((void**)&p_xn,  g_xn);
    cudaGetSymbolAddress((void**)&p_bu,  g_bu);
    cudaGetSymbolAddress((void**)&p_hs,  g_hs);
    cudaGetSymbolAddress((void**)&p_y,   g_y);
    cudaGetSymbolAddress((void**)&p_g,   g_g);
    cudaGetSymbolAddress((void**)&p_gam, g_gam);

    // params
    prep_kernel<<<(LNUM * HH) / 256, 256>>>(nu_log, theta_log);

    // input projection: x = inputs @ W_in^T + b_in   (M=8192, N=1024, K=256)
    gemm_f32<<<dim3(DD / BN, MTOT / BM), 256>>>(
        inputs, FF, W_in, nullptr, FF, 0, 0, 1.f,
        b_in, nullptr, x, DD, FF, 0, nullptr, nullptr);

    for (int l = 0; l < LNUM; l++) {
        // layernorm
        ln_kernel<<<MTOT, 256>>>(x, ln_scale + l * DD, ln_bias + l * DD, p_xn);

        // Bu = gamma * (xn @ [B_re;B_im]^T)   (N=2048, K=1024, N-split at 1024, epi=gamma scale)
        gemm_f32<<<dim3(2 * HH / BN, MTOT / BM), 256>>>(
            p_xn, DD,
            B_re + (size_t)l * HH * DD, B_im + (size_t)l * HH * DD, DD,
            HH, 0, 1.f, nullptr, nullptr,
            p_bu, 2 * HH, DD, 1, nullptr, p_gam + l * HH);

        // scan
        scan_sum_kernel  <<<dim3(HH / 256, NCHUNK, BB), 256>>>(p_bu, l * HH);
        scan_carry_kernel<<<(BB * HH) / 256, 256>>>(l * HH);
        scan_apply_kernel<<<dim3(HH / 256, NCHUNK, BB), 256>>>(p_bu, p_hs, l * HH);

        // y = gelu( hs @ [C_re | -C_im]^T + xn * D_diag )   (N=1024, K=2048, K-split at 1024)
        gemm_f32<<<dim3(DD / BN, MTOT / BM), 256>>>(
            p_hs, 2 * HH,
            C_re + (size_t)l * DD * HH, C_im + (size_t)l * DD * HH, HH,
            0, HH, -1.f, nullptr, nullptr,
            p_y, DD, 2 * HH, 2, p_xn, D_diag + l * DD);

        // g = y @ [w1;w2]^T + [b1;b2]   (N=2048, K=1024, N-split at 1024)
        gemm_f32<<<dim3(2 * DD / BN, MTOT / BM), 256>>>(
            p_y, DD,
            w1 + (size_t)l * DD * DD, w2 + (size_t)l * DD * DD, DD,
            DD, 0, 1.f, b1 + l * DD, b2 + l * DD,
            p_g, 2 * DD, DD, 0, nullptr, nullptr);

        // x += g1 * sigmoid(g2)
        glu_combine_kernel<<<(MTOT * DD / 4) / 256, 256>>>(p_g, x);
    }
    (void)in_sizes; (void)n_in; (void)out_size;
}

// round 3
// speedup vs baseline: 1.0005x; 1.0005x over previous
#include <cuda_runtime.h>
#include <math.h>

// ---------------- problem constants ----------------
#define LNUM 4
#define BB   4
#define TT   2048
#define DD   1024
#define HH   1024
#define FF   256
#define MTOT (BB*TT)          // 8192
#define NCHUNK 16
#define CL   (TT/NCHUNK)      // 128

// ---------------- GEMM tile config ----------------
#define BM 128
#define BN 128
#define BK 16

// ---------------- scratch (device globals; no allocs allowed) ----------------
__device__ float g_xn[MTOT*DD];          // 32 MB
__device__ float g_bu[MTOT*2*HH];        // 64 MB
__device__ float g_hs[MTOT*2*HH];        // 64 MB
__device__ float g_y [MTOT*DD];          // 32 MB
__device__ float g_g [MTOT*2*DD];        // 64 MB
__device__ float g_lam_re[LNUM*HH];
__device__ float g_lam_im[LNUM*HH];
__device__ float g_gam  [LNUM*HH];
__device__ float g_sum_re[BB*NCHUNK*HH];
__device__ float g_sum_im[BB*NCHUNK*HH];
__device__ float g_car_re[BB*NCHUNK*HH];
__device__ float g_car_im[BB*NCHUNK*HH];

// ---------------- f32x2 helpers ----------------
__device__ __forceinline__ unsigned long long pk2(float x, float y) {
    unsigned long long r;
    asm("mov.b64 %0, {%1, %2};" : "=l"(r) : "f"(x), "f"(y));
    return r;
}
__device__ __forceinline__ unsigned long long fma2(unsigned long long a,
                                                   unsigned long long b,
                                                   unsigned long long c) {
    unsigned long long d;
    asm("fma.rn.f32x2 %0, %1, %2, %3;" : "=l"(d) : "l"(a), "l"(b), "l"(c));
    return d;
}

__device__ __forceinline__ float gelu_exact(float v) {
    return 0.5f * v * (1.0f + erff(v * 0.70710678118654752f));
}

// ---------------- parameter prep ----------------
__global__ void prep_kernel(const float* __restrict__ nu_log,
                            const float* __restrict__ theta_log) {
    int i = blockIdx.x * blockDim.x + threadIdx.x;   // L*H
    float nu = expf(nu_log[i]);
    float th = expf(theta_log[i]);
    float r  = expf(-nu);
    g_lam_re[i] = r * cosf(th);
    g_lam_im[i] = r * sinf(th);
    g_gam[i]    = sqrtf(1.0f - expf(-2.0f * nu) + 1e-5f);
}

// ---------------- layernorm ----------------
__global__ void ln_kernel(const float* __restrict__ x,
                          const float* __restrict__ sc,
                          const float* __restrict__ bi,
                          float* __restrict__ o) {
    __shared__ float red[16];
    int row = blockIdx.x;
    int tid = threadIdx.x;
    const float* xr = x + (size_t)row * DD;
    float4 v = *(const float4*)(xr + tid * 4);
    float s  = v.x + v.y + v.z + v.w;
    float ss = v.x*v.x + v.y*v.y + v.z*v.z + v.w*v.w;
    #pragma unroll
    for (int off = 16; off; off >>= 1) {
        s  += __shfl_xor_sync(0xffffffffu, s,  off);
        ss += __shfl_xor_sync(0xffffffffu, ss, off);
    }
    int wid = tid >> 5;
    if ((tid & 31) == 0) { red[wid] = s; red[8 + wid] = ss; }
    __syncthreads();
    float S = 0.f, SS = 0.f;
    #pragma unroll
    for (int w = 0; w < 8; w++) { S += red[w]; SS += red[8 + w]; }
    float mu  = S * (1.0f / DD);
    float var = SS * (1.0f / DD) - mu * mu;
    float rstd = rsqrtf(var + 1e-5f);
    float4 s4 = *(const float4*)(sc + tid * 4);
    float4 b4 = *(const float4*)(bi + tid * 4);
    float4 ov;
    ov.x = (v.x - mu) * rstd * s4.x + b4.x;
    ov.y = (v.y - mu) * rstd * s4.y + b4.y;
    ov.z = (v.z - mu) * rstd * s4.z + b4.z;
    ov.w = (v.w - mu) * rstd * s4.w + b4.w;
    *(float4*)(o + (size_t)row * DD + tid * 4) = ov;
}

// ---------------- generic fp32 GEMM:  C[m,n] = sum_k A[m,k] * W(n,k)  ----------------
// W(n,k) resolved via optional N-split (two weight matrices stacked over n) or
// K-split (two weight matrices concatenated over k, second multiplied by w1sign).
// epi: 0 = +bias (per-n, split like W)   1 = *epi_n[n & (HH-1)]   2 = gelu(acc + epi_m[m,n]*epi_n[n])
__global__ __launch_bounds__(256, 2)
void gemm_f32(const float* __restrict__ A, int lda,
              const float* __restrict__ W0, const float* __restrict__ W1,
              int ldw, int nsplit, int ksplit, float w1sign,
              const float* __restrict__ bias0, const float* __restrict__ bias1,
              float* __restrict__ C, int ldc,
              int K,
              int epi, const float* __restrict__ epi_m, const float* __restrict__ epi_n) {
    __shared__ float As[2][BK][BM + 4];
    __shared__ float Ws[2][BK][BN + 4];

    const int tid  = threadIdx.x;
    const int m0   = blockIdx.y * BM;
    const int n0   = blockIdx.x * BN;
    const int rowL = tid >> 2;          // 0..63
    const int col4 = (tid & 3) * 4;     // 0,4,8,12

    const float* biasb = nullptr;
    if (bias0)
        biasb = (nsplit && n0 >= nsplit) ? (bias1 + (n0 - nsplit)) : (bias0 + n0);

    const float* WbaseN = (nsplit && n0 >= nsplit)
                        ? (W1 + (size_t)(n0 - nsplit) * ldw)
                        : (W0 + (size_t)n0 * ldw);
    const float* Aptr = A + (size_t)m0 * lda;

    const int ntiles = K / BK;

    float4 ra[2], rw[2];
    float sgnS;
    {   // prefetch tile 0
        const float* wb; int keff;
        if (ksplit) {
            wb = W0 + (size_t)n0 * ldw; keff = 0; sgnS = 1.f;
        } else { wb = WbaseN; keff = 0; sgnS = 1.f; }
        #pragma unroll
        for (int p = 0; p < 2; p++) {
            ra[p] = *(const float4*)(Aptr + (size_t)(rowL + 64*p) * lda + col4);
            rw[p] = *(const float4*)(wb   + (size_t)(rowL + 64*p) * ldw + keff + col4);
        }
    }
    int buf = 0;
    #pragma unroll
    for (int p = 0; p < 2; p++) {
        int r = rowL + 64*p;
        As[0][col4+0][r] = ra[p].x;  As[0][col4+1][r] = ra[p].y;
        As[0][col4+2][r] = ra[p].z;  As[0][col4+3][r] = ra[p].w;
        Ws[0][col4+0][r] = sgnS*rw[p].x;  Ws[0][col4+1][r] = sgnS*rw[p].y;
        Ws[0][col4+2][r] = sgnS*rw[p].z;  Ws[0][col4+3][r] = sgnS*rw[p].w;
    }
    __syncthreads();

    unsigned long long acc[8][4];
    #pragma unroll
    for (int i = 0; i < 8; i++)
        #pragma unroll
        for (int j = 0; j < 4; j++) acc[i][j] = 0ULL;

    const int ty = tid >> 4, tx = tid & 15;

    for (int t = 0; t < ntiles; t++) {
        float sgn = 1.f;
        if (t + 1 < ntiles) {
            int k0 = (t + 1) * BK;
            const float* wb; int keff;
            if (ksplit && k0 >= ksplit) { wb = W1 + (size_t)n0 * ldw; keff = k0 - ksplit; sgn = w1sign; }
            else if (ksplit)            { wb = W0 + (size_t)n0 * ldw; keff = k0; }
            else                        { wb = WbaseN;                keff = k0; }
            #pragma unroll
            for (int p = 0; p < 2; p++) {
                ra[p] = *(const float4*)(Aptr + (size_t)(rowL + 64*p) * lda + k0 + col4);
                rw[p] = *(const float4*)(wb   + (size_t)(rowL + 64*p) * ldw + keff + col4);
            }
        }
        #pragma unroll
        for (int kk = 0; kk < BK; kk++) {
            float4 a0 = *(const float4*)&As[buf][kk][ty*8];
            float4 a1 = *(const float4*)&As[buf][kk][ty*8 + 4];
            ulonglong2 w01 = *(const ulonglong2*)&Ws[buf][kk][tx*8];
            ulonglong2 w23 = *(const ulonglong2*)&Ws[buf][kk][tx*8 + 4];
            unsigned long long bb0 = w01.x, bb1 = w01.y, bb2 = w23.x, bb3 = w23.y;
            float av[8] = {a0.x, a0.y, a0.z, a0.w, a1.x, a1.y, a1.z, a1.w};
            #pragma unroll
            for (int i = 0; i < 8; i++) {
                unsigned long long ai = pk2(av[i], av[i]);
                acc[i][0] = fma2(ai, bb0, acc[i][0]);
                acc[i][1] = fma2(ai, bb1, acc[i][1]);
                acc[i][2] = fma2(ai, bb2, acc[i][2]);
                acc[i][3] = fma2(ai, bb3, acc[i][3]);
            }
        }
        if (t + 1 < ntiles) {
            int nb = buf ^ 1;
            #pragma unroll
            for (int p = 0; p < 2; p++) {
                int r = rowL + 64*p;
                As[nb][col4+0][r] = ra[p].x;  As[nb][col4+1][r] = ra[p].y;
                As[nb][col4+2][r] = ra[p].z;  As[nb][col4+3][r] = ra[p].w;
                Ws[nb][col4+0][r] = sgn*rw[p].x;  Ws[nb][col4+1][r] = sgn*rw[p].y;
                Ws[nb][col4+2][r] = sgn*rw[p].z;  Ws[nb][col4+3][r] = sgn*rw[p].w;
            }
            __syncthreads();
            buf = nb;
        }
    }

    // ---- epilogue ----
    const int mrow = m0 + ty * 8;
    const int ncol = n0 + tx * 8;
    #pragma unroll
    for (int i = 0; i < 8; i++) {
        float c[8];
        #pragma unroll
        for (int j = 0; j < 4; j++) {
            union { unsigned long long u; float2 f; } cv;
            cv.u = acc[i][j];
            c[2*j]   = cv.f.x;
            c[2*j+1] = cv.f.y;
        }
        int gm = mrow + i;
        if (epi == 0) {
            if (biasb) {
                #pragma unroll
                for (int j = 0; j < 8; j++) c[j] += biasb[tx*8 + j];
            }
        } else if (epi == 1) {
            #pragma unroll
            for (int j = 0; j < 8; j++) c[j] *= epi_n[(ncol + j) & (HH - 1)];
        } else {
            #pragma unroll
            for (int j = 0; j < 8; j++) {
                float v = c[j] + epi_m[(size_t)gm * DD + ncol + j] * epi_n[ncol + j];
                c[j] = gelu_exact(v);
            }
        }
        *(float4*)(C + (size_t)gm * ldc + ncol)     = make_float4(c[0], c[1], c[2], c[3]);
        *(float4*)(C + (size_t)gm * ldc + ncol + 4) = make_float4(c[4], c[5], c[6], c[7]);
    }
}

// ---------------- scan: pass 1 (chunk-local summaries) ----------------
__global__ void scan_sum_kernel(const float* __restrict__ bu, int loff) {
    int h = blockIdx.x * blockDim.x + threadIdx.x;
    int c = blockIdx.y, b = blockIdx.z;
    float lre = g_lam_re[loff + h], lim = g_lam_im[loff + h];
    size_t base = ((size_t)(b * TT + c * CL)) * (2 * HH) + h;
    float are = 0.f, aim = 0.f;
    #pragma unroll 8
    for (int j = 0; j < CL; j++) {
        float ure = bu[base], uim = bu[base + HH];
        float nr = fmaf(are, lre, fmaf(-aim, lim, ure));
        float ni = fmaf(are, lim, fmaf(aim, lre, uim));
        are = nr; aim = ni;
        base += 2 * HH;
    }
    int o = (b * NCHUNK + c) * HH + h;
    g_sum_re[o] = are; g_sum_im[o] = aim;
}

// ---------------- scan: pass 2 (carry scan over chunks) ----------------
__global__ void scan_carry_kernel(int loff) {
    int idx = blockIdx.x * blockDim.x + threadIdx.x;  // B*H
    int b = idx >> 10, h = idx & (HH - 1);
    float lre = g_lam_re[loff + h], lim = g_lam_im[loff + h];
    float pre = lre, pim = lim;
    #pragma unroll
    for (int i = 0; i < 7; i++) {   // lam^128
        float nr = pre*pre - pim*pim;
        float ni = 2.f*pre*pim;
        pre = nr; pim = ni;
    }
    float cre = 0.f, cim = 0.f;
    #pragma unroll
    for (int c = 0; c < NCHUNK; c++) {
        int o = (b * NCHUNK + c) * HH + h;
        g_car_re[o] = cre; g_car_im[o] = cim;
        float sre = g_sum_re[o], sim = g_sum_im[o];
        float nr = cre*pre - cim*pim + sre;
        float ni = cre*pim + cim*pre + sim;
        cre = nr; cim = ni;
    }
}

// ---------------- scan: pass 3 (apply with correct carry, write hs) ----------------
__global__ void scan_apply_kernel(const float* __restrict__ bu,
                                  float* __restrict__ hs, int loff) {
    int h = blockIdx.x * blockDim.x + threadIdx.x;
    int c = blockIdx.y, b = blockIdx.z;
    float lre = g_lam_re[loff + h], lim = g_lam_im[loff + h];
    int o = (b * NCHUNK + c) * HH + h;
    float are = g_car_re[o], aim = g_car_im[o];
    size_t base = ((size_t)(b * TT + c * CL)) * (2 * HH) + h;
    #pragma unroll 8
    for (int j = 0; j < CL; j++) {
        float ure = bu[base], uim = bu[base + HH];
        float nr = fmaf(are, lre, fmaf(-aim, lim, ure));
        float ni = fmaf(are, lim, fmaf(aim, lre, uim));
        are = nr; aim = ni;
        hs[base]      = are;
        hs[base + HH] = aim;
        base += 2 * HH;
    }
}

// ---------------- GLU combine + residual:  x += g1 * sigmoid(g2) ----------------
__global__ void glu_combine_kernel(const float* __restrict__ g, float* __restrict__ x) {
    int i = blockIdx.x * blockDim.x + threadIdx.x;   // over MTOT*DD/4
    int m  = i / (DD / 4);
    int c4 = (i % (DD / 4)) * 4;
    const float* gr = g + (size_t)m * (2 * DD);
    float4 a  = *(const float4*)(gr + c4);
    float4 bq = *(const float4*)(gr + DD + c4);
    float4 xo = *(float4*)(x + (size_t)m * DD + c4);
    xo.x = fmaf(a.x, 1.f / (1.f + expf(-bq.x)), xo.x);
    xo.y = fmaf(a.y, 1.f / (1.f + expf(-bq.y)), xo.y);
    xo.z = fmaf(a.z, 1.f / (1.f + expf(-bq.z)), xo.z);
    xo.w = fmaf(a.w, 1.f / (1.f + expf(-bq.w)), xo.w);
    *(float4*)(x + (size_t)m * DD + c4) = xo;
}

// ---------------- launch ----------------
extern "C" void kernel_launch(void* const* d_in, const int* in_sizes, int n_in,
                              void* d_out, int out_size) {
    const float* inputs    = (const float*)d_in[0];
    const float* W_in      = (const float*)d_in[1];
    const float* b_in      = (const float*)d_in[2];
    const float* nu_log    = (const float*)d_in[3];
    const float* theta_log = (const float*)d_in[4];
    const float* B_re      = (const float*)d_in[5];
    const float* B_im      = (const float*)d_in[6];
    const float* C_re      = (const float*)d_in[7];
    const float* C_im      = (const float*)d_in[8];
    const float* D_diag    = (const float*)d_in[9];
    const float* ln_scale  = (const float*)d_in[10];
    const float* ln_bias   = (const float*)d_in[11];
    const float* w1        = (const float*)d_in[12];
    const float* b1        = (const float*)d_in[13];
    const float* w2        = (const float*)d_in[14];
    const float* b2        = (const float*)d_in[15];
    float* x = (float*)d_out;

    float *p_xn, *p_bu, *p_hs, *p_y, *p_g, *p_gam;
    cudaGetSymbolAddress((void**)&p_xn,  g_xn);
    cudaGetSymbolAddress((void**)&p_bu,  g_bu);
    cudaGetSymbolAddress((void**)&p_hs,  g_hs);
    cudaGetSymbolAddress((void**)&p_y,   g_y);
    cudaGetSymbolAddress((void**)&p_g,   g_g);
    cudaGetSymbolAddress((void**)&p_gam, g_gam);

    // params
    prep_kernel<<<(LNUM * HH) / 256, 256>>>(nu_log, theta_log);

    // input projection: x = inputs @ W_in^T + b_in   (M=8192, N=1024, K=256)
    gemm_f32<<<dim3(DD / BN, MTOT / BM), 256>>>(
        inputs, FF, W_in, nullptr, FF, 0, 0, 1.f,
        b_in, nullptr, x, DD, FF, 0, nullptr, nullptr);

    for (int l = 0; l < LNUM; l++) {
        // layernorm
        ln_kernel<<<MTOT, 256>>>(x, ln_scale + l * DD, ln_bias + l * DD, p_xn);

        // Bu = gamma * (xn @ [B_re;B_im]^T)   (N=2048, K=1024, N-split at 1024, epi=gamma scale)
        gemm_f32<<<dim3(2 * HH / BN, MTOT / BM), 256>>>(
            p_xn, DD,
            B_re + (size_t)l * HH * DD, B_im + (size_t)l * HH * DD, DD,
            HH, 0, 1.f, nullptr, nullptr,
            p_bu, 2 * HH, DD, 1, nullptr, p_gam + l * HH);

        // scan
        scan_sum_kernel  <<<dim3(HH / 256, NCHUNK, BB), 256>>>(p_bu, l * HH);
        scan_carry_kernel<<<(BB * HH) / 256, 256>>>(l * HH);
        scan_apply_kernel<<<dim3(HH / 256, NCHUNK, BB), 256>>>(p_bu, p_hs, l * HH);

        // y = gelu( hs @ [C_re | -C_im]^T + xn * D_diag )   (N=1024, K=2048, K-split at 1024)
        gemm_f32<<<dim3(DD / BN, MTOT / BM), 256>>>(
            p_hs, 2 * HH,
            C_re + (size_t)l * DD * HH, C_im + (size_t)l * DD * HH, HH,
            0, HH, -1.f, nullptr, nullptr,
            p_y, DD, 2 * HH, 2, p_xn, D_diag + l * DD);

        // g = y @ [w1;w2]^T + [b1;b2]   (N=2048, K=1024, N-split at 1024)
        gemm_f32<<<dim3(2 * DD / BN, MTOT / BM), 256>>>(
            p_y, DD,
            w1 + (size_t)l * DD * DD, w2 + (size_t)l * DD * DD, DD,
            DD, 0, 1.f, b1 + l * DD, b2 + l * DD,
            p_g, 2 * DD, DD, 0, nullptr, nullptr);

        // x += g1 * sigmoid(g2)
        glu_combine_kernel<<<(MTOT * DD / 4) / 256, 256>>>(p_g, x);
    }
    (void)in_sizes; (void)n_in; (void)out_size;
}

// round 5
// speedup vs baseline: 2.4169x; 2.4157x over previous
#include <cuda_runtime.h>
#include <cuda_bf16.h>
#include <math.h>
#include <stdint.h>

// ---------------- problem constants ----------------
#define LNUM 4
#define BB   4
#define TT   2048
#define DD   1024
#define HH   1024
#define FF   256
#define MTOT (BB*TT)          // 8192
#define NCHUNK 16
#define CL   (TT/NCHUNK)      // 128

// ---------------- mma GEMM config ----------------
#define BKC   32                      // k elements per stage
#define ROWP  40                      // padded row length (bf16) -> 80B, conflict-free
#define MATB  (128*ROWP*2)            // bytes per matrix tile in a stage
#define STAGEB (4*MATB)               // Ah, Al, Wh, Wl
#define NST   2
#define SMEMB (NST*STAGEB)            // 81920 B

typedef __nv_bfloat16 bf16;

// ---------------- scratch (device globals; no allocs allowed) ----------------
__device__ __align__(16) float g_xn[MTOT*DD];
__device__ __align__(16) bf16  g_xn_h[MTOT*DD];
__device__ __align__(16) bf16  g_xn_l[MTOT*DD];
__device__ __align__(16) bf16  g_in_h[MTOT*FF];
__device__ __align__(16) bf16  g_in_l[MTOT*FF];
__device__ __align__(16) float g_bu[MTOT*2*HH];
__device__ __align__(16) bf16  g_hs_h[MTOT*2*HH];
__device__ __align__(16) bf16  g_hs_l[MTOT*2*HH];
__device__ __align__(16) bf16  g_y_h[MTOT*DD];
__device__ __align__(16) bf16  g_y_l[MTOT*DD];
__device__ __align__(16) float g_g[MTOT*2*DD];
__device__ __align__(16) bf16  g_win_h[DD*FF];
__device__ __align__(16) bf16  g_win_l[DD*FF];
__device__ __align__(16) bf16  g_bw_h[LNUM*2*HH*DD];
__device__ __align__(16) bf16  g_bw_l[LNUM*2*HH*DD];
__device__ __align__(16) bf16  g_cw_h[LNUM*DD*2*HH];
__device__ __align__(16) bf16  g_cw_l[LNUM*DD*2*HH];
__device__ __align__(16) bf16  g_gw_h[LNUM*2*DD*DD];
__device__ __align__(16) bf16  g_gw_l[LNUM*2*DD*DD];
__device__ float g_lam_re[LNUM*HH];
__device__ float g_lam_im[LNUM*HH];
__device__ float g_gam  [LNUM*HH];
__device__ float g_sum_re[BB*NCHUNK*HH];
__device__ float g_sum_im[BB*NCHUNK*HH];
__device__ float g_car_re[BB*NCHUNK*HH];
__device__ float g_car_im[BB*NCHUNK*HH];

// ---------------- helpers ----------------
__device__ __forceinline__ float gelu_exact(float v) {
    return 0.5f * v * (1.0f + erff(v * 0.70710678118654752f));
}
__device__ __forceinline__ void split2(float v, bf16& h, bf16& l) {
    h = __float2bfloat16(v);
    l = __float2bfloat16(v - __bfloat162float(h));
}
__device__ __forceinline__ void cp16(uint32_t d, const void* s) {
    asm volatile("cp.async.cg.shared.global [%0], [%1], 16;" :: "r"(d), "l"(s));
}
__device__ __forceinline__ void cpcommit() {
    asm volatile("cp.async.commit_group;" ::: "memory");
}
template<int N> __device__ __forceinline__ void cpwait() {
    asm volatile("cp.async.wait_group %0;" :: "n"(N) : "memory");
}
__device__ __forceinline__ void mma_bf16(float* c, const uint32_t* a,
                                         uint32_t b0, uint32_t b1) {
    asm volatile("mma.sync.aligned.m16n8k16.row.col.f32.bf16.bf16.f32 "
        "{%0,%1,%2,%3}, {%4,%5,%6,%7}, {%8,%9}, {%0,%1,%2,%3};"
        : "+f"(c[0]), "+f"(c[1]), "+f"(c[2]), "+f"(c[3])
        : "r"(a[0]), "r"(a[1]), "r"(a[2]), "r"(a[3]), "r"(b0), "r"(b1));
}

// load one K-stage: Ah, Al (rows m0..m0+127) and Wh, Wl (rows n0..n0+127)
__device__ __forceinline__ void ldstage(char* smbase, int slot,
        const bf16* Ah, const bf16* Al, int lda,
        const bf16* Wh, const bf16* Wl, int ldw,
        int m0, int n0, int kb, int tid) {
    uint32_t st = (uint32_t)__cvta_generic_to_shared(smbase) + (uint32_t)slot * STAGEB;
    #pragma unroll
    for (int j = 0; j < 2; j++) {
        int chunk = tid + j * 256;
        int row   = chunk >> 2;
        int c16   = (chunk & 3) * 16;      // byte offset within 64B row payload
        uint32_t d = st + (uint32_t)row * (ROWP*2) + c16;
        int ke = kb + (c16 >> 1);          // element offset
        cp16(d,           Ah + (size_t)(m0+row)*lda + ke);
        cp16(d +   MATB,  Al + (size_t)(m0+row)*lda + ke);
        cp16(d + 2*MATB,  Wh + (size_t)(n0+row)*ldw + ke);
        cp16(d + 3*MATB,  Wl + (size_t)(n0+row)*ldw + ke);
    }
    cpcommit();
}

// ---------------- split-bf16 3-pass tensor-core GEMM ----------------
// C[m,n] = sum_k A[m,k]*W[n,k]
// epi 0: Cf = acc + bias(n)          (bias1 used for n>=nsplit)
// epi 1: Cf = acc * epi_n[n & 1023]
// epi 2: Ch/Cl = split(gelu(acc + epi_m[m*1024+n]*epi_n[n]))
__global__ __launch_bounds__(256, 2)
void gemm_mma(const bf16* __restrict__ Ah, const bf16* __restrict__ Al, int lda,
              const bf16* __restrict__ Wh, const bf16* __restrict__ Wl,
              float* __restrict__ Cf, bf16* __restrict__ Ch, bf16* __restrict__ Cl,
              int ldc, int K, int epi,
              const float* __restrict__ bias0, const float* __restrict__ bias1, int nsplit,
              const float* __restrict__ epi_m, const float* __restrict__ epi_n) {
    extern __shared__ __align__(16) char smc[];
    const int tid  = threadIdx.x;
    const int wid  = tid >> 5, lane = tid & 31;
    const int g    = lane >> 2, t2 = lane & 3;
    const int warpM = wid & 3;          // 0..3
    const int warpN = wid >> 2;         // 0..1
    const int m0 = blockIdx.y * 128;
    const int n0 = blockIdx.x * 128;
    const int NCH = K / BKC;

    float acc[2][8][4];
    #pragma unroll
    for (int i = 0; i < 2; i++)
        #pragma unroll
        for (int j = 0; j < 8; j++)
            #pragma unroll
            for (int q = 0; q < 4; q++) acc[i][j][q] = 0.f;

    ldstage(smc, 0, Ah, Al, lda, Wh, Wl, K, m0, n0, 0,   tid);
    ldstage(smc, 1, Ah, Al, lda, Wh, Wl, K, m0, n0, BKC, tid);

    for (int t = 0; t < NCH; t++) {
        cpwait<1>();
        __syncthreads();
        const char* st   = smc + (t & 1) * STAGEB;
        const char* Ah_s = st;
        const char* Al_s = st + MATB;
        const char* Wh_s = st + 2*MATB;
        const char* Wl_s = st + 3*MATB;
        #pragma unroll
        for (int kh = 0; kh < 2; kh++) {
            const int kb = (kh*16 + t2*2) * 2;   // byte offset in row
            uint32_t ah[2][4], al[2][4];
            #pragma unroll
            for (int mt = 0; mt < 2; mt++) {
                int r0 = warpM*32 + mt*16 + g;
                const char* p0 = Ah_s + r0*(ROWP*2) + kb;
                const char* p1 = Ah_s + (r0+8)*(ROWP*2) + kb;
                ah[mt][0] = *(const uint32_t*)p0;
                ah[mt][1] = *(const uint32_t*)p1;
                ah[mt][2] = *(const uint32_t*)(p0 + 16);
                ah[mt][3] = *(const uint32_t*)(p1 + 16);
                const char* q0 = Al_s + r0*(ROWP*2) + kb;
                const char* q1 = Al_s + (r0+8)*(ROWP*2) + kb;
                al[mt][0] = *(const uint32_t*)q0;
                al[mt][1] = *(const uint32_t*)q1;
                al[mt][2] = *(const uint32_t*)(q0 + 16);
                al[mt][3] = *(const uint32_t*)(q1 + 16);
            }
            #pragma unroll
            for (int nt = 0; nt < 8; nt++) {
                int rn = warpN*64 + nt*8 + g;
                const char* qh = Wh_s + rn*(ROWP*2) + kb;
                const char* ql = Wl_s + rn*(ROWP*2) + kb;
                uint32_t bh0 = *(const uint32_t*)qh;
                uint32_t bh1 = *(const uint32_t*)(qh + 16);
                uint32_t bl0 = *(const uint32_t*)ql;
                uint32_t bl1 = *(const uint32_t*)(ql + 16);
                #pragma unroll
                for (int mt = 0; mt < 2; mt++) {
                    mma_bf16(acc[mt][nt], ah[mt], bh0, bh1);
                    mma_bf16(acc[mt][nt], al[mt], bh0, bh1);
                    mma_bf16(acc[mt][nt], ah[mt], bl0, bl1);
                }
            }
        }
        __syncthreads();
        if (t + 2 < NCH)
            ldstage(smc, t & 1, Ah, Al, lda, Wh, Wl, K, m0, n0, (t+2)*BKC, tid);
        else
            cpcommit();   // keep group accounting aligned for cpwait<1>
    }

    // ---- epilogue ----
    #pragma unroll
    for (int mt = 0; mt < 2; mt++) {
        #pragma unroll
        for (int nt = 0; nt < 8; nt++) {
            int row0 = m0 + warpM*32 + mt*16 + g;
            int row1 = row0 + 8;
            int col  = n0 + warpN*64 + nt*8 + t2*2;
            float c0 = acc[mt][nt][0], c1 = acc[mt][nt][1];
            float c2 = acc[mt][nt][2], c3 = acc[mt][nt][3];
            if (epi == 0) {
                const float* bb = (bias1 && col >= nsplit) ? (bias1 + col - nsplit)
                                                           : (bias0 + col);
                float2 v0 = make_float2(c0 + bb[0], c1 + bb[1]);
                float2 v1 = make_float2(c2 + bb[0], c3 + bb[1]);
                *(float2*)(Cf + (size_t)row0 * ldc + col) = v0;
                *(float2*)(Cf + (size_t)row1 * ldc + col) = v1;
            } else if (epi == 1) {
                float e0 = epi_n[col & (HH-1)], e1 = epi_n[(col+1) & (HH-1)];
                *(float2*)(Cf + (size_t)row0 * ldc + col) = make_float2(c0*e0, c1*e1);
                *(float2*)(Cf + (size_t)row1 * ldc + col) = make_float2(c2*e0, c3*e1);
            } else {
                float d0 = epi_n[col], d1 = epi_n[col+1];
                float2 x0 = *(const float2*)(epi_m + (size_t)row0 * DD + col);
                float2 x1 = *(const float2*)(epi_m + (size_t)row1 * DD + col);
                float v0 = gelu_exact(c0 + x0.x * d0);
                float v1 = gelu_exact(c1 + x0.y * d1);
                float v2 = gelu_exact(c2 + x1.x * d0);
                float v3 = gelu_exact(c3 + x1.y * d1);
                bf16 h0,l0,h1,l1,h2,l2,h3,l3;
                split2(v0,h0,l0); split2(v1,h1,l1);
                split2(v2,h2,l2); split2(v3,h3,l3);
                __nv_bfloat162 ph0(h0,h1), pl0(l0,l1), ph1(h2,h3), pl1(l2,l3);
                *(uint32_t*)(Ch + (size_t)row0 * ldc + col) = *(uint32_t*)&ph0;
                *(uint32_t*)(Cl + (size_t)row0 * ldc + col) = *(uint32_t*)&pl0;
                *(uint32_t*)(Ch + (size_t)row1 * ldc + col) = *(uint32_t*)&ph1;
                *(uint32_t*)(Cl + (size_t)row1 * ldc + col) = *(uint32_t*)&pl1;
            }
        }
    }
}

// ---------------- parameter prep ----------------
__global__ void prep_kernel(const float* __restrict__ nu_log,
                            const float* __restrict__ theta_log) {
    int i = blockIdx.x * blockDim.x + threadIdx.x;   // L*H
    float nu = expf(nu_log[i]);
    float th = expf(theta_log[i]);
    float r  = expf(-nu);
    g_lam_re[i] = r * cosf(th);
    g_lam_im[i] = r * sinf(th);
    g_gam[i]    = sqrtf(1.0f - expf(-2.0f * nu) + 1e-5f);
}

// ---------------- splitters ----------------
__global__ void split_kernel(const float* __restrict__ s,
                             bf16* __restrict__ oh, bf16* __restrict__ ol, int n) {
    int i = blockIdx.x * 256 + threadIdx.x;
    if (i >= n) return;
    bf16 h, l;
    split2(s[i], h, l);
    oh[i] = h; ol[i] = l;
}
// C-weight: dst[r*2048 + coff + c] = sgn*src[r*1024 + c]
__global__ void split_cw_kernel(const float* __restrict__ s,
                                bf16* __restrict__ oh, bf16* __restrict__ ol,
                                float sgn, int coff) {
    int i = blockIdx.x * 256 + threadIdx.x;   // over DD*HH
    int r = i >> 10, c = i & 1023;
    float v = sgn * s[i];
    size_t d = (size_t)r * 2048 + coff + c;
    bf16 h, l;
    split2(v, h, l);
    oh[d] = h; ol[d] = l;
}

// ---------------- layernorm (+ bf16 split outputs) ----------------
__global__ void ln_kernel(const float* __restrict__ x,
                          const float* __restrict__ sc,
                          const float* __restrict__ bi,
                          float* __restrict__ o,
                          bf16* __restrict__ oh, bf16* __restrict__ ol) {
    __shared__ float red[16];
    int row = blockIdx.x;
    int tid = threadIdx.x;
    const float* xr = x + (size_t)row * DD;
    float4 v = *(const float4*)(xr + tid * 4);
    float s  = v.x + v.y + v.z + v.w;
    float ss = v.x*v.x + v.y*v.y + v.z*v.z + v.w*v.w;
    #pragma unroll
    for (int off = 16; off; off >>= 1) {
        s  += __shfl_xor_sync(0xffffffffu, s,  off);
        ss += __shfl_xor_sync(0xffffffffu, ss, off);
    }
    int wid = tid >> 5;
    if ((tid & 31) == 0) { red[wid] = s; red[8 + wid] = ss; }
    __syncthreads();
    float S = 0.f, SS = 0.f;
    #pragma unroll
    for (int w = 0; w < 8; w++) { S += red[w]; SS += red[8 + w]; }
    float mu  = S * (1.0f / DD);
    float var = SS * (1.0f / DD) - mu * mu;
    float rstd = rsqrtf(var + 1e-5f);
    float4 s4 = *(const float4*)(sc + tid * 4);
    float4 b4 = *(const float4*)(bi + tid * 4);
    float ov[4];
    ov[0] = (v.x - mu) * rstd * s4.x + b4.x;
    ov[1] = (v.y - mu) * rstd * s4.y + b4.y;
    ov[2] = (v.z - mu) * rstd * s4.z + b4.z;
    ov[3] = (v.w - mu) * rstd * s4.w + b4.w;
    *(float4*)(o + (size_t)row * DD + tid * 4) = make_float4(ov[0], ov[1], ov[2], ov[3]);
    bf16 h[4], l[4];
    #pragma unroll
    for (int j = 0; j < 4; j++) split2(ov[j], h[j], l[j]);
    *(uint2*)(oh + (size_t)row * DD + tid * 4) = *(uint2*)h;
    *(uint2*)(ol + (size_t)row * DD + tid * 4) = *(uint2*)l;
}

// ---------------- scan ----------------
__global__ void scan_sum_kernel(const float* __restrict__ bu, int loff) {
    int h = blockIdx.x * blockDim.x + threadIdx.x;
    int c = blockIdx.y, b = blockIdx.z;
    float lre = g_lam_re[loff + h], lim = g_lam_im[loff + h];
    size_t base = ((size_t)(b * TT + c * CL)) * (2 * HH) + h;
    float are = 0.f, aim = 0.f;
    #pragma unroll 8
    for (int j = 0; j < CL; j++) {
        float ure = bu[base], uim = bu[base + HH];
        float nr = fmaf(are, lre, fmaf(-aim, lim, ure));
        float ni = fmaf(are, lim, fmaf(aim, lre, uim));
        are = nr; aim = ni;
        base += 2 * HH;
    }
    int o = (b * NCHUNK + c) * HH + h;
    g_sum_re[o] = are; g_sum_im[o] = aim;
}

__global__ void scan_carry_kernel(int loff) {
    int idx = blockIdx.x * blockDim.x + threadIdx.x;  // B*H
    int b = idx >> 10, h = idx & (HH - 1);
    float lre = g_lam_re[loff + h], lim = g_lam_im[loff + h];
    float pre = lre, pim = lim;
    #pragma unroll
    for (int i = 0; i < 7; i++) {   // lam^128
        float nr = pre*pre - pim*pim;
        float ni = 2.f*pre*pim;
        pre = nr; pim = ni;
    }
    float cre = 0.f, cim = 0.f;
    #pragma unroll
    for (int c = 0; c < NCHUNK; c++) {
        int o = (b * NCHUNK + c) * HH + h;
        g_car_re[o] = cre; g_car_im[o] = cim;
        float sre = g_sum_re[o], sim = g_sum_im[o];
        float nr = cre*pre - cim*pim + sre;
        float ni = cre*pim + cim*pre + sim;
        cre = nr; cim = ni;
    }
}

__global__ void scan_apply_kernel(const float* __restrict__ bu,
                                  bf16* __restrict__ hsh, bf16* __restrict__ hsl,
                                  int loff) {
    int h = blockIdx.x * blockDim.x + threadIdx.x;
    int c = blockIdx.y, b = blockIdx.z;
    float lre = g_lam_re[loff + h], lim = g_lam_im[loff + h];
    int o = (b * NCHUNK + c) * HH + h;
    float are = g_car_re[o], aim = g_car_im[o];
    size_t base = ((size_t)(b * TT + c * CL)) * (2 * HH) + h;
    #pragma unroll 4
    for (int j = 0; j < CL; j++) {
        float ure = bu[base], uim = bu[base + HH];
        float nr = fmaf(are, lre, fmaf(-aim, lim, ure));
        float ni = fmaf(are, lim, fmaf(aim, lre, uim));
        are = nr; aim = ni;
        bf16 hh, ll;
        split2(are, hh, ll);
        hsh[base] = hh; hsl[base] = ll;
        split2(aim, hh, ll);
        hsh[base + HH] = hh; hsl[base + HH] = ll;
        base += 2 * HH;
    }
}

// ---------------- GLU combine + residual ----------------
__global__ void glu_combine_kernel(const float* __restrict__ g, float* __restrict__ x) {
    int i = blockIdx.x * blockDim.x + threadIdx.x;
    int m  = i / (DD / 4);
    int c4 = (i % (DD / 4)) * 4;
    const float* gr = g + (size_t)m * (2 * DD);
    float4 a  = *(const float4*)(gr + c4);
    float4 bq = *(const float4*)(gr + DD + c4);
    float4 xo = *(float4*)(x + (size_t)m * DD + c4);
    xo.x = fmaf(a.x, 1.f / (1.f + expf(-bq.x)), xo.x);
    xo.y = fmaf(a.y, 1.f / (1.f + expf(-bq.y)), xo.y);
    xo.z = fmaf(a.z, 1.f / (1.f + expf(-bq.z)), xo.z);
    xo.w = fmaf(a.w, 1.f / (1.f + expf(-bq.w)), xo.w);
    *(float4*)(x + (size_t)m * DD + c4) = xo;
}

// ---------------- launch ----------------
extern "C" void kernel_launch(void* const* d_in, const int* in_sizes, int n_in,
                              void* d_out, int out_size) {
    const float* inputs    = (const float*)d_in[0];
    const float* W_in      = (const float*)d_in[1];
    const float* b_in      = (const float*)d_in[2];
    const float* nu_log    = (const float*)d_in[3];
    const float* theta_log = (const float*)d_in[4];
    const float* B_re      = (const float*)d_in[5];
    const float* B_im      = (const float*)d_in[6];
    const float* C_re      = (const float*)d_in[7];
    const float* C_im      = (const float*)d_in[8];
    const float* D_diag    = (const float*)d_in[9];
    const float* ln_scale  = (const float*)d_in[10];
    const float* ln_bias   = (const float*)d_in[11];
    const float* w1        = (const float*)d_in[12];
    const float* b1        = (const float*)d_in[13];
    const float* w2        = (const float*)d_in[14];
    const float* b2        = (const float*)d_in[15];
    float* x = (float*)d_out;

    cudaFuncSetAttribute(gemm_mma, cudaFuncAttributeMaxDynamicSharedMemorySize, SMEMB);

    float *p_xn, *p_bu, *p_g, *p_gam;
    bf16 *p_xnh, *p_xnl, *p_inh, *p_inl, *p_hsh, *p_hsl, *p_yh, *p_yl;
    bf16 *p_winh, *p_winl, *p_bwh, *p_bwl, *p_cwh, *p_cwl, *p_gwh, *p_gwl;
    cudaGetSymbolAddress((void**)&p_xn,  g_xn);
    cudaGetSymbolAddress((void**)&p_bu,  g_bu);
    cudaGetSymbolAddress((void**)&p_g,   g_g);
    cudaGetSymbolAddress((void**)&p_gam, g_gam);
    cudaGetSymbolAddress((void**)&p_xnh, g_xn_h);
    cudaGetSymbolAddress((void**)&p_xnl, g_xn_l);
    cudaGetSymbolAddress((void**)&p_inh, g_in_h);
    cudaGetSymbolAddress((void**)&p_inl, g_in_l);
    cudaGetSymbolAddress((void**)&p_hsh, g_hs_h);
    cudaGetSymbolAddress((void**)&p_hsl, g_hs_l);
    cudaGetSymbolAddress((void**)&p_yh,  g_y_h);
    cudaGetSymbolAddress((void**)&p_yl,  g_y_l);
    cudaGetSymbolAddress((void**)&p_winh, g_win_h);
    cudaGetSymbolAddress((void**)&p_winl, g_win_l);
    cudaGetSymbolAddress((void**)&p_bwh, g_bw_h);
    cudaGetSymbolAddress((void**)&p_bwl, g_bw_l);
    cudaGetSymbolAddress((void**)&p_cwh, g_cw_h);
    cudaGetSymbolAddress((void**)&p_cwl, g_cw_l);
    cudaGetSymbolAddress((void**)&p_gwh, g_gw_h);
    cudaGetSymbolAddress((void**)&p_gwl, g_gw_l);

    prep_kernel<<<(LNUM * HH) / 256, 256>>>(nu_log, theta_log);

    // split inputs & all weights
    split_kernel<<<(MTOT*FF)/256, 256>>>(inputs, p_inh, p_inl, MTOT*FF);
    split_kernel<<<(DD*FF)/256, 256>>>(W_in, p_winh, p_winl, DD*FF);
    for (int l = 0; l < LNUM; l++) {
        size_t wo = (size_t)l * 2 * HH * DD;
        split_kernel<<<(HH*DD)/256, 256>>>(B_re + (size_t)l*HH*DD, p_bwh + wo,         p_bwl + wo,         HH*DD);
        split_kernel<<<(HH*DD)/256, 256>>>(B_im + (size_t)l*HH*DD, p_bwh + wo + HH*DD, p_bwl + wo + HH*DD, HH*DD);
        size_t co = (size_t)l * DD * 2 * HH;
        split_cw_kernel<<<(DD*HH)/256, 256>>>(C_re + (size_t)l*DD*HH, p_cwh + co, p_cwl + co,  1.f, 0);
        split_cw_kernel<<<(DD*HH)/256, 256>>>(C_im + (size_t)l*DD*HH, p_cwh + co, p_cwl + co, -1.f, HH);
        size_t go = (size_t)l * 2 * DD * DD;
        split_kernel<<<(DD*DD)/256, 256>>>(w1 + (size_t)l*DD*DD, p_gwh + go,         p_gwl + go,         DD*DD);
        split_kernel<<<(DD*DD)/256, 256>>>(w2 + (size_t)l*DD*DD, p_gwh + go + DD*DD, p_gwl + go + DD*DD, DD*DD);
    }

    // input projection: x = inputs @ W_in^T + b_in
    gemm_mma<<<dim3(DD/128, MTOT/128), 256, SMEMB>>>(
        p_inh, p_inl, FF, p_winh, p_winl,
        x, nullptr, nullptr, DD, FF, 0,
        b_in, nullptr, 1 << 30, nullptr, nullptr);

    for (int l = 0; l < LNUM; l++) {
        ln_kernel<<<MTOT, 256>>>(x, ln_scale + l*DD, ln_bias + l*DD, p_xn, p_xnh, p_xnl);

        // Bu = gamma * (xn @ [B_re;B_im]^T)
        gemm_mma<<<dim3(2*HH/128, MTOT/128), 256, SMEMB>>>(
            p_xnh, p_xnl, DD,
            p_bwh + (size_t)l*2*HH*DD, p_bwl + (size_t)l*2*HH*DD,
            p_bu, nullptr, nullptr, 2*HH, DD, 1,
            nullptr, nullptr, 0, nullptr, p_gam + l*HH);

        scan_sum_kernel  <<<dim3(HH/256, NCHUNK, BB), 256>>>(p_bu, l*HH);
        scan_carry_kernel<<<(BB*HH)/256, 256>>>(l*HH);
        scan_apply_kernel<<<dim3(HH/256, NCHUNK, BB), 256>>>(p_bu, p_hsh, p_hsl, l*HH);

        // y = gelu( hs @ [C_re | -C_im]^T + xn * D_diag ), output split bf16
        gemm_mma<<<dim3(DD/128, MTOT/128), 256, SMEMB>>>(
            p_hsh, p_hsl, 2*HH,
            p_cwh + (size_t)l*DD*2*HH, p_cwl + (size_t)l*DD*2*HH,
            nullptr, p_yh, p_yl, DD, 2*HH, 2,
            nullptr, nullptr, 0, p_xn, D_diag + l*DD);

        // g = y @ [w1;w2]^T + [b1;b2]
        gemm_mma<<<dim3(2*DD/128, MTOT/128), 256, SMEMB>>>(
            p_yh, p_yl, DD,
            p_gwh + (size_t)l*2*DD*DD, p_gwl + (size_t)l*2*DD*DD,
            p_g, nullptr, nullptr, 2*DD, DD, 0,
            b1 + l*DD, b2 + l*DD, DD, nullptr, nullptr);

        glu_combine_kernel<<<(MTOT*DD/4)/256, 256>>>(p_g, x);
    }
    (void)in_sizes; (void)n_in; (void)out_size;
}

// round 6
// speedup vs baseline: 2.5391x; 1.0506x over previous
#include <cuda_runtime.h>
#include <cuda_bf16.h>
#include <math.h>
#include <stdint.h>

// ---------------- problem constants ----------------
#define LNUM 4
#define BB   4
#define TT   2048
#define DD   1024
#define HH   1024
#define FF   256
#define MTOT (BB*TT)          // 8192
#define NCHUNK 16
#define CL   (TT/NCHUNK)      // 128

// ---------------- mma GEMM config ----------------
#define BKC   32                      // k elements per stage
#define ROWP  40                      // padded row length (bf16) -> 80B
#define MATB  (128*ROWP*2)            // bytes per matrix tile in a stage
#define STAGEB (4*MATB)               // Ah, Al, Wh, Wl
#define SMEMB (2*STAGEB)              // 81920 B
#define QS    72                      // fused-GLU smem staging stride (floats)

typedef __nv_bfloat16 bf16;

// ---------------- scratch (device globals; no allocs allowed) ----------------
__device__ __align__(16) float g_xn[MTOT*DD];
__device__ __align__(16) bf16  g_xn_h[MTOT*DD];
__device__ __align__(16) bf16  g_xn_l[MTOT*DD];
__device__ __align__(16) bf16  g_in_h[MTOT*FF];
__device__ __align__(16) bf16  g_in_l[MTOT*FF];
__device__ __align__(16) float g_bu[MTOT*2*HH];
__device__ __align__(16) bf16  g_hs_h[MTOT*2*HH];
__device__ __align__(16) bf16  g_hs_l[MTOT*2*HH];
__device__ __align__(16) bf16  g_y_h[MTOT*DD];
__device__ __align__(16) bf16  g_y_l[MTOT*DD];
__device__ __align__(16) bf16  g_win_h[DD*FF];
__device__ __align__(16) bf16  g_win_l[DD*FF];
__device__ __align__(16) bf16  g_bw_h[LNUM*2*HH*DD];
__device__ __align__(16) bf16  g_bw_l[LNUM*2*HH*DD];
__device__ __align__(16) bf16  g_cw_h[LNUM*DD*2*HH];
__device__ __align__(16) bf16  g_cw_l[LNUM*DD*2*HH];
__device__ __align__(16) bf16  g_gw_h[LNUM*2*DD*DD];
__device__ __align__(16) bf16  g_gw_l[LNUM*2*DD*DD];
__device__ float g_lam_re[LNUM*HH];
__device__ float g_lam_im[LNUM*HH];
__device__ float g_gam  [LNUM*HH];
__device__ float g_sum_re[BB*NCHUNK*HH];
__device__ float g_sum_im[BB*NCHUNK*HH];
__device__ float g_car_re[BB*NCHUNK*HH];
__device__ float g_car_im[BB*NCHUNK*HH];

// ---------------- helpers ----------------
__device__ __forceinline__ float gelu_exact(float v) {
    return 0.5f * v * (1.0f + erff(v * 0.70710678118654752f));
}
__device__ __forceinline__ void split2(float v, bf16& h, bf16& l) {
    h = __float2bfloat16(v);
    l = __float2bfloat16(v - __bfloat162float(h));
}
__device__ __forceinline__ void cp16(uint32_t d, const void* s) {
    asm volatile("cp.async.cg.shared.global [%0], [%1], 16;" :: "r"(d), "l"(s));
}
__device__ __forceinline__ void cpcommit() {
    asm volatile("cp.async.commit_group;" ::: "memory");
}
template<int N> __device__ __forceinline__ void cpwait() {
    asm volatile("cp.async.wait_group %0;" :: "n"(N) : "memory");
}
__device__ __forceinline__ void mma_bf16(float* c, const uint32_t* a,
                                         uint32_t b0, uint32_t b1) {
    asm volatile("mma.sync.aligned.m16n8k16.row.col.f32.bf16.bf16.f32 "
        "{%0,%1,%2,%3}, {%4,%5,%6,%7}, {%8,%9}, {%0,%1,%2,%3};"
        : "+f"(c[0]), "+f"(c[1]), "+f"(c[2]), "+f"(c[3])
        : "r"(a[0]), "r"(a[1]), "r"(a[2]), "r"(a[3]), "r"(b0), "r"(b1));
}
__device__ __forceinline__ void ldm4(uint32_t* r, uint32_t a) {
    asm volatile("ldmatrix.sync.aligned.m8n8.x4.shared.b16 {%0,%1,%2,%3}, [%4];"
        : "=r"(r[0]), "=r"(r[1]), "=r"(r[2]), "=r"(r[3]) : "r"(a));
}

// load one K-stage: Ah, Al (rows m0..m0+127) and Wh, Wl (rows n0..n0+127)
__device__ __forceinline__ void ldstage(uint32_t sb, int slot,
        const bf16* Ah, const bf16* Al, int lda,
        const bf16* Wh, const bf16* Wl, int ldw,
        int m0, int n0, int kb, int tid) {
    uint32_t st = sb + (uint32_t)slot * STAGEB;
    #pragma unroll
    for (int j = 0; j < 2; j++) {
        int chunk = tid + j * 256;
        int row   = chunk >> 2;
        int c16   = (chunk & 3) * 16;
        uint32_t d = st + (uint32_t)row * (ROWP*2) + c16;
        int ke = kb + (c16 >> 1);
        cp16(d,           Ah + (size_t)(m0+row)*lda + ke);
        cp16(d +   MATB,  Al + (size_t)(m0+row)*lda + ke);
        cp16(d + 2*MATB,  Wh + (size_t)(n0+row)*ldw + ke);
        cp16(d + 3*MATB,  Wl + (size_t)(n0+row)*ldw + ke);
    }
    cpcommit();
}

// ---------------- split-bf16 3-pass tensor-core GEMM ----------------
// C[m,n] = sum_k A[m,k]*W[n,k]
// epi 0: Cf = acc + bias0(n)
// epi 1: Cf = acc * epi_n[n & 1023]
// epi 2: Ch/Cl = split(gelu(acc + epi_m[m*1024+n]*epi_n[n]))
// epi 3: fused GLU: W interleaved [w1|w2] per 128-tile; x += (a+b1)*sigmoid(q+b2)
__global__ __launch_bounds__(256, 2)
void gemm_mma(const bf16* __restrict__ Ah, const bf16* __restrict__ Al, int lda,
              const bf16* __restrict__ Wh, const bf16* __restrict__ Wl,
              float* __restrict__ Cf, bf16* __restrict__ Ch, bf16* __restrict__ Cl,
              int ldc, int K, int epi,
              const float* __restrict__ bias0, const float* __restrict__ bias1,
              const float* __restrict__ epi_m, const float* __restrict__ epi_n) {
    extern __shared__ __align__(16) char smc[];
    uint32_t sb = (uint32_t)__cvta_generic_to_shared(smc);
    const int tid  = threadIdx.x;
    const int wid  = tid >> 5, lane = tid & 31;
    const int g    = lane >> 2, t2 = lane & 3;
    const int warpM = wid & 3;
    const int warpN = wid >> 2;
    const int m0 = blockIdx.y * 128;
    const int n0 = blockIdx.x * 128;
    const int NCH = K / BKC;

    // ldmatrix per-lane address offsets
    const int grp = lane >> 3, rr = lane & 7;
    uint32_t a_off[2], b_off[4];
    #pragma unroll
    for (int mt = 0; mt < 2; mt++) {
        int r = warpM*32 + mt*16 + rr + (grp & 1)*8;
        a_off[mt] = (uint32_t)r * (ROWP*2) + (grp >> 1) * 16;
    }
    #pragma unroll
    for (int ntp = 0; ntp < 4; ntp++) {
        int r = warpN*64 + ntp*16 + rr + (grp >> 1)*8;
        b_off[ntp] = (uint32_t)r * (ROWP*2) + (grp & 1) * 16;
    }

    float acc[2][8][4];
    #pragma unroll
    for (int i = 0; i < 2; i++)
        #pragma unroll
        for (int j = 0; j < 8; j++)
            #pragma unroll
            for (int q = 0; q < 4; q++) acc[i][j][q] = 0.f;

    ldstage(sb, 0, Ah, Al, lda, Wh, Wl, K, m0, n0, 0,   tid);
    ldstage(sb, 1, Ah, Al, lda, Wh, Wl, K, m0, n0, BKC, tid);

    for (int t = 0; t < NCH; t++) {
        cpwait<1>();
        __syncthreads();
        uint32_t st   = sb + (uint32_t)(t & 1) * STAGEB;
        uint32_t Ah_s = st, Al_s = st + MATB, Wh_s = st + 2*MATB, Wl_s = st + 3*MATB;
        #pragma unroll
        for (int kh = 0; kh < 2; kh++) {
            const uint32_t kb = kh * 32;
            uint32_t ah[2][4], al[2][4];
            ldm4(ah[0], Ah_s + a_off[0] + kb);
            ldm4(ah[1], Ah_s + a_off[1] + kb);
            ldm4(al[0], Al_s + a_off[0] + kb);
            ldm4(al[1], Al_s + a_off[1] + kb);
            #pragma unroll
            for (int ntp = 0; ntp < 4; ntp++) {
                uint32_t bh[4], bl[4];
                ldm4(bh, Wh_s + b_off[ntp] + kb);
                ldm4(bl, Wl_s + b_off[ntp] + kb);
                #pragma unroll
                for (int sub = 0; sub < 2; sub++) {
                    int nt = ntp*2 + sub;
                    uint32_t b0h = bh[sub*2], b1h = bh[sub*2+1];
                    uint32_t b0l = bl[sub*2], b1l = bl[sub*2+1];
                    mma_bf16(acc[0][nt], ah[0], b0h, b1h);
                    mma_bf16(acc[1][nt], ah[1], b0h, b1h);
                    mma_bf16(acc[0][nt], al[0], b0h, b1h);
                    mma_bf16(acc[1][nt], al[1], b0h, b1h);
                    mma_bf16(acc[0][nt], ah[0], b0l, b1l);
                    mma_bf16(acc[1][nt], ah[1], b0l, b1l);
                }
            }
        }
        __syncthreads();
        if (t + 2 < NCH)
            ldstage(sb, t & 1, Ah, Al, lda, Wh, Wl, K, m0, n0, (t+2)*BKC, tid);
        else
            cpcommit();
    }

    // ---- epilogue ----
    if (epi == 3) {
        // fused GLU: tile cols 0-63 = w1 (a), 64-127 = w2 (q); output cols co..co+63
        const int co = blockIdx.x * 64;
        float* qs = (float*)smc;
        if (warpN == 1) {
            #pragma unroll
            for (int mt = 0; mt < 2; mt++)
                #pragma unroll
                for (int nt = 0; nt < 8; nt++) {
                    int r0 = warpM*32 + mt*16 + g, r1 = r0 + 8;
                    int c  = nt*8 + t2*2;
                    float bb0 = bias1[co + c], bb1 = bias1[co + c + 1];
                    qs[r0*QS + c]     = acc[mt][nt][0] + bb0;
                    qs[r0*QS + c + 1] = acc[mt][nt][1] + bb1;
                    qs[r1*QS + c]     = acc[mt][nt][2] + bb0;
                    qs[r1*QS + c + 1] = acc[mt][nt][3] + bb1;
                }
        }
        __syncthreads();
        if (warpN == 0) {
            #pragma unroll
            for (int mt = 0; mt < 2; mt++)
                #pragma unroll
                for (int nt = 0; nt < 8; nt++) {
                    int r0 = warpM*32 + mt*16 + g, r1 = r0 + 8;
                    int c  = nt*8 + t2*2;
                    float bb0 = bias0[co + c], bb1 = bias0[co + c + 1];
                    float a00 = acc[mt][nt][0] + bb0, a01 = acc[mt][nt][1] + bb1;
                    float a10 = acc[mt][nt][2] + bb0, a11 = acc[mt][nt][3] + bb1;
                    float q00 = qs[r0*QS + c], q01 = qs[r0*QS + c + 1];
                    float q10 = qs[r1*QS + c], q11 = qs[r1*QS + c + 1];
                    float* x0 = Cf + (size_t)(m0 + r0) * DD + co + c;
                    float* x1 = Cf + (size_t)(m0 + r1) * DD + co + c;
                    float2 v0 = *(float2*)x0, v1 = *(float2*)x1;
                    v0.x = fmaf(a00, 1.f/(1.f + expf(-q00)), v0.x);
                    v0.y = fmaf(a01, 1.f/(1.f + expf(-q01)), v0.y);
                    v1.x = fmaf(a10, 1.f/(1.f + expf(-q10)), v1.x);
                    v1.y = fmaf(a11, 1.f/(1.f + expf(-q11)), v1.y);
                    *(float2*)x0 = v0;
                    *(float2*)x1 = v1;
                }
        }
        return;
    }
    #pragma unroll
    for (int mt = 0; mt < 2; mt++) {
        #pragma unroll
        for (int nt = 0; nt < 8; nt++) {
            int row0 = m0 + warpM*32 + mt*16 + g;
            int row1 = row0 + 8;
            int col  = n0 + warpN*64 + nt*8 + t2*2;
            float c0 = acc[mt][nt][0], c1 = acc[mt][nt][1];
            float c2 = acc[mt][nt][2], c3 = acc[mt][nt][3];
            if (epi == 0) {
                float b0v = bias0[col], b1v = bias0[col + 1];
                *(float2*)(Cf + (size_t)row0 * ldc + col) = make_float2(c0 + b0v, c1 + b1v);
                *(float2*)(Cf + (size_t)row1 * ldc + col) = make_float2(c2 + b0v, c3 + b1v);
            } else if (epi == 1) {
                float e0 = epi_n[col & (HH-1)], e1 = epi_n[(col+1) & (HH-1)];
                *(float2*)(Cf + (size_t)row0 * ldc + col) = make_float2(c0*e0, c1*e1);
                *(float2*)(Cf + (size_t)row1 * ldc + col) = make_float2(c2*e0, c3*e1);
            } else {
                float d0 = epi_n[col], d1 = epi_n[col+1];
                float2 x0 = *(const float2*)(epi_m + (size_t)row0 * DD + col);
                float2 x1 = *(const float2*)(epi_m + (size_t)row1 * DD + col);
                float v0 = gelu_exact(c0 + x0.x * d0);
                float v1 = gelu_exact(c1 + x0.y * d1);
                float v2 = gelu_exact(c2 + x1.x * d0);
                float v3 = gelu_exact(c3 + x1.y * d1);
                bf16 h0,l0,h1,l1,h2,l2,h3,l3;
                split2(v0,h0,l0); split2(v1,h1,l1);
                split2(v2,h2,l2); split2(v3,h3,l3);
                __nv_bfloat162 ph0(h0,h1), pl0(l0,l1), ph1(h2,h3), pl1(l2,l3);
                *(uint32_t*)(Ch + (size_t)row0 * ldc + col) = *(uint32_t*)&ph0;
                *(uint32_t*)(Cl + (size_t)row0 * ldc + col) = *(uint32_t*)&pl0;
                *(uint32_t*)(Ch + (size_t)row1 * ldc + col) = *(uint32_t*)&ph1;
                *(uint32_t*)(Cl + (size_t)row1 * ldc + col) = *(uint32_t*)&pl1;
            }
        }
    }
}

// ---------------- parameter prep ----------------
__global__ void prep_kernel(const float* __restrict__ nu_log,
                            const float* __restrict__ theta_log) {
    int i = blockIdx.x * blockDim.x + threadIdx.x;
    float nu = expf(nu_log[i]);
    float th = expf(theta_log[i]);
    float r  = expf(-nu);
    g_lam_re[i] = r * cosf(th);
    g_lam_im[i] = r * sinf(th);
    g_gam[i]    = sqrtf(1.0f - expf(-2.0f * nu) + 1e-5f);
}

// ---------------- input splitter ----------------
__global__ void split_in_kernel(const float* __restrict__ s) {
    int i = blockIdx.x * 256 + threadIdx.x;
    bf16 h, l;
    split2(s[i], h, l);
    g_in_h[i] = h; g_in_l[i] = l;
}

// ---------------- all-weights splitter ----------------
#define NW  (DD*FF)
#define NB  (LNUM*2*HH*DD)
#define NC  (LNUM*DD*2*HH)
#define NG  (LNUM*2*DD*DD)
__global__ void split_wts_kernel(const float* __restrict__ W_in,
                                 const float* __restrict__ B_re,
                                 const float* __restrict__ B_im,
                                 const float* __restrict__ C_re,
                                 const float* __restrict__ C_im,
                                 const float* __restrict__ w1,
                                 const float* __restrict__ w2) {
    int idx = blockIdx.x * 256 + threadIdx.x;
    float v; bf16 h, l;
    if (idx < NW) {
        v = W_in[idx];
        split2(v, h, l);
        g_win_h[idx] = h; g_win_l[idx] = l;
        return;
    }
    idx -= NW;
    if (idx < NB) {
        int l_ = idx / (2*HH*DD);
        int r  = idx - l_ * (2*HH*DD);
        v = (r < HH*DD) ? B_re[(size_t)l_*HH*DD + r] : B_im[(size_t)l_*HH*DD + r - HH*DD];
        split2(v, h, l);
        g_bw_h[idx] = h; g_bw_l[idx] = l;
        return;
    }
    idx -= NB;
    if (idx < NC) {
        int l_ = idx / (DD*2*HH);
        int t  = idx - l_ * (DD*2*HH);
        int r  = t >> 11, c = t & 2047;
        if (c < HH) v = C_re[(size_t)l_*DD*HH + r*HH + c];
        else        v = -C_im[(size_t)l_*DD*HH + r*HH + (c - HH)];
        split2(v, h, l);
        g_cw_h[idx] = h; g_cw_l[idx] = l;
        return;
    }
    idx -= NC;
    {
        int l_ = idx / (2*DD*DD);
        int t  = idx - l_ * (2*DD*DD);
        int np = t >> 10, c = t & 1023;
        int blk = np >> 7, off = np & 127;
        if (off < 64) v = w1[(size_t)l_*DD*DD + (blk*64 + off)*DD + c];
        else          v = w2[(size_t)l_*DD*DD + (blk*64 + off - 64)*DD + c];
        split2(v, h, l);
        g_gw_h[idx] = h; g_gw_l[idx] = l;
    }
}

// ---------------- layernorm (+ bf16 split outputs) ----------------
__global__ void ln_kernel(const float* __restrict__ x,
                          const float* __restrict__ sc,
                          const float* __restrict__ bi,
                          float* __restrict__ o,
                          bf16* __restrict__ oh, bf16* __restrict__ ol) {
    __shared__ float red[16];
    int row = blockIdx.x;
    int tid = threadIdx.x;
    const float* xr = x + (size_t)row * DD;
    float4 v = *(const float4*)(xr + tid * 4);
    float s  = v.x + v.y + v.z + v.w;
    float ss = v.x*v.x + v.y*v.y + v.z*v.z + v.w*v.w;
    #pragma unroll
    for (int off = 16; off; off >>= 1) {
        s  += __shfl_xor_sync(0xffffffffu, s,  off);
        ss += __shfl_xor_sync(0xffffffffu, ss, off);
    }
    int wid = tid >> 5;
    if ((tid & 31) == 0) { red[wid] = s; red[8 + wid] = ss; }
    __syncthreads();
    float S = 0.f, SS = 0.f;
    #pragma unroll
    for (int w = 0; w < 8; w++) { S += red[w]; SS += red[8 + w]; }
    float mu  = S * (1.0f / DD);
    float var = SS * (1.0f / DD) - mu * mu;
    float rstd = rsqrtf(var + 1e-5f);
    float4 s4 = *(const float4*)(sc + tid * 4);
    float4 b4 = *(const float4*)(bi + tid * 4);
    float ov[4];
    ov[0] = (v.x - mu) * rstd * s4.x + b4.x;
    ov[1] = (v.y - mu) * rstd * s4.y + b4.y;
    ov[2] = (v.z - mu) * rstd * s4.z + b4.z;
    ov[3] = (v.w - mu) * rstd * s4.w + b4.w;
    *(float4*)(o + (size_t)row * DD + tid * 4) = make_float4(ov[0], ov[1], ov[2], ov[3]);
    bf16 h[4], l[4];
    #pragma unroll
    for (int j = 0; j < 4; j++) split2(ov[j], h[j], l[j]);
    *(uint2*)(oh + (size_t)row * DD + tid * 4) = *(uint2*)h;
    *(uint2*)(ol + (size_t)row * DD + tid * 4) = *(uint2*)l;
}

// ---------------- scan ----------------
__global__ void scan_sum_kernel(const float* __restrict__ bu, int loff) {
    int h = blockIdx.x * blockDim.x + threadIdx.x;
    int c = blockIdx.y, b = blockIdx.z;
    float lre = g_lam_re[loff + h], lim = g_lam_im[loff + h];
    size_t base = ((size_t)(b * TT + c * CL)) * (2 * HH) + h;
    float are = 0.f, aim = 0.f;
    #pragma unroll 8
    for (int j = 0; j < CL; j++) {
        float ure = bu[base], uim = bu[base + HH];
        float nr = fmaf(are, lre, fmaf(-aim, lim, ure));
        float ni = fmaf(are, lim, fmaf(aim, lre, uim));
        are = nr; aim = ni;
        base += 2 * HH;
    }
    int o = (b * NCHUNK + c) * HH + h;
    g_sum_re[o] = are; g_sum_im[o] = aim;
}

__global__ void scan_carry_kernel(int loff) {
    int idx = blockIdx.x * blockDim.x + threadIdx.x;
    int b = idx >> 10, h = idx & (HH - 1);
    float lre = g_lam_re[loff + h], lim = g_lam_im[loff + h];
    float pre = lre, pim = lim;
    #pragma unroll
    for (int i = 0; i < 7; i++) {
        float nr = pre*pre - pim*pim;
        float ni = 2.f*pre*pim;
        pre = nr; pim = ni;
    }
    float cre = 0.f, cim = 0.f;
    #pragma unroll
    for (int c = 0; c < NCHUNK; c++) {
        int o = (b * NCHUNK + c) * HH + h;
        g_car_re[o] = cre; g_car_im[o] = cim;
        float sre = g_sum_re[o], sim = g_sum_im[o];
        float nr = cre*pre - cim*pim + sre;
        float ni = cre*pim + cim*pre + sim;
        cre = nr; cim = ni;
    }
}

__global__ void scan_apply_kernel(const float* __restrict__ bu,
                                  bf16* __restrict__ hsh, bf16* __restrict__ hsl,
                                  int loff) {
    int h = blockIdx.x * blockDim.x + threadIdx.x;
    int c = blockIdx.y, b = blockIdx.z;
    float lre = g_lam_re[loff + h], lim = g_lam_im[loff + h];
    int o = (b * NCHUNK + c) * HH + h;
    float are = g_car_re[o], aim = g_car_im[o];
    size_t base = ((size_t)(b * TT + c * CL)) * (2 * HH) + h;
    #pragma unroll 4
    for (int j = 0; j < CL; j++) {
        float ure = bu[base], uim = bu[base + HH];
        float nr = fmaf(are, lre, fmaf(-aim, lim, ure));
        float ni = fmaf(are, lim, fmaf(aim, lre, uim));
        are = nr; aim = ni;
        bf16 hh, ll;
        split2(are, hh, ll);
        hsh[base] = hh; hsl[base] = ll;
        split2(aim, hh, ll);
        hsh[base + HH] = hh; hsl[base + HH] = ll;
        base += 2 * HH;
    }
}

// ---------------- launch ----------------
extern "C" void kernel_launch(void* const* d_in, const int* in_sizes, int n_in,
                              void* d_out, int out_size) {
    const float* inputs    = (const float*)d_in[0];
    const float* W_in      = (const float*)d_in[1];
    const float* b_in      = (const float*)d_in[2];
    const float* nu_log    = (const float*)d_in[3];
    const float* theta_log = (const float*)d_in[4];
    const float* B_re      = (const float*)d_in[5];
    const float* B_im      = (const float*)d_in[6];
    const float* C_re      = (const float*)d_in[7];
    const float* C_im      = (const float*)d_in[8];
    const float* D_diag    = (const float*)d_in[9];
    const float* ln_scale  = (const float*)d_in[10];
    const float* ln_bias   = (const float*)d_in[11];
    const float* w1        = (const float*)d_in[12];
    const float* b1        = (const float*)d_in[13];
    const float* w2        = (const float*)d_in[14];
    const float* b2        = (const float*)d_in[15];
    float* x = (float*)d_out;

    cudaFuncSetAttribute(gemm_mma, cudaFuncAttributeMaxDynamicSharedMemorySize, SMEMB);

    float *p_xn, *p_bu, *p_gam;
    bf16 *p_xnh, *p_xnl, *p_inh, *p_inl, *p_hsh, *p_hsl, *p_yh, *p_yl;
    bf16 *p_winh, *p_winl, *p_bwh, *p_bwl, *p_cwh, *p_cwl, *p_gwh, *p_gwl;
    cudaGetSymbolAddress((void**)&p_xn,  g_xn);
    cudaGetSymbolAddress((void**)&p_bu,  g_bu);
    cudaGetSymbolAddress((void**)&p_gam, g_gam);
    cudaGetSymbolAddress((void**)&p_xnh, g_xn_h);
    cudaGetSymbolAddress((void**)&p_xnl, g_xn_l);
    cudaGetSymbolAddress((void**)&p_inh, g_in_h);
    cudaGetSymbolAddress((void**)&p_inl, g_in_l);
    cudaGetSymbolAddress((void**)&p_hsh, g_hs_h);
    cudaGetSymbolAddress((void**)&p_hsl, g_hs_l);
    cudaGetSymbolAddress((void**)&p_yh,  g_y_h);
    cudaGetSymbolAddress((void**)&p_yl,  g_y_l);
    cudaGetSymbolAddress((void**)&p_winh, g_win_h);
    cudaGetSymbolAddress((void**)&p_winl, g_win_l);
    cudaGetSymbolAddress((void**)&p_bwh, g_bw_h);
    cudaGetSymbolAddress((void**)&p_bwl, g_bw_l);
    cudaGetSymbolAddress((void**)&p_cwh, g_cw_h);
    cudaGetSymbolAddress((void**)&p_cwl, g_cw_l);
    cudaGetSymbolAddress((void**)&p_gwh, g_gw_h);
    cudaGetSymbolAddress((void**)&p_gwl, g_gw_l);

    // 1: params, 2: split inputs, 3: split all weights
    prep_kernel<<<(LNUM * HH) / 256, 256>>>(nu_log, theta_log);
    split_in_kernel<<<(MTOT*FF)/256, 256>>>(inputs);
    split_wts_kernel<<<(NW + NB + NC + NG)/256, 256>>>(
        W_in, B_re, B_im, C_re, C_im, w1, w2);

    // 4: input projection: x = inputs @ W_in^T + b_in
    gemm_mma<<<dim3(DD/128, MTOT/128), 256, SMEMB>>>(
        p_inh, p_inl, FF, p_winh, p_winl,
        x, nullptr, nullptr, DD, FF, 0,
        b_in, nullptr, nullptr, nullptr);

    for (int l = 0; l < LNUM; l++) {
        // 5: layernorm
        ln_kernel<<<MTOT, 256>>>(x, ln_scale + l*DD, ln_bias + l*DD, p_xn, p_xnh, p_xnl);

        // 6: Bu = gamma * (xn @ [B_re;B_im]^T)
        gemm_mma<<<dim3(2*HH/128, MTOT/128), 256, SMEMB>>>(
            p_xnh, p_xnl, DD,
            p_bwh + (size_t)l*2*HH*DD, p_bwl + (size_t)l*2*HH*DD,
            p_bu, nullptr, nullptr, 2*HH, DD, 1,
            nullptr, nullptr, nullptr, p_gam + l*HH);

        scan_sum_kernel  <<<dim3(HH/256, NCHUNK, BB), 256>>>(p_bu, l*HH);
        scan_carry_kernel<<<(BB*HH)/256, 256>>>(l*HH);
        scan_apply_kernel<<<dim3(HH/256, NCHUNK, BB), 256>>>(p_bu, p_hsh, p_hsl, l*HH);

        // y = gelu( hs @ [C_re | -C_im]^T + xn * D_diag ), output split bf16
        gemm_mma<<<dim3(DD/128, MTOT/128), 256, SMEMB>>>(
            p_hsh, p_hsl, 2*HH,
            p_cwh + (size_t)l*DD*2*HH, p_cwl + (size_t)l*DD*2*HH,
            nullptr, p_yh, p_yl, DD, 2*HH, 2,
            nullptr, nullptr, p_xn, D_diag + l*DD);

        // fused GLU + residual: x += (y@w1^T + b1) * sigmoid(y@w2^T + b2)
        gemm_mma<<<dim3(2*DD/128, MTOT/128), 256, SMEMB>>>(
            p_yh, p_yl, DD,
            p_gwh + (size_t)l*2*DD*DD, p_gwl + (size_t)l*2*DD*DD,
            x, nullptr, nullptr, DD, DD, 3,
            b1 + l*DD, b2 + l*DD, nullptr, nullptr);
    }
    (void)in_sizes; (void)n_in; (void)out_size;
}

// round 7
// speedup vs baseline: 2.9585x; 1.1652x over previous
#include <cuda_runtime.h>
#include <cuda_bf16.h>
#include <math.h>
#include <stdint.h>

// ---------------- problem constants ----------------
#define LNUM 4
#define BB   4
#define TT   2048
#define DD   1024
#define HH   1024
#define FF   256
#define MTOT (BB*TT)          // 8192
#define NCHUNK 16
#define CL   (TT/NCHUNK)      // 128

// ---------------- mma GEMM config ----------------
#define BKC   32                      // k elements per stage
#define MATB  (128*64)                // 128 rows x 64B (swizzled, no pad)
#define STAGEB (4*MATB)               // Ah, Al, Wh, Wl = 32 KB
#define NSTG  3
#define SMEMB (NSTG*STAGEB)           // 98304 B -> 2 CTAs/SM
#define QS    72                      // fused-GLU smem staging stride (floats)

typedef __nv_bfloat16 bf16;

// ---------------- scratch (device globals; no allocs allowed) ----------------
__device__ __align__(16) float g_xn[MTOT*DD];
__device__ __align__(16) bf16  g_xn_h[MTOT*DD];
__device__ __align__(16) bf16  g_xn_l[MTOT*DD];
__device__ __align__(16) bf16  g_in_h[MTOT*FF];
__device__ __align__(16) bf16  g_in_l[MTOT*FF];
__device__ __align__(16) float g_bu[MTOT*2*HH];
__device__ __align__(16) bf16  g_hs_h[MTOT*2*HH];
__device__ __align__(16) bf16  g_hs_l[MTOT*2*HH];
__device__ __align__(16) bf16  g_y_h[MTOT*DD];
__device__ __align__(16) bf16  g_y_l[MTOT*DD];
__device__ __align__(16) bf16  g_win_h[DD*FF];
__device__ __align__(16) bf16  g_win_l[DD*FF];
__device__ __align__(16) bf16  g_bw_h[LNUM*2*HH*DD];
__device__ __align__(16) bf16  g_bw_l[LNUM*2*HH*DD];
__device__ __align__(16) bf16  g_cw_h[LNUM*DD*2*HH];
__device__ __align__(16) bf16  g_cw_l[LNUM*DD*2*HH];
__device__ __align__(16) bf16  g_gw_h[LNUM*2*DD*DD];
__device__ __align__(16) bf16  g_gw_l[LNUM*2*DD*DD];
__device__ float g_lam_re[LNUM*HH];
__device__ float g_lam_im[LNUM*HH];
__device__ float g_gam  [LNUM*HH];
__device__ float g_sum_re[BB*NCHUNK*HH];
__device__ float g_sum_im[BB*NCHUNK*HH];
__device__ float g_car_re[BB*NCHUNK*HH];
__device__ float g_car_im[BB*NCHUNK*HH];

// ---------------- helpers ----------------
__device__ __forceinline__ float gelu_exact(float v) {
    return 0.5f * v * (1.0f + erff(v * 0.70710678118654752f));
}
__device__ __forceinline__ void split2(float v, bf16& h, bf16& l) {
    h = __float2bfloat16(v);
    l = __float2bfloat16(v - __bfloat162float(h));
}
__device__ __forceinline__ void cp16(uint32_t d, const void* s) {
    asm volatile("cp.async.cg.shared.global [%0], [%1], 16;" :: "r"(d), "l"(s));
}
__device__ __forceinline__ void cpcommit() {
    asm volatile("cp.async.commit_group;" ::: "memory");
}
template<int N> __device__ __forceinline__ void cpwait() {
    asm volatile("cp.async.wait_group %0;" :: "n"(N) : "memory");
}
__device__ __forceinline__ void mma_bf16(float* c, const uint32_t* a,
                                         uint32_t b0, uint32_t b1) {
    asm volatile("mma.sync.aligned.m16n8k16.row.col.f32.bf16.bf16.f32 "
        "{%0,%1,%2,%3}, {%4,%5,%6,%7}, {%8,%9}, {%0,%1,%2,%3};"
        : "+f"(c[0]), "+f"(c[1]), "+f"(c[2]), "+f"(c[3])
        : "r"(a[0]), "r"(a[1]), "r"(a[2]), "r"(a[3]), "r"(b0), "r"(b1));
}
__device__ __forceinline__ void ldm4(uint32_t* r, uint32_t a) {
    asm volatile("ldmatrix.sync.aligned.m8n8.x4.shared.b16 {%0,%1,%2,%3}, [%4];"
        : "=r"(r[0]), "=r"(r[1]), "=r"(r[2]), "=r"(r[3]) : "r"(a));
}

// swizzled chunk offset: row r (64B rows), 16B-chunk c
__device__ __forceinline__ uint32_t swz(int r, int c) {
    return (uint32_t)(r * 64 + ((c ^ ((r >> 1) & 3)) << 4));
}

// load one K-stage: Ah, Al (rows m0..m0+127) and Wh, Wl (rows n0..n0+127)
__device__ __forceinline__ void ldstage(uint32_t sb, int slot,
        const bf16* Ah, const bf16* Al, int lda,
        const bf16* Wh, const bf16* Wl, int ldw,
        int m0, int n0, int kb, int tid) {
    uint32_t st = sb + (uint32_t)slot * STAGEB;
    #pragma unroll
    for (int j = 0; j < 2; j++) {
        int chunk = tid + j * 256;
        int row   = chunk >> 2;
        int c     = chunk & 3;
        uint32_t d = st + swz(row, c);
        int ke = kb + c * 8;
        cp16(d,           Ah + (size_t)(m0+row)*lda + ke);
        cp16(d +   MATB,  Al + (size_t)(m0+row)*lda + ke);
        cp16(d + 2*MATB,  Wh + (size_t)(n0+row)*ldw + ke);
        cp16(d + 3*MATB,  Wl + (size_t)(n0+row)*ldw + ke);
    }
    cpcommit();
}

// ---------------- split-bf16 3-pass tensor-core GEMM ----------------
// C[m,n] = sum_k A[m,k]*W[n,k]
// epi 0: Cf = acc + bias0(n)
// epi 1: Cf = acc * epi_n[n & 1023]
// epi 2: Ch/Cl = split(gelu(acc + epi_m[m*1024+n]*epi_n[n]))
// epi 3: fused GLU: W interleaved [w1|w2] per 128-tile; x += (a+b1)*sigmoid(q+b2)
__global__ __launch_bounds__(256, 2)
void gemm_mma(const bf16* __restrict__ Ah, const bf16* __restrict__ Al, int lda,
              const bf16* __restrict__ Wh, const bf16* __restrict__ Wl,
              float* __restrict__ Cf, bf16* __restrict__ Ch, bf16* __restrict__ Cl,
              int ldc, int K, int epi,
              const float* __restrict__ bias0, const float* __restrict__ bias1,
              const float* __restrict__ epi_m, const float* __restrict__ epi_n) {
    extern __shared__ __align__(16) char smc[];
    uint32_t sb = (uint32_t)__cvta_generic_to_shared(smc);
    const int tid  = threadIdx.x;
    const int wid  = tid >> 5, lane = tid & 31;
    const int g    = lane >> 2, t2 = lane & 3;
    const int warpM = wid & 3;
    const int warpN = wid >> 2;
    const int m0 = blockIdx.y * 128;
    const int n0 = blockIdx.x * 128;
    const int NCH = K / BKC;

    // ldmatrix per-lane rows / chunk bases
    const int grp = lane >> 3, rr = lane & 7;
    const int cA0 = grp >> 1;           // A chunk base (0/1)
    const int cB0 = grp & 1;            // B chunk base (0/1)
    int  rA[2], rB[4];
    #pragma unroll
    for (int mt = 0; mt < 2; mt++) rA[mt] = warpM*32 + mt*16 + rr + (grp & 1)*8;
    #pragma unroll
    for (int ntp = 0; ntp < 4; ntp++) rB[ntp] = warpN*64 + ntp*16 + rr + (grp >> 1)*8;

    float acc[2][8][4];
    #pragma unroll
    for (int i = 0; i < 2; i++)
        #pragma unroll
        for (int j = 0; j < 8; j++)
            #pragma unroll
            for (int q = 0; q < 4; q++) acc[i][j][q] = 0.f;

    ldstage(sb, 0, Ah, Al, lda, Wh, Wl, K, m0, n0, 0,     tid);
    ldstage(sb, 1, Ah, Al, lda, Wh, Wl, K, m0, n0, BKC,   tid);
    ldstage(sb, 2, Ah, Al, lda, Wh, Wl, K, m0, n0, 2*BKC, tid);

    int slot = 0;
    for (int t = 0; t < NCH; t++) {
        cpwait<2>();
        __syncthreads();
        uint32_t st   = sb + (uint32_t)slot * STAGEB;
        uint32_t Ah_s = st, Al_s = st + MATB, Wh_s = st + 2*MATB, Wl_s = st + 3*MATB;
        #pragma unroll
        for (int kh = 0; kh < 2; kh++) {
            uint32_t ah[2][4], al[2][4];
            #pragma unroll
            for (int mt = 0; mt < 2; mt++) {
                uint32_t ao = swz(rA[mt], cA0 + 2*kh);
                ldm4(ah[mt], Ah_s + ao);
                ldm4(al[mt], Al_s + ao);
            }
            #pragma unroll
            for (int ntp = 0; ntp < 4; ntp++) {
                uint32_t bo = swz(rB[ntp], cB0 + 2*kh);
                uint32_t bh[4], bl[4];
                ldm4(bh, Wh_s + bo);
                ldm4(bl, Wl_s + bo);
                #pragma unroll
                for (int sub = 0; sub < 2; sub++) {
                    int nt = ntp*2 + sub;
                    uint32_t b0h = bh[sub*2], b1h = bh[sub*2+1];
                    uint32_t b0l = bl[sub*2], b1l = bl[sub*2+1];
                    mma_bf16(acc[0][nt], ah[0], b0h, b1h);
                    mma_bf16(acc[1][nt], ah[1], b0h, b1h);
                    mma_bf16(acc[0][nt], al[0], b0h, b1h);
                    mma_bf16(acc[1][nt], al[1], b0h, b1h);
                    mma_bf16(acc[0][nt], ah[0], b0l, b1l);
                    mma_bf16(acc[1][nt], ah[1], b0l, b1l);
                }
            }
        }
        __syncthreads();
        if (t + NSTG < NCH)
            ldstage(sb, slot, Ah, Al, lda, Wh, Wl, K, m0, n0, (t+NSTG)*BKC, tid);
        else
            cpcommit();
        slot = (slot + 1 == NSTG) ? 0 : slot + 1;
    }

    // ---- epilogue ----
    if (epi == 3) {
        // fused GLU: tile cols 0-63 = w1 (a), 64-127 = w2 (q); output cols co..co+63
        const int co = blockIdx.x * 64;
        float* qs = (float*)smc;
        if (warpN == 1) {
            #pragma unroll
            for (int mt = 0; mt < 2; mt++)
                #pragma unroll
                for (int nt = 0; nt < 8; nt++) {
                    int r0 = warpM*32 + mt*16 + g, r1 = r0 + 8;
                    int c  = nt*8 + t2*2;
                    float bb0 = bias1[co + c], bb1 = bias1[co + c + 1];
                    qs[r0*QS + c]     = acc[mt][nt][0] + bb0;
                    qs[r0*QS + c + 1] = acc[mt][nt][1] + bb1;
                    qs[r1*QS + c]     = acc[mt][nt][2] + bb0;
                    qs[r1*QS + c + 1] = acc[mt][nt][3] + bb1;
                }
        }
        __syncthreads();
        if (warpN == 0) {
            #pragma unroll
            for (int mt = 0; mt < 2; mt++)
                #pragma unroll
                for (int nt = 0; nt < 8; nt++) {
                    int r0 = warpM*32 + mt*16 + g, r1 = r0 + 8;
                    int c  = nt*8 + t2*2;
                    float bb0 = bias0[co + c], bb1 = bias0[co + c + 1];
                    float a00 = acc[mt][nt][0] + bb0, a01 = acc[mt][nt][1] + bb1;
                    float a10 = acc[mt][nt][2] + bb0, a11 = acc[mt][nt][3] + bb1;
                    float q00 = qs[r0*QS + c], q01 = qs[r0*QS + c + 1];
                    float q10 = qs[r1*QS + c], q11 = qs[r1*QS + c + 1];
                    float* x0 = Cf + (size_t)(m0 + r0) * DD + co + c;
                    float* x1 = Cf + (size_t)(m0 + r1) * DD + co + c;
                    float2 v0 = *(float2*)x0, v1 = *(float2*)x1;
                    v0.x = fmaf(a00, 1.f/(1.f + expf(-q00)), v0.x);
                    v0.y = fmaf(a01, 1.f/(1.f + expf(-q01)), v0.y);
                    v1.x = fmaf(a10, 1.f/(1.f + expf(-q10)), v1.x);
                    v1.y = fmaf(a11, 1.f/(1.f + expf(-q11)), v1.y);
                    *(float2*)x0 = v0;
                    *(float2*)x1 = v1;
                }
        }
        return;
    }
    #pragma unroll
    for (int mt = 0; mt < 2; mt++) {
        #pragma unroll
        for (int nt = 0; nt < 8; nt++) {
            int row0 = m0 + warpM*32 + mt*16 + g;
            int row1 = row0 + 8;
            int col  = n0 + warpN*64 + nt*8 + t2*2;
            float c0 = acc[mt][nt][0], c1 = acc[mt][nt][1];
            float c2 = acc[mt][nt][2], c3 = acc[mt][nt][3];
            if (epi == 0) {
                float b0v = bias0[col], b1v = bias0[col + 1];
                *(float2*)(Cf + (size_t)row0 * ldc + col) = make_float2(c0 + b0v, c1 + b1v);
                *(float2*)(Cf + (size_t)row1 * ldc + col) = make_float2(c2 + b0v, c3 + b1v);
            } else if (epi == 1) {
                float e0 = epi_n[col & (HH-1)], e1 = epi_n[(col+1) & (HH-1)];
                *(float2*)(Cf + (size_t)row0 * ldc + col) = make_float2(c0*e0, c1*e1);
                *(float2*)(Cf + (size_t)row1 * ldc + col) = make_float2(c2*e0, c3*e1);
            } else {
                float d0 = epi_n[col], d1 = epi_n[col+1];
                float2 x0 = *(const float2*)(epi_m + (size_t)row0 * DD + col);
                float2 x1 = *(const float2*)(epi_m + (size_t)row1 * DD + col);
                float v0 = gelu_exact(c0 + x0.x * d0);
                float v1 = gelu_exact(c1 + x0.y * d1);
                float v2 = gelu_exact(c2 + x1.x * d0);
                float v3 = gelu_exact(c3 + x1.y * d1);
                bf16 h0,l0,h1,l1,h2,l2,h3,l3;
                split2(v0,h0,l0); split2(v1,h1,l1);
                split2(v2,h2,l2); split2(v3,h3,l3);
                __nv_bfloat162 ph0(h0,h1), pl0(l0,l1), ph1(h2,h3), pl1(l2,l3);
                *(uint32_t*)(Ch + (size_t)row0 * ldc + col) = *(uint32_t*)&ph0;
                *(uint32_t*)(Cl + (size_t)row0 * ldc + col) = *(uint32_t*)&pl0;
                *(uint32_t*)(Ch + (size_t)row1 * ldc + col) = *(uint32_t*)&ph1;
                *(uint32_t*)(Cl + (size_t)row1 * ldc + col) = *(uint32_t*)&pl1;
            }
        }
    }
}

// ---------------- parameter prep ----------------
__global__ void prep_kernel(const float* __restrict__ nu_log,
                            const float* __restrict__ theta_log) {
    int i = blockIdx.x * blockDim.x + threadIdx.x;
    float nu = expf(nu_log[i]);
    float th = expf(theta_log[i]);
    float r  = expf(-nu);
    g_lam_re[i] = r * cosf(th);
    g_lam_im[i] = r * sinf(th);
    g_gam[i]    = sqrtf(1.0f - expf(-2.0f * nu) + 1e-5f);
}

// ---------------- input splitter ----------------
__global__ void split_in_kernel(const float* __restrict__ s) {
    int i = blockIdx.x * 256 + threadIdx.x;
    bf16 h, l;
    split2(s[i], h, l);
    g_in_h[i] = h; g_in_l[i] = l;
}

// ---------------- all-weights splitter ----------------
#define NW  (DD*FF)
#define NB  (LNUM*2*HH*DD)
#define NC  (LNUM*DD*2*HH)
#define NG  (LNUM*2*DD*DD)
__global__ void split_wts_kernel(const float* __restrict__ W_in,
                                 const float* __restrict__ B_re,
                                 const float* __restrict__ B_im,
                                 const float* __restrict__ C_re,
                                 const float* __restrict__ C_im,
                                 const float* __restrict__ w1,
                                 const float* __restrict__ w2) {
    int idx = blockIdx.x * 256 + threadIdx.x;
    float v; bf16 h, l;
    if (idx < NW) {
        v = W_in[idx];
        split2(v, h, l);
        g_win_h[idx] = h; g_win_l[idx] = l;
        return;
    }
    idx -= NW;
    if (idx < NB) {
        int l_ = idx / (2*HH*DD);
        int r  = idx - l_ * (2*HH*DD);
        v = (r < HH*DD) ? B_re[(size_t)l_*HH*DD + r] : B_im[(size_t)l_*HH*DD + r - HH*DD];
        split2(v, h, l);
        g_bw_h[idx] = h; g_bw_l[idx] = l;
        return;
    }
    idx -= NB;
    if (idx < NC) {
        int l_ = idx / (DD*2*HH);
        int t  = idx - l_ * (DD*2*HH);
        int r  = t >> 11, c = t & 2047;
        if (c < HH) v = C_re[(size_t)l_*DD*HH + r*HH + c];
        else        v = -C_im[(size_t)l_*DD*HH + r*HH + (c - HH)];
        split2(v, h, l);
        g_cw_h[idx] = h; g_cw_l[idx] = l;
        return;
    }
    idx -= NC;
    {
        int l_ = idx / (2*DD*DD);
        int t  = idx - l_ * (2*DD*DD);
        int np = t >> 10, c = t & 1023;
        int blk = np >> 7, off = np & 127;
        if (off < 64) v = w1[(size_t)l_*DD*DD + (blk*64 + off)*DD + c];
        else          v = w2[(size_t)l_*DD*DD + (blk*64 + off - 64)*DD + c];
        split2(v, h, l);
        g_gw_h[idx] = h; g_gw_l[idx] = l;
    }
}

// ---------------- layernorm (+ bf16 split outputs) ----------------
__global__ void ln_kernel(const float* __restrict__ x,
                          const float* __restrict__ sc,
                          const float* __restrict__ bi,
                          float* __restrict__ o,
                          bf16* __restrict__ oh, bf16* __restrict__ ol) {
    __shared__ float red[16];
    int row = blockIdx.x;
    int tid = threadIdx.x;
    const float* xr = x + (size_t)row * DD;
    float4 v = *(const float4*)(xr + tid * 4);
    float s  = v.x + v.y + v.z + v.w;
    float ss = v.x*v.x + v.y*v.y + v.z*v.z + v.w*v.w;
    #pragma unroll
    for (int off = 16; off; off >>= 1) {
        s  += __shfl_xor_sync(0xffffffffu, s,  off);
        ss += __shfl_xor_sync(0xffffffffu, ss, off);
    }
    int wid = tid >> 5;
    if ((tid & 31) == 0) { red[wid] = s; red[8 + wid] = ss; }
    __syncthreads();
    float S = 0.f, SS = 0.f;
    #pragma unroll
    for (int w = 0; w < 8; w++) { S += red[w]; SS += red[8 + w]; }
    float mu  = S * (1.0f / DD);
    float var = SS * (1.0f / DD) - mu * mu;
    float rstd = rsqrtf(var + 1e-5f);
    float4 s4 = *(const float4*)(sc + tid * 4);
    float4 b4 = *(const float4*)(bi + tid * 4);
    float ov[4];
    ov[0] = (v.x - mu) * rstd * s4.x + b4.x;
    ov[1] = (v.y - mu) * rstd * s4.y + b4.y;
    ov[2] = (v.z - mu) * rstd * s4.z + b4.z;
    ov[3] = (v.w - mu) * rstd * s4.w + b4.w;
    *(float4*)(o + (size_t)row * DD + tid * 4) = make_float4(ov[0], ov[1], ov[2], ov[3]);
    bf16 h[4], l[4];
    #pragma unroll
    for (int j = 0; j < 4; j++) split2(ov[j], h[j], l[j]);
    *(uint2*)(oh + (size_t)row * DD + tid * 4) = *(uint2*)h;
    *(uint2*)(ol + (size_t)row * DD + tid * 4) = *(uint2*)l;
}

// ---------------- scan ----------------
__global__ void scan_sum_kernel(const float* __restrict__ bu, int loff) {
    int h = blockIdx.x * blockDim.x + threadIdx.x;
    int c = blockIdx.y, b = blockIdx.z;
    float lre = g_lam_re[loff + h], lim = g_lam_im[loff + h];
    size_t base = ((size_t)(b * TT + c * CL)) * (2 * HH) + h;
    float are = 0.f, aim = 0.f;
    #pragma unroll 8
    for (int j = 0; j < CL; j++) {
        float ure = bu[base], uim = bu[base + HH];
        float nr = fmaf(are, lre, fmaf(-aim, lim, ure));
        float ni = fmaf(are, lim, fmaf(aim, lre, uim));
        are = nr; aim = ni;
        base += 2 * HH;
    }
    int o = (b * NCHUNK + c) * HH + h;
    g_sum_re[o] = are; g_sum_im[o] = aim;
}

__global__ void scan_carry_kernel(int loff) {
    int idx = blockIdx.x * blockDim.x + threadIdx.x;
    int b = idx >> 10, h = idx & (HH - 1);
    float lre = g_lam_re[loff + h], lim = g_lam_im[loff + h];
    float pre = lre, pim = lim;
    #pragma unroll
    for (int i = 0; i < 7; i++) {
        float nr = pre*pre - pim*pim;
        float ni = 2.f*pre*pim;
        pre = nr; pim = ni;
    }
    float cre = 0.f, cim = 0.f;
    #pragma unroll
    for (int c = 0; c < NCHUNK; c++) {
        int o = (b * NCHUNK + c) * HH + h;
        g_car_re[o] = cre; g_car_im[o] = cim;
        float sre = g_sum_re[o], sim = g_sum_im[o];
        float nr = cre*pre - cim*pim + sre;
        float ni = cre*pim + cim*pre + sim;
        cre = nr; cim = ni;
    }
}

__global__ void scan_apply_kernel(const float* __restrict__ bu,
                                  bf16* __restrict__ hsh, bf16* __restrict__ hsl,
                                  int loff) {
    int h = blockIdx.x * blockDim.x + threadIdx.x;
    int c = blockIdx.y, b = blockIdx.z;
    float lre = g_lam_re[loff + h], lim = g_lam_im[loff + h];
    int o = (b * NCHUNK + c) * HH + h;
    float are = g_car_re[o], aim = g_car_im[o];
    size_t base = ((size_t)(b * TT + c * CL)) * (2 * HH) + h;
    #pragma unroll 4
    for (int j = 0; j < CL; j++) {
        float ure = bu[base], uim = bu[base + HH];
        float nr = fmaf(are, lre, fmaf(-aim, lim, ure));
        float ni = fmaf(are, lim, fmaf(aim, lre, uim));
        are = nr; aim = ni;
        bf16 hh, ll;
        split2(are, hh, ll);
        hsh[base] = hh; hsl[base] = ll;
        split2(aim, hh, ll);
        hsh[base + HH] = hh; hsl[base + HH] = ll;
        base += 2 * HH;
    }
}

// ---------------- launch ----------------
extern "C" void kernel_launch(void* const* d_in, const int* in_sizes, int n_in,
                              void* d_out, int out_size) {
    const float* inputs    = (const float*)d_in[0];
    const float* W_in      = (const float*)d_in[1];
    const float* b_in      = (const float*)d_in[2];
    const float* nu_log    = (const float*)d_in[3];
    const float* theta_log = (const float*)d_in[4];
    const float* B_re      = (const float*)d_in[5];
    const float* B_im      = (const float*)d_in[6];
    const float* C_re      = (const float*)d_in[7];
    const float* C_im      = (const float*)d_in[8];
    const float* D_diag    = (const float*)d_in[9];
    const float* ln_scale  = (const float*)d_in[10];
    const float* ln_bias   = (const float*)d_in[11];
    const float* w1        = (const float*)d_in[12];
    const float* b1        = (const float*)d_in[13];
    const float* w2        = (const float*)d_in[14];
    const float* b2        = (const float*)d_in[15];
    float* x = (float*)d_out;

    cudaFuncSetAttribute(gemm_mma, cudaFuncAttributeMaxDynamicSharedMemorySize, SMEMB);

    float *p_xn, *p_bu, *p_gam;
    bf16 *p_xnh, *p_xnl, *p_inh, *p_inl, *p_hsh, *p_hsl, *p_yh, *p_yl;
    bf16 *p_winh, *p_winl, *p_bwh, *p_bwl, *p_cwh, *p_cwl, *p_gwh, *p_gwl;
    cudaGetSymbolAddress((void**)&p_xn,  g_xn);
    cudaGetSymbolAddress((void**)&p_bu,  g_bu);
    cudaGetSymbolAddress((void**)&p_gam, g_gam);
    cudaGetSymbolAddress((void**)&p_xnh, g_xn_h);
    cudaGetSymbolAddress((void**)&p_xnl, g_xn_l);
    cudaGetSymbolAddress((void**)&p_inh, g_in_h);
    cudaGetSymbolAddress((void**)&p_inl, g_in_l);
    cudaGetSymbolAddress((void**)&p_hsh, g_hs_h);
    cudaGetSymbolAddress((void**)&p_hsl, g_hs_l);
    cudaGetSymbolAddress((void**)&p_yh,  g_y_h);
    cudaGetSymbolAddress((void**)&p_yl,  g_y_l);
    cudaGetSymbolAddress((void**)&p_winh, g_win_h);
    cudaGetSymbolAddress((void**)&p_winl, g_win_l);
    cudaGetSymbolAddress((void**)&p_bwh, g_bw_h);
    cudaGetSymbolAddress((void**)&p_bwl, g_bw_l);
    cudaGetSymbolAddress((void**)&p_cwh, g_cw_h);
    cudaGetSymbolAddress((void**)&p_cwl, g_cw_l);
    cudaGetSymbolAddress((void**)&p_gwh, g_gw_h);
    cudaGetSymbolAddress((void**)&p_gwl, g_gw_l);

    // 1: params, 2: split inputs, 3: split all weights
    prep_kernel<<<(LNUM * HH) / 256, 256>>>(nu_log, theta_log);
    split_in_kernel<<<(MTOT*FF)/256, 256>>>(inputs);
    split_wts_kernel<<<(NW + NB + NC + NG)/256, 256>>>(
        W_in, B_re, B_im, C_re, C_im, w1, w2);

    // 4: input projection: x = inputs @ W_in^T + b_in
    gemm_mma<<<dim3(DD/128, MTOT/128), 256, SMEMB>>>(
        p_inh, p_inl, FF, p_winh, p_winl,
        x, nullptr, nullptr, DD, FF, 0,
        b_in, nullptr, nullptr, nullptr);

    for (int l = 0; l < LNUM; l++) {
        // layernorm
        ln_kernel<<<MTOT, 256>>>(x, ln_scale + l*DD, ln_bias + l*DD, p_xn, p_xnh, p_xnl);

        // Bu = gamma * (xn @ [B_re;B_im]^T)
        gemm_mma<<<dim3(2*HH/128, MTOT/128), 256, SMEMB>>>(
            p_xnh, p_xnl, DD,
            p_bwh + (size_t)l*2*HH*DD, p_bwl + (size_t)l*2*HH*DD,
            p_bu, nullptr, nullptr, 2*HH, DD, 1,
            nullptr, nullptr, nullptr, p_gam + l*HH);

        scan_sum_kernel  <<<dim3(HH/256, NCHUNK, BB), 256>>>(p_bu, l*HH);
        scan_carry_kernel<<<(BB*HH)/256, 256>>>(l*HH);
        scan_apply_kernel<<<dim3(HH/256, NCHUNK, BB), 256>>>(p_bu, p_hsh, p_hsl, l*HH);

        // y = gelu( hs @ [C_re | -C_im]^T + xn * D_diag ), output split bf16
        gemm_mma<<<dim3(DD/128, MTOT/128), 256, SMEMB>>>(
            p_hsh, p_hsl, 2*HH,
            p_cwh + (size_t)l*DD*2*HH, p_cwl + (size_t)l*DD*2*HH,
            nullptr, p_yh, p_yl, DD, 2*HH, 2,
            nullptr, nullptr, p_xn, D_diag + l*DD);

        // fused GLU + residual: x += (y@w1^T + b1) * sigmoid(y@w2^T + b2)
        gemm_mma<<<dim3(2*DD/128, MTOT/128), 256, SMEMB>>>(
            p_yh, p_yl, DD,
            p_gwh + (size_t)l*2*DD*DD, p_gwl + (size_t)l*2*DD*DD,
            x, nullptr, nullptr, DD, DD, 3,
            b1 + l*DD, b2 + l*DD, nullptr, nullptr);
    }
    (void)in_sizes; (void)n_in; (void)out_size;
}

// round 8
// speedup vs baseline: 2.9877x; 1.0099x over previous
#include <cuda_runtime.h>
#include <cuda_bf16.h>
#include <math.h>
#include <stdint.h>

// ---------------- problem constants ----------------
#define LNUM 4
#define BB   4
#define TT   2048
#define DD   1024
#define HH   1024
#define FF   256
#define MTOT (BB*TT)          // 8192
#define NCHUNK 16
#define CL   (TT/NCHUNK)      // 128

// ---------------- mma GEMM config ----------------
#define BKC   32                      // k elements per stage
#define MATB  (128*64)                // 128 rows x 64B (swizzled, no pad)
#define STAGEB (4*MATB)               // Ah, Al, Wh, Wl = 32 KB
#define NSTG  3
#define SMEMB (NSTG*STAGEB)           // 98304 B -> 2 CTAs/SM
#define QS    72                      // fused-GLU smem staging stride (floats)

typedef __nv_bfloat16 bf16;

// ---------------- scratch (device globals; no allocs allowed) ----------------
__device__ __align__(16) float g_xn[MTOT*DD];
__device__ __align__(16) bf16  g_xn_h[MTOT*DD];
__device__ __align__(16) bf16  g_xn_l[MTOT*DD];
__device__ __align__(16) bf16  g_in_h[MTOT*FF];
__device__ __align__(16) bf16  g_in_l[MTOT*FF];
__device__ __align__(16) float g_bu[MTOT*2*HH];
__device__ __align__(16) bf16  g_hs_h[MTOT*2*HH];
__device__ __align__(16) bf16  g_hs_l[MTOT*2*HH];
__device__ __align__(16) bf16  g_y_h[MTOT*DD];
__device__ __align__(16) bf16  g_y_l[MTOT*DD];
__device__ __align__(16) bf16  g_win_h[DD*FF];
__device__ __align__(16) bf16  g_win_l[DD*FF];
__device__ __align__(16) bf16  g_bw_h[LNUM*2*HH*DD];
__device__ __align__(16) bf16  g_bw_l[LNUM*2*HH*DD];
__device__ __align__(16) bf16  g_cw_h[LNUM*DD*2*HH];
__device__ __align__(16) bf16  g_cw_l[LNUM*DD*2*HH];
__device__ __align__(16) bf16  g_gw_h[LNUM*2*DD*DD];
__device__ __align__(16) bf16  g_gw_l[LNUM*2*DD*DD];
__device__ float g_lam_re[LNUM*HH];
__device__ float g_lam_im[LNUM*HH];
__device__ float g_gam  [LNUM*HH];
__device__ float g_sum_re[BB*NCHUNK*HH];
__device__ float g_sum_im[BB*NCHUNK*HH];
__device__ float g_car_re[BB*NCHUNK*HH];
__device__ float g_car_im[BB*NCHUNK*HH];

// ---------------- helpers ----------------
__device__ __forceinline__ float gelu_exact(float v) {
    return 0.5f * v * (1.0f + erff(v * 0.70710678118654752f));
}
__device__ __forceinline__ void split2(float v, bf16& h, bf16& l) {
    h = __float2bfloat16(v);
    l = __float2bfloat16(v - __bfloat162float(h));
}
__device__ __forceinline__ void cp16(uint32_t d, const void* s) {
    asm volatile("cp.async.cg.shared.global [%0], [%1], 16;" :: "r"(d), "l"(s));
}
__device__ __forceinline__ void cpcommit() {
    asm volatile("cp.async.commit_group;" ::: "memory");
}
template<int N> __device__ __forceinline__ void cpwait() {
    asm volatile("cp.async.wait_group %0;" :: "n"(N) : "memory");
}
__device__ __forceinline__ void mma_bf16(float* c, const uint32_t* a,
                                         uint32_t b0, uint32_t b1) {
    asm volatile("mma.sync.aligned.m16n8k16.row.col.f32.bf16.bf16.f32 "
        "{%0,%1,%2,%3}, {%4,%5,%6,%7}, {%8,%9}, {%0,%1,%2,%3};"
        : "+f"(c[0]), "+f"(c[1]), "+f"(c[2]), "+f"(c[3])
        : "r"(a[0]), "r"(a[1]), "r"(a[2]), "r"(a[3]), "r"(b0), "r"(b1));
}
__device__ __forceinline__ void ldm4(uint32_t* r, uint32_t a) {
    asm volatile("ldmatrix.sync.aligned.m8n8.x4.shared.b16 {%0,%1,%2,%3}, [%4];"
        : "=r"(r[0]), "=r"(r[1]), "=r"(r[2]), "=r"(r[3]) : "r"(a));
}

// swizzled chunk offset: row r (64B rows), 16B-chunk c
__device__ __forceinline__ uint32_t swz(int r, int c) {
    return (uint32_t)(r * 64 + ((c ^ ((r >> 1) & 3)) << 4));
}

// load one K-stage: Ah, Al (rows m0..m0+127) and Wh, Wl (rows n0..n0+127)
__device__ __forceinline__ void ldstage(uint32_t sb, int slot,
        const bf16* Ah, const bf16* Al, int lda,
        const bf16* Wh, const bf16* Wl, int ldw,
        int m0, int n0, int kb, int tid) {
    uint32_t st = sb + (uint32_t)slot * STAGEB;
    #pragma unroll
    for (int j = 0; j < 2; j++) {
        int chunk = tid + j * 256;
        int row   = chunk >> 2;
        int c     = chunk & 3;
        uint32_t d = st + swz(row, c);
        int ke = kb + c * 8;
        cp16(d,           Ah + (size_t)(m0+row)*lda + ke);
        cp16(d +   MATB,  Al + (size_t)(m0+row)*lda + ke);
        cp16(d + 2*MATB,  Wh + (size_t)(n0+row)*ldw + ke);
        cp16(d + 3*MATB,  Wl + (size_t)(n0+row)*ldw + ke);
    }
    cpcommit();
}

// ---------------- split-bf16 3-pass tensor-core GEMM ----------------
// C[m,n] = sum_k A[m,k]*W[n,k]
// epi 0: Cf = acc + bias0(n)
// epi 1: Cf = acc * epi_n[n & 1023]
// epi 2: Ch/Cl = split(gelu(acc + epi_m[m*1024+n]*epi_n[n]))
// epi 3: fused GLU: W interleaved [w1|w2] per 128-tile; x += (a+b1)*sigmoid(q+b2)
__global__ __launch_bounds__(256, 2)
void gemm_mma(const bf16* __restrict__ Ah, const bf16* __restrict__ Al, int lda,
              const bf16* __restrict__ Wh, const bf16* __restrict__ Wl,
              float* __restrict__ Cf, bf16* __restrict__ Ch, bf16* __restrict__ Cl,
              int ldc, int K, int epi,
              const float* __restrict__ bias0, const float* __restrict__ bias1,
              const float* __restrict__ epi_m, const float* __restrict__ epi_n) {
    extern __shared__ __align__(16) char smc[];
    uint32_t sb = (uint32_t)__cvta_generic_to_shared(smc);
    const int tid  = threadIdx.x;
    const int wid  = tid >> 5, lane = tid & 31;
    const int g    = lane >> 2, t2 = lane & 3;
    const int warpM = wid & 3;
    const int warpN = wid >> 2;
    const int m0 = blockIdx.y * 128;
    const int n0 = blockIdx.x * 128;
    const int NCH = K / BKC;

    // ldmatrix per-lane rows / chunk bases
    const int grp = lane >> 3, rr = lane & 7;
    const int cA0 = grp >> 1;           // A chunk base (0/1)
    const int cB0 = grp & 1;            // B chunk base (0/1)
    int  rA[2], rB[4];
    #pragma unroll
    for (int mt = 0; mt < 2; mt++) rA[mt] = warpM*32 + mt*16 + rr + (grp & 1)*8;
    #pragma unroll
    for (int ntp = 0; ntp < 4; ntp++) rB[ntp] = warpN*64 + ntp*16 + rr + (grp >> 1)*8;

    float acc[2][8][4];
    #pragma unroll
    for (int i = 0; i < 2; i++)
        #pragma unroll
        for (int j = 0; j < 8; j++)
            #pragma unroll
            for (int q = 0; q < 4; q++) acc[i][j][q] = 0.f;

    // prologue: stages 0,1 in flight; wait stage 0, publish
    ldstage(sb, 0, Ah, Al, lda, Wh, Wl, K, m0, n0, 0,   tid);
    ldstage(sb, 1, Ah, Al, lda, Wh, Wl, K, m0, n0, BKC, tid);
    cpwait<1>();
    __syncthreads();

    int slot = 0;
    for (int t = 0; t < NCH; t++) {
        // issue loads for stage t+2 first (overlap with compute below)
        if (t + 2 < NCH)
            ldstage(sb, (t + 2) % NSTG, Ah, Al, lda, Wh, Wl, K, m0, n0, (t+2)*BKC, tid);
        else
            cpcommit();

        uint32_t st   = sb + (uint32_t)slot * STAGEB;
        uint32_t Ah_s = st, Al_s = st + MATB, Wh_s = st + 2*MATB, Wl_s = st + 3*MATB;

        // A-fragment double buffer over kh
        uint32_t ah[2][2][4], al[2][2][4];
        #pragma unroll
        for (int mt = 0; mt < 2; mt++) {
            uint32_t ao = swz(rA[mt], cA0);
            ldm4(ah[0][mt], Ah_s + ao);
            ldm4(al[0][mt], Al_s + ao);
        }
        #pragma unroll
        for (int kh = 0; kh < 2; kh++) {
            if (kh == 0) {
                #pragma unroll
                for (int mt = 0; mt < 2; mt++) {
                    uint32_t ao = swz(rA[mt], cA0 + 2);
                    ldm4(ah[1][mt], Ah_s + ao);
                    ldm4(al[1][mt], Al_s + ao);
                }
            }
            uint32_t (*pah)[4] = ah[kh];
            uint32_t (*pal)[4] = al[kh];
            #pragma unroll
            for (int ntp = 0; ntp < 4; ntp++) {
                uint32_t bo = swz(rB[ntp], cB0 + 2*kh);
                uint32_t bh[4], bl[4];
                ldm4(bh, Wh_s + bo);
                ldm4(bl, Wl_s + bo);
                int nt0 = ntp*2, nt1 = ntp*2 + 1;
                // pass hi*hi
                mma_bf16(acc[0][nt0], pah[0], bh[0], bh[1]);
                mma_bf16(acc[1][nt0], pah[1], bh[0], bh[1]);
                mma_bf16(acc[0][nt1], pah[0], bh[2], bh[3]);
                mma_bf16(acc[1][nt1], pah[1], bh[2], bh[3]);
                // pass lo*hi
                mma_bf16(acc[0][nt0], pal[0], bh[0], bh[1]);
                mma_bf16(acc[1][nt0], pal[1], bh[0], bh[1]);
                mma_bf16(acc[0][nt1], pal[0], bh[2], bh[3]);
                mma_bf16(acc[1][nt1], pal[1], bh[2], bh[3]);
                // pass hi*lo
                mma_bf16(acc[0][nt0], pah[0], bl[0], bl[1]);
                mma_bf16(acc[1][nt0], pah[1], bl[0], bl[1]);
                mma_bf16(acc[0][nt1], pah[0], bl[2], bl[3]);
                mma_bf16(acc[1][nt1], pah[1], bl[2], bl[3]);
            }
        }

        cpwait<1>();       // stage t+1 landed (issuing thread)
        __syncthreads();   // publish CTA-wide; frees slot of stage t-1 overwrite rule
        slot = (slot + 1 == NSTG) ? 0 : slot + 1;
    }

    // ---- epilogue ----
    if (epi == 3) {
        // fused GLU: tile cols 0-63 = w1 (a), 64-127 = w2 (q); output cols co..co+63
        const int co = blockIdx.x * 64;
        float* qs = (float*)smc;
        if (warpN == 1) {
            #pragma unroll
            for (int mt = 0; mt < 2; mt++)
                #pragma unroll
                for (int nt = 0; nt < 8; nt++) {
                    int r0 = warpM*32 + mt*16 + g, r1 = r0 + 8;
                    int c  = nt*8 + t2*2;
                    float bb0 = bias1[co + c], bb1 = bias1[co + c + 1];
                    qs[r0*QS + c]     = acc[mt][nt][0] + bb0;
                    qs[r0*QS + c + 1] = acc[mt][nt][1] + bb1;
                    qs[r1*QS + c]     = acc[mt][nt][2] + bb0;
                    qs[r1*QS + c + 1] = acc[mt][nt][3] + bb1;
                }
        }
        __syncthreads();
        if (warpN == 0) {
            #pragma unroll
            for (int mt = 0; mt < 2; mt++)
                #pragma unroll
                for (int nt = 0; nt < 8; nt++) {
                    int r0 = warpM*32 + mt*16 + g, r1 = r0 + 8;
                    int c  = nt*8 + t2*2;
                    float bb0 = bias0[co + c], bb1 = bias0[co + c + 1];
                    float a00 = acc[mt][nt][0] + bb0, a01 = acc[mt][nt][1] + bb1;
                    float a10 = acc[mt][nt][2] + bb0, a11 = acc[mt][nt][3] + bb1;
                    float q00 = qs[r0*QS + c], q01 = qs[r0*QS + c + 1];
                    float q10 = qs[r1*QS + c], q11 = qs[r1*QS + c + 1];
                    float* x0 = Cf + (size_t)(m0 + r0) * DD + co + c;
                    float* x1 = Cf + (size_t)(m0 + r1) * DD + co + c;
                    float2 v0 = *(float2*)x0, v1 = *(float2*)x1;
                    v0.x = fmaf(a00, 1.f/(1.f + expf(-q00)), v0.x);
                    v0.y = fmaf(a01, 1.f/(1.f + expf(-q01)), v0.y);
                    v1.x = fmaf(a10, 1.f/(1.f + expf(-q10)), v1.x);
                    v1.y = fmaf(a11, 1.f/(1.f + expf(-q11)), v1.y);
                    *(float2*)x0 = v0;
                    *(float2*)x1 = v1;
                }
        }
        return;
    }
    #pragma unroll
    for (int mt = 0; mt < 2; mt++) {
        #pragma unroll
        for (int nt = 0; nt < 8; nt++) {
            int row0 = m0 + warpM*32 + mt*16 + g;
            int row1 = row0 + 8;
            int col  = n0 + warpN*64 + nt*8 + t2*2;
            float c0 = acc[mt][nt][0], c1 = acc[mt][nt][1];
            float c2 = acc[mt][nt][2], c3 = acc[mt][nt][3];
            if (epi == 0) {
                float b0v = bias0[col], b1v = bias0[col + 1];
                *(float2*)(Cf + (size_t)row0 * ldc + col) = make_float2(c0 + b0v, c1 + b1v);
                *(float2*)(Cf + (size_t)row1 * ldc + col) = make_float2(c2 + b0v, c3 + b1v);
            } else if (epi == 1) {
                float e0 = epi_n[col & (HH-1)], e1 = epi_n[(col+1) & (HH-1)];
                *(float2*)(Cf + (size_t)row0 * ldc + col) = make_float2(c0*e0, c1*e1);
                *(float2*)(Cf + (size_t)row1 * ldc + col) = make_float2(c2*e0, c3*e1);
            } else {
                float d0 = epi_n[col], d1 = epi_n[col+1];
                float2 x0 = *(const float2*)(epi_m + (size_t)row0 * DD + col);
                float2 x1 = *(const float2*)(epi_m + (size_t)row1 * DD + col);
                float v0 = gelu_exact(c0 + x0.x * d0);
                float v1 = gelu_exact(c1 + x0.y * d1);
                float v2 = gelu_exact(c2 + x1.x * d0);
                float v3 = gelu_exact(c3 + x1.y * d1);
                bf16 h0,l0,h1,l1,h2,l2,h3,l3;
                split2(v0,h0,l0); split2(v1,h1,l1);
                split2(v2,h2,l2); split2(v3,h3,l3);
                __nv_bfloat162 ph0(h0,h1), pl0(l0,l1), ph1(h2,h3), pl1(l2,l3);
                *(uint32_t*)(Ch + (size_t)row0 * ldc + col) = *(uint32_t*)&ph0;
                *(uint32_t*)(Cl + (size_t)row0 * ldc + col) = *(uint32_t*)&pl0;
                *(uint32_t*)(Ch + (size_t)row1 * ldc + col) = *(uint32_t*)&ph1;
                *(uint32_t*)(Cl + (size_t)row1 * ldc + col) = *(uint32_t*)&pl1;
            }
        }
    }
}

// ---------------- parameter prep ----------------
__global__ void prep_kernel(const float* __restrict__ nu_log,
                            const float* __restrict__ theta_log) {
    int i = blockIdx.x * blockDim.x + threadIdx.x;
    float nu = expf(nu_log[i]);
    float th = expf(theta_log[i]);
    float r  = expf(-nu);
    g_lam_re[i] = r * cosf(th);
    g_lam_im[i] = r * sinf(th);
    g_gam[i]    = sqrtf(1.0f - expf(-2.0f * nu) + 1e-5f);
}

// ---------------- input splitter ----------------
__global__ void split_in_kernel(const float* __restrict__ s) {
    int i = blockIdx.x * 256 + threadIdx.x;
    bf16 h, l;
    split2(s[i], h, l);
    g_in_h[i] = h; g_in_l[i] = l;
}

// ---------------- all-weights splitter ----------------
#define NW  (DD*FF)
#define NB  (LNUM*2*HH*DD)
#define NC  (LNUM*DD*2*HH)
#define NG  (LNUM*2*DD*DD)
__global__ void split_wts_kernel(const float* __restrict__ W_in,
                                 const float* __restrict__ B_re,
                                 const float* __restrict__ B_im,
                                 const float* __restrict__ C_re,
                                 const float* __restrict__ C_im,
                                 const float* __restrict__ w1,
                                 const float* __restrict__ w2) {
    int idx = blockIdx.x * 256 + threadIdx.x;
    float v; bf16 h, l;
    if (idx < NW) {
        v = W_in[idx];
        split2(v, h, l);
        g_win_h[idx] = h; g_win_l[idx] = l;
        return;
    }
    idx -= NW;
    if (idx < NB) {
        int l_ = idx / (2*HH*DD);
        int r  = idx - l_ * (2*HH*DD);
        v = (r < HH*DD) ? B_re[(size_t)l_*HH*DD + r] : B_im[(size_t)l_*HH*DD + r - HH*DD];
        split2(v, h, l);
        g_bw_h[idx] = h; g_bw_l[idx] = l;
        return;
    }
    idx -= NB;
    if (idx < NC) {
        int l_ = idx / (DD*2*HH);
        int t  = idx - l_ * (DD*2*HH);
        int r  = t >> 11, c = t & 2047;
        if (c < HH) v = C_re[(size_t)l_*DD*HH + r*HH + c];
        else        v = -C_im[(size_t)l_*DD*HH + r*HH + (c - HH)];
        split2(v, h, l);
        g_cw_h[idx] = h; g_cw_l[idx] = l;
        return;
    }
    idx -= NC;
    {
        int l_ = idx / (2*DD*DD);
        int t  = idx - l_ * (2*DD*DD);
        int np = t >> 10, c = t & 1023;
        int blk = np >> 7, off = np & 127;
        if (off < 64) v = w1[(size_t)l_*DD*DD + (blk*64 + off)*DD + c];
        else          v = w2[(size_t)l_*DD*DD + (blk*64 + off - 64)*DD + c];
        split2(v, h, l);
        g_gw_h[idx] = h; g_gw_l[idx] = l;
    }
}

// ---------------- layernorm (+ bf16 split outputs) ----------------
__global__ void ln_kernel(const float* __restrict__ x,
                          const float* __restrict__ sc,
                          const float* __restrict__ bi,
                          float* __restrict__ o,
                          bf16* __restrict__ oh, bf16* __restrict__ ol) {
    __shared__ float red[16];
    int row = blockIdx.x;
    int tid = threadIdx.x;
    const float* xr = x + (size_t)row * DD;
    float4 v = *(const float4*)(xr + tid * 4);
    float s  = v.x + v.y + v.z + v.w;
    float ss = v.x*v.x + v.y*v.y + v.z*v.z + v.w*v.w;
    #pragma unroll
    for (int off = 16; off; off >>= 1) {
        s  += __shfl_xor_sync(0xffffffffu, s,  off);
        ss += __shfl_xor_sync(0xffffffffu, ss, off);
    }
    int wid = tid >> 5;
    if ((tid & 31) == 0) { red[wid] = s; red[8 + wid] = ss; }
    __syncthreads();
    float S = 0.f, SS = 0.f;
    #pragma unroll
    for (int w = 0; w < 8; w++) { S += red[w]; SS += red[8 + w]; }
    float mu  = S * (1.0f / DD);
    float var = SS * (1.0f / DD) - mu * mu;
    float rstd = rsqrtf(var + 1e-5f);
    float4 s4 = *(const float4*)(sc + tid * 4);
    float4 b4 = *(const float4*)(bi + tid * 4);
    float ov[4];
    ov[0] = (v.x - mu) * rstd * s4.x + b4.x;
    ov[1] = (v.y - mu) * rstd * s4.y + b4.y;
    ov[2] = (v.z - mu) * rstd * s4.z + b4.z;
    ov[3] = (v.w - mu) * rstd * s4.w + b4.w;
    *(float4*)(o + (size_t)row * DD + tid * 4) = make_float4(ov[0], ov[1], ov[2], ov[3]);
    bf16 h[4], l[4];
    #pragma unroll
    for (int j = 0; j < 4; j++) split2(ov[j], h[j], l[j]);
    *(uint2*)(oh + (size_t)row * DD + tid * 4) = *(uint2*)h;
    *(uint2*)(ol + (size_t)row * DD + tid * 4) = *(uint2*)l;
}

// ---------------- scan ----------------
__global__ void scan_sum_kernel(const float* __restrict__ bu, int loff) {
    int h = blockIdx.x * blockDim.x + threadIdx.x;
    int c = blockIdx.y, b = blockIdx.z;
    float lre = g_lam_re[loff + h], lim = g_lam_im[loff + h];
    size_t base = ((size_t)(b * TT + c * CL)) * (2 * HH) + h;
    float are = 0.f, aim = 0.f;
    #pragma unroll 8
    for (int j = 0; j < CL; j++) {
        float ure = bu[base], uim = bu[base + HH];
        float nr = fmaf(are, lre, fmaf(-aim, lim, ure));
        float ni = fmaf(are, lim, fmaf(aim, lre, uim));
        are = nr; aim = ni;
        base += 2 * HH;
    }
    int o = (b * NCHUNK + c) * HH + h;
    g_sum_re[o] = are; g_sum_im[o] = aim;
}

__global__ void scan_carry_kernel(int loff) {
    int idx = blockIdx.x * blockDim.x + threadIdx.x;
    int b = idx >> 10, h = idx & (HH - 1);
    float lre = g_lam_re[loff + h], lim = g_lam_im[loff + h];
    float pre = lre, pim = lim;
    #pragma unroll
    for (int i = 0; i < 7; i++) {
        float nr = pre*pre - pim*pim;
        float ni = 2.f*pre*pim;
        pre = nr; pim = ni;
    }
    float cre = 0.f, cim = 0.f;
    #pragma unroll
    for (int c = 0; c < NCHUNK; c++) {
        int o = (b * NCHUNK + c) * HH + h;
        g_car_re[o] = cre; g_car_im[o] = cim;
        float sre = g_sum_re[o], sim = g_sum_im[o];
        float nr = cre*pre - cim*pim + sre;
        float ni = cre*pim + cim*pre + sim;
        cre = nr; cim = ni;
    }
}

__global__ void scan_apply_kernel(const float* __restrict__ bu,
                                  bf16* __restrict__ hsh, bf16* __restrict__ hsl,
                                  int loff) {
    int h = blockIdx.x * blockDim.x + threadIdx.x;
    int c = blockIdx.y, b = blockIdx.z;
    float lre = g_lam_re[loff + h], lim = g_lam_im[loff + h];
    int o = (b * NCHUNK + c) * HH + h;
    float are = g_car_re[o], aim = g_car_im[o];
    size_t base = ((size_t)(b * TT + c * CL)) * (2 * HH) + h;
    #pragma unroll 4
    for (int j = 0; j < CL; j++) {
        float ure = bu[base], uim = bu[base + HH];
        float nr = fmaf(are, lre, fmaf(-aim, lim, ure));
        float ni = fmaf(are, lim, fmaf(aim, lre, uim));
        are = nr; aim = ni;
        bf16 hh, ll;
        split2(are, hh, ll);
        hsh[base] = hh; hsl[base] = ll;
        split2(aim, hh, ll);
        hsh[base + HH] = hh; hsl[base + HH] = ll;
        base += 2 * HH;
    }
}

// ---------------- launch ----------------
extern "C" void kernel_launch(void* const* d_in, const int* in_sizes, int n_in,
                              void* d_out, int out_size) {
    const float* inputs    = (const float*)d_in[0];
    const float* W_in      = (const float*)d_in[1];
    const float* b_in      = (const float*)d_in[2];
    const float* nu_log    = (const float*)d_in[3];
    const float* theta_log = (const float*)d_in[4];
    const float* B_re      = (const float*)d_in[5];
    const float* B_im      = (const float*)d_in[6];
    const float* C_re      = (const float*)d_in[7];
    const float* C_im      = (const float*)d_in[8];
    const float* D_diag    = (const float*)d_in[9];
    const float* ln_scale  = (const float*)d_in[10];
    const float* ln_bias   = (const float*)d_in[11];
    const float* w1        = (const float*)d_in[12];
    const float* b1        = (const float*)d_in[13];
    const float* w2        = (const float*)d_in[14];
    const float* b2        = (const float*)d_in[15];
    float* x = (float*)d_out;

    cudaFuncSetAttribute(gemm_mma, cudaFuncAttributeMaxDynamicSharedMemorySize, SMEMB);

    float *p_xn, *p_bu, *p_gam;
    bf16 *p_xnh, *p_xnl, *p_inh, *p_inl, *p_hsh, *p_hsl, *p_yh, *p_yl;
    bf16 *p_winh, *p_winl, *p_bwh, *p_bwl, *p_cwh, *p_cwl, *p_gwh, *p_gwl;
    cudaGetSymbolAddress((void**)&p_xn,  g_xn);
    cudaGetSymbolAddress((void**)&p_bu,  g_bu);
    cudaGetSymbolAddress((void**)&p_gam, g_gam);
    cudaGetSymbolAddress((void**)&p_xnh, g_xn_h);
    cudaGetSymbolAddress((void**)&p_xnl, g_xn_l);
    cudaGetSymbolAddress((void**)&p_inh, g_in_h);
    cudaGetSymbolAddress((void**)&p_inl, g_in_l);
    cudaGetSymbolAddress((void**)&p_hsh, g_hs_h);
    cudaGetSymbolAddress((void**)&p_hsl, g_hs_l);
    cudaGetSymbolAddress((void**)&p_yh,  g_y_h);
    cudaGetSymbolAddress((void**)&p_yl,  g_y_l);
    cudaGetSymbolAddress((void**)&p_winh, g_win_h);
    cudaGetSymbolAddress((void**)&p_winl, g_win_l);
    cudaGetSymbolAddress((void**)&p_bwh, g_bw_h);
    cudaGetSymbolAddress((void**)&p_bwl, g_bw_l);
    cudaGetSymbolAddress((void**)&p_cwh, g_cw_h);
    cudaGetSymbolAddress((void**)&p_cwl, g_cw_l);
    cudaGetSymbolAddress((void**)&p_gwh, g_gw_h);
    cudaGetSymbolAddress((void**)&p_gwl, g_gw_l);

    // params, split inputs, split all weights
    prep_kernel<<<(LNUM * HH) / 256, 256>>>(nu_log, theta_log);
    split_in_kernel<<<(MTOT*FF)/256, 256>>>(inputs);
    split_wts_kernel<<<(NW + NB + NC + NG)/256, 256>>>(
        W_in, B_re, B_im, C_re, C_im, w1, w2);

    // input projection: x = inputs @ W_in^T + b_in
    gemm_mma<<<dim3(DD/128, MTOT/128), 256, SMEMB>>>(
        p_inh, p_inl, FF, p_winh, p_winl,
        x, nullptr, nullptr, DD, FF, 0,
        b_in, nullptr, nullptr, nullptr);

    for (int l = 0; l < LNUM; l++) {
        // layernorm
        ln_kernel<<<MTOT, 256>>>(x, ln_scale + l*DD, ln_bias + l*DD, p_xn, p_xnh, p_xnl);

        // Bu = gamma * (xn @ [B_re;B_im]^T)
        gemm_mma<<<dim3(2*HH/128, MTOT/128), 256, SMEMB>>>(
            p_xnh, p_xnl, DD,
            p_bwh + (size_t)l*2*HH*DD, p_bwl + (size_t)l*2*HH*DD,
            p_bu, nullptr, nullptr, 2*HH, DD, 1,
            nullptr, nullptr, nullptr, p_gam + l*HH);

        scan_sum_kernel  <<<dim3(HH/256, NCHUNK, BB), 256>>>(p_bu, l*HH);
        scan_carry_kernel<<<(BB*HH)/256, 256>>>(l*HH);
        scan_apply_kernel<<<dim3(HH/256, NCHUNK, BB), 256>>>(p_bu, p_hsh, p_hsl, l*HH);

        // y = gelu( hs @ [C_re | -C_im]^T + xn * D_diag ), output split bf16
        gemm_mma<<<dim3(DD/128, MTOT/128), 256, SMEMB>>>(
            p_hsh, p_hsl, 2*HH,
            p_cwh + (size_t)l*DD*2*HH, p_cwl + (size_t)l*DD*2*HH,
            nullptr, p_yh, p_yl, DD, 2*HH, 2,
            nullptr, nullptr, p_xn, D_diag + l*DD);

        // fused GLU + residual: x += (y@w1^T + b1) * sigmoid(y@w2^T + b2)
        gemm_mma<<<dim3(2*DD/128, MTOT/128), 256, SMEMB>>>(
            p_yh, p_yl, DD,
            p_gwh + (size_t)l*2*DD*DD, p_gwl + (size_t)l*2*DD*DD,
            x, nullptr, nullptr, DD, DD, 3,
            b1 + l*DD, b2 + l*DD, nullptr, nullptr);
    }
    (void)in_sizes; (void)n_in; (void)out_size;
}

// round 9
// speedup vs baseline: 4.0602x; 1.3589x over previous
#include <cuda_runtime.h>
#include <cuda_fp16.h>
#include <math.h>
#include <stdint.h>

// ---------------- problem constants ----------------
#define LNUM 4
#define BB   4
#define TT   2048
#define DD   1024
#define HH   1024
#define FF   256
#define MTOT (BB*TT)          // 8192
#define NCHUNK 16
#define CL   (TT/NCHUNK)      // 128

// ---------------- mma GEMM config ----------------
#define BKC   32                      // k elements per stage
#define MATB  (128*64)                // 128 rows x 64B (swizzled, no pad)
#define STAGEB (3*MATB)               // Ah, Al, W = 24 KB
#define NSTG  3
#define SMEMB (NSTG*STAGEB)           // 73728 B -> 2 CTAs/SM
#define QS    72                      // fused-GLU smem staging stride (floats)

typedef __half f16;

// ---------------- scratch (device globals; no allocs allowed) ----------------
__device__ __align__(16) float g_xn[MTOT*DD];
__device__ __align__(16) f16   g_xn_h[MTOT*DD];
__device__ __align__(16) f16   g_xn_l[MTOT*DD];
__device__ __align__(16) f16   g_in_h[MTOT*FF];
__device__ __align__(16) f16   g_in_l[MTOT*FF];
__device__ __align__(16) float g_bu[MTOT*2*HH];
__device__ __align__(16) f16   g_hs_h[MTOT*2*HH];
__device__ __align__(16) f16   g_hs_l[MTOT*2*HH];
__device__ __align__(16) f16   g_y_h[MTOT*DD];
__device__ __align__(16) f16   g_y_l[MTOT*DD];
__device__ __align__(16) f16   g_win[DD*FF];
__device__ __align__(16) f16   g_bw[LNUM*2*HH*DD];
__device__ __align__(16) f16   g_cw[LNUM*DD*2*HH];
__device__ __align__(16) f16   g_gw[LNUM*2*DD*DD];
__device__ float g_lam_re[LNUM*HH];
__device__ float g_lam_im[LNUM*HH];
__device__ float g_gam  [LNUM*HH];
__device__ float g_sum_re[BB*NCHUNK*HH];
__device__ float g_sum_im[BB*NCHUNK*HH];
__device__ float g_car_re[BB*NCHUNK*HH];
__device__ float g_car_im[BB*NCHUNK*HH];

// ---------------- helpers ----------------
__device__ __forceinline__ float gelu_exact(float v) {
    return 0.5f * v * (1.0f + erff(v * 0.70710678118654752f));
}
__device__ __forceinline__ void split2h(float v, f16& h, f16& l) {
    h = __float2half_rn(v);
    l = __float2half_rn(v - __half2float(h));
}
__device__ __forceinline__ void cp16(uint32_t d, const void* s) {
    asm volatile("cp.async.cg.shared.global [%0], [%1], 16;" :: "r"(d), "l"(s));
}
__device__ __forceinline__ void cpcommit() {
    asm volatile("cp.async.commit_group;" ::: "memory");
}
template<int N> __device__ __forceinline__ void cpwait() {
    asm volatile("cp.async.wait_group %0;" :: "n"(N) : "memory");
}
__device__ __forceinline__ void mma_f16(float* c, const uint32_t* a,
                                        uint32_t b0, uint32_t b1) {
    asm volatile("mma.sync.aligned.m16n8k16.row.col.f32.f16.f16.f32 "
        "{%0,%1,%2,%3}, {%4,%5,%6,%7}, {%8,%9}, {%0,%1,%2,%3};"
        : "+f"(c[0]), "+f"(c[1]), "+f"(c[2]), "+f"(c[3])
        : "r"(a[0]), "r"(a[1]), "r"(a[2]), "r"(a[3]), "r"(b0), "r"(b1));
}
__device__ __forceinline__ void ldm4(uint32_t* r, uint32_t a) {
    asm volatile("ldmatrix.sync.aligned.m8n8.x4.shared.b16 {%0,%1,%2,%3}, [%4];"
        : "=r"(r[0]), "=r"(r[1]), "=r"(r[2]), "=r"(r[3]) : "r"(a));
}

// swizzled chunk offset: row r (64B rows), 16B-chunk c
__device__ __forceinline__ uint32_t swz(int r, int c) {
    return (uint32_t)(r * 64 + ((c ^ ((r >> 1) & 3)) << 4));
}

// load one K-stage: Ah, Al (rows m0..) and W (rows n0..)
__device__ __forceinline__ void ldstage(uint32_t sb, int slot,
        const f16* Ah, const f16* Al, int lda,
        const f16* W, int ldw,
        int m0, int n0, int kb, int tid) {
    uint32_t st = sb + (uint32_t)slot * STAGEB;
    #pragma unroll
    for (int j = 0; j < 2; j++) {
        int chunk = tid + j * 256;
        int row   = chunk >> 2;
        int c     = chunk & 3;
        uint32_t d = st + swz(row, c);
        int ke = kb + c * 8;
        cp16(d,           Ah + (size_t)(m0+row)*lda + ke);
        cp16(d +   MATB,  Al + (size_t)(m0+row)*lda + ke);
        cp16(d + 2*MATB,  W  + (size_t)(n0+row)*ldw + ke);
    }
    cpcommit();
}

// ---------------- split-fp16 2-pass tensor-core GEMM ----------------
// C[m,n] = sum_k A[m,k]*W[n,k];  A = Ah+Al (fp16 planes), W = fp16 (rn)
// epi 0: Cf = acc + bias0(n)
// epi 1: Cf = acc * epi_n[n & 1023]
// epi 2: Ch/Cl = split(gelu(acc + epi_m[m*1024+n]*epi_n[n]))
// epi 3: fused GLU: W interleaved [w1|w2] per 128-tile; x += (a+b1)*sigmoid(q+b2)
__global__ __launch_bounds__(256, 2)
void gemm_mma(const f16* __restrict__ Ah, const f16* __restrict__ Al, int lda,
              const f16* __restrict__ W,
              float* __restrict__ Cf, f16* __restrict__ Ch, f16* __restrict__ Cl,
              int ldc, int K, int epi,
              const float* __restrict__ bias0, const float* __restrict__ bias1,
              const float* __restrict__ epi_m, const float* __restrict__ epi_n) {
    extern __shared__ __align__(16) char smc[];
    uint32_t sb = (uint32_t)__cvta_generic_to_shared(smc);
    const int tid  = threadIdx.x;
    const int wid  = tid >> 5, lane = tid & 31;
    const int g    = lane >> 2, t2 = lane & 3;
    const int warpM = wid & 3;
    const int warpN = wid >> 2;
    const int m0 = blockIdx.y * 128;
    const int n0 = blockIdx.x * 128;
    const int NCH = K / BKC;

    // ldmatrix per-lane rows / chunk bases
    const int grp = lane >> 3, rr = lane & 7;
    const int cA0 = grp >> 1;           // A chunk base (0/1)
    const int cB0 = grp & 1;            // B chunk base (0/1)
    int  rA[2], rB[4];
    #pragma unroll
    for (int mt = 0; mt < 2; mt++) rA[mt] = warpM*32 + mt*16 + rr + (grp & 1)*8;
    #pragma unroll
    for (int ntp = 0; ntp < 4; ntp++) rB[ntp] = warpN*64 + ntp*16 + rr + (grp >> 1)*8;

    float acc[2][8][4];
    #pragma unroll
    for (int i = 0; i < 2; i++)
        #pragma unroll
        for (int j = 0; j < 8; j++)
            #pragma unroll
            for (int q = 0; q < 4; q++) acc[i][j][q] = 0.f;

    // prologue: stages 0,1 in flight; wait stage 0, publish
    ldstage(sb, 0, Ah, Al, lda, W, K, m0, n0, 0,   tid);
    ldstage(sb, 1, Ah, Al, lda, W, K, m0, n0, BKC, tid);
    cpwait<1>();
    __syncthreads();

    int slot = 0;
    for (int t = 0; t < NCH; t++) {
        // issue loads for stage t+2 first (overlap with compute below)
        if (t + 2 < NCH)
            ldstage(sb, (t + 2) % NSTG, Ah, Al, lda, W, K, m0, n0, (t+2)*BKC, tid);
        else
            cpcommit();

        uint32_t st   = sb + (uint32_t)slot * STAGEB;
        uint32_t Ah_s = st, Al_s = st + MATB, W_s = st + 2*MATB;

        #pragma unroll
        for (int kh = 0; kh < 2; kh++) {
            uint32_t ah[2][4], al[2][4];
            #pragma unroll
            for (int mt = 0; mt < 2; mt++) {
                uint32_t ao = swz(rA[mt], cA0 + 2*kh);
                ldm4(ah[mt], Ah_s + ao);
                ldm4(al[mt], Al_s + ao);
            }
            #pragma unroll
            for (int ntp = 0; ntp < 4; ntp++) {
                uint32_t bo = swz(rB[ntp], cB0 + 2*kh);
                uint32_t bh[4];
                ldm4(bh, W_s + bo);
                int nt0 = ntp*2, nt1 = ntp*2 + 1;
                // pass hi
                mma_f16(acc[0][nt0], ah[0], bh[0], bh[1]);
                mma_f16(acc[1][nt0], ah[1], bh[0], bh[1]);
                mma_f16(acc[0][nt1], ah[0], bh[2], bh[3]);
                mma_f16(acc[1][nt1], ah[1], bh[2], bh[3]);
                // pass lo
                mma_f16(acc[0][nt0], al[0], bh[0], bh[1]);
                mma_f16(acc[1][nt0], al[1], bh[0], bh[1]);
                mma_f16(acc[0][nt1], al[0], bh[2], bh[3]);
                mma_f16(acc[1][nt1], al[1], bh[2], bh[3]);
            }
        }

        cpwait<1>();
        __syncthreads();
        slot = (slot + 1 == NSTG) ? 0 : slot + 1;
    }

    // ---- epilogue ----
    if (epi == 3) {
        // fused GLU: tile cols 0-63 = w1 (a), 64-127 = w2 (q); output cols co..co+63
        const int co = blockIdx.x * 64;
        float* qs = (float*)smc;
        if (warpN == 1) {
            #pragma unroll
            for (int mt = 0; mt < 2; mt++)
                #pragma unroll
                for (int nt = 0; nt < 8; nt++) {
                    int r0 = warpM*32 + mt*16 + g, r1 = r0 + 8;
                    int c  = nt*8 + t2*2;
                    float bb0 = bias1[co + c], bb1 = bias1[co + c + 1];
                    qs[r0*QS + c]     = acc[mt][nt][0] + bb0;
                    qs[r0*QS + c + 1] = acc[mt][nt][1] + bb1;
                    qs[r1*QS + c]     = acc[mt][nt][2] + bb0;
                    qs[r1*QS + c + 1] = acc[mt][nt][3] + bb1;
                }
        }
        __syncthreads();
        if (warpN == 0) {
            #pragma unroll
            for (int mt = 0; mt < 2; mt++)
                #pragma unroll
                for (int nt = 0; nt < 8; nt++) {
                    int r0 = warpM*32 + mt*16 + g, r1 = r0 + 8;
                    int c  = nt*8 + t2*2;
                    float bb0 = bias0[co + c], bb1 = bias0[co + c + 1];
                    float a00 = acc[mt][nt][0] + bb0, a01 = acc[mt][nt][1] + bb1;
                    float a10 = acc[mt][nt][2] + bb0, a11 = acc[mt][nt][3] + bb1;
                    float q00 = qs[r0*QS + c], q01 = qs[r0*QS + c + 1];
                    float q10 = qs[r1*QS + c], q11 = qs[r1*QS + c + 1];
                    float* x0 = Cf + (size_t)(m0 + r0) * DD + co + c;
                    float* x1 = Cf + (size_t)(m0 + r1) * DD + co + c;
                    float2 v0 = *(float2*)x0, v1 = *(float2*)x1;
                    v0.x = fmaf(a00, 1.f/(1.f + expf(-q00)), v0.x);
                    v0.y = fmaf(a01, 1.f/(1.f + expf(-q01)), v0.y);
                    v1.x = fmaf(a10, 1.f/(1.f + expf(-q10)), v1.x);
                    v1.y = fmaf(a11, 1.f/(1.f + expf(-q11)), v1.y);
                    *(float2*)x0 = v0;
                    *(float2*)x1 = v1;
                }
        }
        return;
    }
    #pragma unroll
    for (int mt = 0; mt < 2; mt++) {
        #pragma unroll
        for (int nt = 0; nt < 8; nt++) {
            int row0 = m0 + warpM*32 + mt*16 + g;
            int row1 = row0 + 8;
            int col  = n0 + warpN*64 + nt*8 + t2*2;
            float c0 = acc[mt][nt][0], c1 = acc[mt][nt][1];
            float c2 = acc[mt][nt][2], c3 = acc[mt][nt][3];
            if (epi == 0) {
                float b0v = bias0[col], b1v = bias0[col + 1];
                *(float2*)(Cf + (size_t)row0 * ldc + col) = make_float2(c0 + b0v, c1 + b1v);
                *(float2*)(Cf + (size_t)row1 * ldc + col) = make_float2(c2 + b0v, c3 + b1v);
            } else if (epi == 1) {
                float e0 = epi_n[col & (HH-1)], e1 = epi_n[(col+1) & (HH-1)];
                *(float2*)(Cf + (size_t)row0 * ldc + col) = make_float2(c0*e0, c1*e1);
                *(float2*)(Cf + (size_t)row1 * ldc + col) = make_float2(c2*e0, c3*e1);
            } else {
                float d0 = epi_n[col], d1 = epi_n[col+1];
                float2 x0 = *(const float2*)(epi_m + (size_t)row0 * DD + col);
                float2 x1 = *(const float2*)(epi_m + (size_t)row1 * DD + col);
                float v0 = gelu_exact(c0 + x0.x * d0);
                float v1 = gelu_exact(c1 + x0.y * d1);
                float v2 = gelu_exact(c2 + x1.x * d0);
                float v3 = gelu_exact(c3 + x1.y * d1);
                f16 h0,l0,h1,l1,h2,l2,h3,l3;
                split2h(v0,h0,l0); split2h(v1,h1,l1);
                split2h(v2,h2,l2); split2h(v3,h3,l3);
                __half2 ph0(h0,h1), pl0(l0,l1), ph1(h2,h3), pl1(l2,l3);
                *(uint32_t*)(Ch + (size_t)row0 * ldc + col) = *(uint32_t*)&ph0;
                *(uint32_t*)(Cl + (size_t)row0 * ldc + col) = *(uint32_t*)&pl0;
                *(uint32_t*)(Ch + (size_t)row1 * ldc + col) = *(uint32_t*)&ph1;
                *(uint32_t*)(Cl + (size_t)row1 * ldc + col) = *(uint32_t*)&pl1;
            }
        }
    }
}

// ---------------- parameter prep ----------------
__global__ void prep_kernel(const float* __restrict__ nu_log,
                            const float* __restrict__ theta_log) {
    int i = blockIdx.x * blockDim.x + threadIdx.x;
    float nu = expf(nu_log[i]);
    float th = expf(theta_log[i]);
    float r  = expf(-nu);
    g_lam_re[i] = r * cosf(th);
    g_lam_im[i] = r * sinf(th);
    g_gam[i]    = sqrtf(1.0f - expf(-2.0f * nu) + 1e-5f);
}

// ---------------- input splitter ----------------
__global__ void split_in_kernel(const float* __restrict__ s) {
    int i = blockIdx.x * 256 + threadIdx.x;
    f16 h, l;
    split2h(s[i], h, l);
    g_in_h[i] = h; g_in_l[i] = l;
}

// ---------------- all-weights converter (single fp16 plane) ----------------
#define NW  (DD*FF)
#define NB  (LNUM*2*HH*DD)
#define NC  (LNUM*DD*2*HH)
#define NG  (LNUM*2*DD*DD)
__global__ void split_wts_kernel(const float* __restrict__ W_in,
                                 const float* __restrict__ B_re,
                                 const float* __restrict__ B_im,
                                 const float* __restrict__ C_re,
                                 const float* __restrict__ C_im,
                                 const float* __restrict__ w1,
                                 const float* __restrict__ w2) {
    int idx = blockIdx.x * 256 + threadIdx.x;
    float v;
    if (idx < NW) {
        g_win[idx] = __float2half_rn(W_in[idx]);
        return;
    }
    idx -= NW;
    if (idx < NB) {
        int l_ = idx / (2*HH*DD);
        int r  = idx - l_ * (2*HH*DD);
        v = (r < HH*DD) ? B_re[(size_t)l_*HH*DD + r] : B_im[(size_t)l_*HH*DD + r - HH*DD];
        g_bw[idx] = __float2half_rn(v);
        return;
    }
    idx -= NB;
    if (idx < NC) {
        int l_ = idx / (DD*2*HH);
        int t  = idx - l_ * (DD*2*HH);
        int r  = t >> 11, c = t & 2047;
        if (c < HH) v = C_re[(size_t)l_*DD*HH + r*HH + c];
        else        v = -C_im[(size_t)l_*DD*HH + r*HH + (c - HH)];
        g_cw[idx] = __float2half_rn(v);
        return;
    }
    idx -= NC;
    {
        int l_ = idx / (2*DD*DD);
        int t  = idx - l_ * (2*DD*DD);
        int np = t >> 10, c = t & 1023;
        int blk = np >> 7, off = np & 127;
        if (off < 64) v = w1[(size_t)l_*DD*DD + (blk*64 + off)*DD + c];
        else          v = w2[(size_t)l_*DD*DD + (blk*64 + off - 64)*DD + c];
        g_gw[idx] = __float2half_rn(v);
    }
}

// ---------------- layernorm (+ fp16 split outputs) ----------------
__global__ void ln_kernel(const float* __restrict__ x,
                          const float* __restrict__ sc,
                          const float* __restrict__ bi,
                          float* __restrict__ o,
                          f16* __restrict__ oh, f16* __restrict__ ol) {
    __shared__ float red[16];
    int row = blockIdx.x;
    int tid = threadIdx.x;
    const float* xr = x + (size_t)row * DD;
    float4 v = *(const float4*)(xr + tid * 4);
    float s  = v.x + v.y + v.z + v.w;
    float ss = v.x*v.x + v.y*v.y + v.z*v.z + v.w*v.w;
    #pragma unroll
    for (int off = 16; off; off >>= 1) {
        s  += __shfl_xor_sync(0xffffffffu, s,  off);
        ss += __shfl_xor_sync(0xffffffffu, ss, off);
    }
    int wid = tid >> 5;
    if ((tid & 31) == 0) { red[wid] = s; red[8 + wid] = ss; }
    __syncthreads();
    float S = 0.f, SS = 0.f;
    #pragma unroll
    for (int w = 0; w < 8; w++) { S += red[w]; SS += red[8 + w]; }
    float mu  = S * (1.0f / DD);
    float var = SS * (1.0f / DD) - mu * mu;
    float rstd = rsqrtf(var + 1e-5f);
    float4 s4 = *(const float4*)(sc + tid * 4);
    float4 b4 = *(const float4*)(bi + tid * 4);
    float ov[4];
    ov[0] = (v.x - mu) * rstd * s4.x + b4.x;
    ov[1] = (v.y - mu) * rstd * s4.y + b4.y;
    ov[2] = (v.z - mu) * rstd * s4.z + b4.z;
    ov[3] = (v.w - mu) * rstd * s4.w + b4.w;
    *(float4*)(o + (size_t)row * DD + tid * 4) = make_float4(ov[0], ov[1], ov[2], ov[3]);
    f16 h[4], l[4];
    #pragma unroll
    for (int j = 0; j < 4; j++) split2h(ov[j], h[j], l[j]);
    *(uint2*)(oh + (size_t)row * DD + tid * 4) = *(uint2*)h;
    *(uint2*)(ol + (size_t)row * DD + tid * 4) = *(uint2*)l;
}

// ---------------- scan ----------------
__global__ void scan_sum_kernel(const float* __restrict__ bu, int loff) {
    int h = blockIdx.x * blockDim.x + threadIdx.x;
    int c = blockIdx.y, b = blockIdx.z;
    float lre = g_lam_re[loff + h], lim = g_lam_im[loff + h];
    size_t base = ((size_t)(b * TT + c * CL)) * (2 * HH) + h;
    float are = 0.f, aim = 0.f;
    #pragma unroll 8
    for (int j = 0; j < CL; j++) {
        float ure = bu[base], uim = bu[base + HH];
        float nr = fmaf(are, lre, fmaf(-aim, lim, ure));
        float ni = fmaf(are, lim, fmaf(aim, lre, uim));
        are = nr; aim = ni;
        base += 2 * HH;
    }
    int o = (b * NCHUNK + c) * HH + h;
    g_sum_re[o] = are; g_sum_im[o] = aim;
}

__global__ void scan_carry_kernel(int loff) {
    int idx = blockIdx.x * blockDim.x + threadIdx.x;
    int b = idx >> 10, h = idx & (HH - 1);
    float lre = g_lam_re[loff + h], lim = g_lam_im[loff + h];
    float pre = lre, pim = lim;
    #pragma unroll
    for (int i = 0; i < 7; i++) {
        float nr = pre*pre - pim*pim;
        float ni = 2.f*pre*pim;
        pre = nr; pim = ni;
    }
    float cre = 0.f, cim = 0.f;
    #pragma unroll
    for (int c = 0; c < NCHUNK; c++) {
        int o = (b * NCHUNK + c) * HH + h;
        g_car_re[o] = cre; g_car_im[o] = cim;
        float sre = g_sum_re[o], sim = g_sum_im[o];
        float nr = cre*pre - cim*pim + sre;
        float ni = cre*pim + cim*pre + sim;
        cre = nr; cim = ni;
    }
}

__global__ void scan_apply_kernel(const float* __restrict__ bu,
                                  f16* __restrict__ hsh, f16* __restrict__ hsl,
                                  int loff) {
    int h = blockIdx.x * blockDim.x + threadIdx.x;
    int c = blockIdx.y, b = blockIdx.z;
    float lre = g_lam_re[loff + h], lim = g_lam_im[loff + h];
    int o = (b * NCHUNK + c) * HH + h;
    float are = g_car_re[o], aim = g_car_im[o];
    size_t base = ((size_t)(b * TT + c * CL)) * (2 * HH) + h;
    #pragma unroll 4
    for (int j = 0; j < CL; j++) {
        float ure = bu[base], uim = bu[base + HH];
        float nr = fmaf(are, lre, fmaf(-aim, lim, ure));
        float ni = fmaf(are, lim, fmaf(aim, lre, uim));
        are = nr; aim = ni;
        f16 hh, ll;
        split2h(are, hh, ll);
        hsh[base] = hh; hsl[base] = ll;
        split2h(aim, hh, ll);
        hsh[base + HH] = hh; hsl[base + HH] = ll;
        base += 2 * HH;
    }
}

// ---------------- launch ----------------
extern "C" void kernel_launch(void* const* d_in, const int* in_sizes, int n_in,
                              void* d_out, int out_size) {
    const float* inputs    = (const float*)d_in[0];
    const float* W_in      = (const float*)d_in[1];
    const float* b_in      = (const float*)d_in[2];
    const float* nu_log    = (const float*)d_in[3];
    const float* theta_log = (const float*)d_in[4];
    const float* B_re      = (const float*)d_in[5];
    const float* B_im      = (const float*)d_in[6];
    const float* C_re      = (const float*)d_in[7];
    const float* C_im      = (const float*)d_in[8];
    const float* D_diag    = (const float*)d_in[9];
    const float* ln_scale  = (const float*)d_in[10];
    const float* ln_bias   = (const float*)d_in[11];
    const float* w1        = (const float*)d_in[12];
    const float* b1        = (const float*)d_in[13];
    const float* w2        = (const float*)d_in[14];
    const float* b2        = (const float*)d_in[15];
    float* x = (float*)d_out;

    cudaFuncSetAttribute(gemm_mma, cudaFuncAttributeMaxDynamicSharedMemorySize, SMEMB);

    float *p_xn, *p_bu, *p_gam;
    f16 *p_xnh, *p_xnl, *p_inh, *p_inl, *p_hsh, *p_hsl, *p_yh, *p_yl;
    f16 *p_win, *p_bw, *p_cw, *p_gw;
    cudaGetSymbolAddress((void**)&p_xn,  g_xn);
    cudaGetSymbolAddress((void**)&p_bu,  g_bu);
    cudaGetSymbolAddress((void**)&p_gam, g_gam);
    cudaGetSymbolAddress((void**)&p_xnh, g_xn_h);
    cudaGetSymbolAddress((void**)&p_xnl, g_xn_l);
    cudaGetSymbolAddress((void**)&p_inh, g_in_h);
    cudaGetSymbolAddress((void**)&p_inl, g_in_l);
    cudaGetSymbolAddress((void**)&p_hsh, g_hs_h);
    cudaGetSymbolAddress((void**)&p_hsl, g_hs_l);
    cudaGetSymbolAddress((void**)&p_yh,  g_y_h);
    cudaGetSymbolAddress((void**)&p_yl,  g_y_l);
    cudaGetSymbolAddress((void**)&p_win, g_win);
    cudaGetSymbolAddress((void**)&p_bw,  g_bw);
    cudaGetSymbolAddress((void**)&p_cw,  g_cw);
    cudaGetSymbolAddress((void**)&p_gw,  g_gw);

    // params, split inputs, convert all weights
    prep_kernel<<<(LNUM * HH) / 256, 256>>>(nu_log, theta_log);
    split_in_kernel<<<(MTOT*FF)/256, 256>>>(inputs);
    split_wts_kernel<<<(NW + NB + NC + NG)/256, 256>>>(
        W_in, B_re, B_im, C_re, C_im, w1, w2);

    // input projection: x = inputs @ W_in^T + b_in
    gemm_mma<<<dim3(DD/128, MTOT/128), 256, SMEMB>>>(
        p_inh, p_inl, FF, p_win,
        x, nullptr, nullptr, DD, FF, 0,
        b_in, nullptr, nullptr, nullptr);

    for (int l = 0; l < LNUM; l++) {
        // layernorm
        ln_kernel<<<MTOT, 256>>>(x, ln_scale + l*DD, ln_bias + l*DD, p_xn, p_xnh, p_xnl);

        // Bu = gamma * (xn @ [B_re;B_im]^T)
        gemm_mma<<<dim3(2*HH/128, MTOT/128), 256, SMEMB>>>(
            p_xnh, p_xnl, DD,
            p_bw + (size_t)l*2*HH*DD,
            p_bu, nullptr, nullptr, 2*HH, DD, 1,
            nullptr, nullptr, nullptr, p_gam + l*HH);

        scan_sum_kernel  <<<dim3(HH/256, NCHUNK, BB), 256>>>(p_bu, l*HH);
        scan_carry_kernel<<<(BB*HH)/256, 256>>>(l*HH);
        scan_apply_kernel<<<dim3(HH/256, NCHUNK, BB), 256>>>(p_bu, p_hsh, p_hsl, l*HH);

        // y = gelu( hs @ [C_re | -C_im]^T + xn * D_diag ), output split fp16
        gemm_mma<<<dim3(DD/128, MTOT/128), 256, SMEMB>>>(
            p_hsh, p_hsl, 2*HH,
            p_cw + (size_t)l*DD*2*HH,
            nullptr, p_yh, p_yl, DD, 2*HH, 2,
            nullptr, nullptr, p_xn, D_diag + l*DD);

        // fused GLU + residual: x += (y@w1^T + b1) * sigmoid(y@w2^T + b2)
        gemm_mma<<<dim3(2*DD/128, MTOT/128), 256, SMEMB>>>(
            p_yh, p_yl, DD,
            p_gw + (size_t)l*2*DD*DD,
            x, nullptr, nullptr, DD, DD, 3,
            b1 + l*DD, b2 + l*DD, nullptr, nullptr);
    }
    (void)in_sizes; (void)n_in; (void)out_size;
}

// round 10
// speedup vs baseline: 4.0691x; 1.0022x over previous
#include <cuda_runtime.h>
#include <cuda_fp16.h>
#include <math.h>
#include <stdint.h>

// ---------------- problem constants ----------------
#define LNUM 4
#define BB   4
#define TT   2048
#define DD   1024
#define HH   1024
#define FF   256
#define MTOT (BB*TT)          // 8192
#define NCHUNK 16
#define CL   (TT/NCHUNK)      // 128

// ---------------- mma GEMM config ----------------
#define BKC   32                      // k elements per stage
#define MATB  (128*64)                // 128 rows x 64B (swizzled, no pad)
#define STAGEB (3*MATB)               // Ah, Al, W = 24 KB
#define NSTG  3
#define SMEMB (NSTG*STAGEB)           // 73728 B -> 2 CTAs/SM
#define QS    72                      // fused-GLU smem staging stride (floats)

typedef __half f16;

// ---------------- scratch (device globals; no allocs allowed) ----------------
__device__ __align__(16) f16   g_xn_h[MTOT*DD];
__device__ __align__(16) f16   g_xn_l[MTOT*DD];
__device__ __align__(16) f16   g_in_h[MTOT*FF];
__device__ __align__(16) f16   g_in_l[MTOT*FF];
__device__ __align__(16) float g_bu[MTOT*2*HH];
__device__ __align__(16) f16   g_hs_h[MTOT*2*HH];
__device__ __align__(16) f16   g_hs_l[MTOT*2*HH];
__device__ __align__(16) f16   g_y_h[MTOT*DD];
__device__ __align__(16) f16   g_win[DD*FF];
__device__ __align__(16) f16   g_bw[LNUM*2*HH*DD];
__device__ __align__(16) f16   g_cw[LNUM*DD*2*HH];
__device__ __align__(16) f16   g_gw[LNUM*2*DD*DD];
__device__ float g_lam_re[LNUM*HH];
__device__ float g_lam_im[LNUM*HH];
__device__ float g_gam  [LNUM*HH];
__device__ float g_sum_re[BB*NCHUNK*HH];
__device__ float g_sum_im[BB*NCHUNK*HH];
__device__ float g_car_re[BB*NCHUNK*HH];
__device__ float g_car_im[BB*NCHUNK*HH];

// ---------------- helpers ----------------
__device__ __forceinline__ float gelu_exact(float v) {
    return 0.5f * v * (1.0f + erff(v * 0.70710678118654752f));
}
__device__ __forceinline__ void split2h(float v, f16& h, f16& l) {
    h = __float2half_rn(v);
    l = __float2half_rn(v - __half2float(h));
}
__device__ __forceinline__ void cp16(uint32_t d, const void* s) {
    asm volatile("cp.async.cg.shared.global [%0], [%1], 16;" :: "r"(d), "l"(s));
}
__device__ __forceinline__ void cpcommit() {
    asm volatile("cp.async.commit_group;" ::: "memory");
}
template<int N> __device__ __forceinline__ void cpwait() {
    asm volatile("cp.async.wait_group %0;" :: "n"(N) : "memory");
}
__device__ __forceinline__ void mma_f16(float* c, const uint32_t* a,
                                        uint32_t b0, uint32_t b1) {
    asm volatile("mma.sync.aligned.m16n8k16.row.col.f32.f16.f16.f32 "
        "{%0,%1,%2,%3}, {%4,%5,%6,%7}, {%8,%9}, {%0,%1,%2,%3};"
        : "+f"(c[0]), "+f"(c[1]), "+f"(c[2]), "+f"(c[3])
        : "r"(a[0]), "r"(a[1]), "r"(a[2]), "r"(a[3]), "r"(b0), "r"(b1));
}
__device__ __forceinline__ void ldm4(uint32_t* r, uint32_t a) {
    asm volatile("ldmatrix.sync.aligned.m8n8.x4.shared.b16 {%0,%1,%2,%3}, [%4];"
        : "=r"(r[0]), "=r"(r[1]), "=r"(r[2]), "=r"(r[3]) : "r"(a));
}

// swizzled chunk offset: row r (64B rows), 16B-chunk c
__device__ __forceinline__ uint32_t swz(int r, int c) {
    return (uint32_t)(r * 64 + ((c ^ ((r >> 1) & 3)) << 4));
}

// load one K-stage: Ah, Al (rows m0..) and W (rows n0..)
__device__ __forceinline__ void ldstage(uint32_t sb, int slot,
        const f16* Ah, const f16* Al, int lda,
        const f16* W, int ldw,
        int m0, int n0, int kb, int tid) {
    uint32_t st = sb + (uint32_t)slot * STAGEB;
    #pragma unroll
    for (int j = 0; j < 2; j++) {
        int chunk = tid + j * 256;
        int row   = chunk >> 2;
        int c     = chunk & 3;
        uint32_t d = st + swz(row, c);
        int ke = kb + c * 8;
        cp16(d,           Ah + (size_t)(m0+row)*lda + ke);
        cp16(d +   MATB,  Al + (size_t)(m0+row)*lda + ke);
        cp16(d + 2*MATB,  W  + (size_t)(n0+row)*ldw + ke);
    }
    cpcommit();
}

// ---------------- split-fp16 tensor-core GEMM ----------------
// C[m,n] = sum_k A[m,k]*W[n,k];  A = Ah(+Al if Al!=null), W = fp16 (rn)
// epi 0: Cf = acc + bias0(n)
// epi 1: Cf = acc * epi_n[n & 1023]
// epi 2: Ch = half(gelu(acc + (epi_mh+epi_ml)[m,n]*epi_n[n]))
// epi 3: fused GLU: W interleaved [w1|w2] per 128-tile; x += (a+b1)*sigmoid(q+b2)
__global__ __launch_bounds__(256, 2)
void gemm_mma(const f16* __restrict__ Ah, const f16* __restrict__ Al, int lda,
              const f16* __restrict__ W,
              float* __restrict__ Cf, f16* __restrict__ Ch,
              int ldc, int K, int epi,
              const float* __restrict__ bias0, const float* __restrict__ bias1,
              const f16* __restrict__ epi_mh, const f16* __restrict__ epi_ml,
              const float* __restrict__ epi_n) {
    extern __shared__ __align__(16) char smc[];
    uint32_t sb = (uint32_t)__cvta_generic_to_shared(smc);
    const int tid  = threadIdx.x;
    const int wid  = tid >> 5, lane = tid & 31;
    const int g    = lane >> 2, t2 = lane & 3;
    const int warpM = wid & 3;
    const int warpN = wid >> 2;
    const int m0 = blockIdx.y * 128;
    const int n0 = blockIdx.x * 128;
    const int NCH = K / BKC;
    const bool twopass = (Al != nullptr);
    const f16* Alx = twopass ? Al : Ah;

    // ldmatrix per-lane rows / chunk bases
    const int grp = lane >> 3, rr = lane & 7;
    const int cA0 = grp >> 1;           // A chunk base (0/1)
    const int cB0 = grp & 1;            // B chunk base (0/1)
    int  rA[2], rB[4];
    #pragma unroll
    for (int mt = 0; mt < 2; mt++) rA[mt] = warpM*32 + mt*16 + rr + (grp & 1)*8;
    #pragma unroll
    for (int ntp = 0; ntp < 4; ntp++) rB[ntp] = warpN*64 + ntp*16 + rr + (grp >> 1)*8;

    float acc[2][8][4];
    #pragma unroll
    for (int i = 0; i < 2; i++)
        #pragma unroll
        for (int j = 0; j < 8; j++)
            #pragma unroll
            for (int q = 0; q < 4; q++) acc[i][j][q] = 0.f;

    // prologue: stages 0,1 in flight; wait stage 0, publish
    ldstage(sb, 0, Ah, Alx, lda, W, K, m0, n0, 0,   tid);
    ldstage(sb, 1, Ah, Alx, lda, W, K, m0, n0, BKC, tid);
    cpwait<1>();
    __syncthreads();

    int slot = 0;
    for (int t = 0; t < NCH; t++) {
        // issue loads for stage t+2 first (overlap with compute below)
        if (t + 2 < NCH)
            ldstage(sb, (t + 2) % NSTG, Ah, Alx, lda, W, K, m0, n0, (t+2)*BKC, tid);
        else
            cpcommit();

        uint32_t st   = sb + (uint32_t)slot * STAGEB;
        uint32_t Ah_s = st, Al_s = st + MATB, W_s = st + 2*MATB;

        #pragma unroll
        for (int kh = 0; kh < 2; kh++) {
            uint32_t ah[2][4], al[2][4];
            #pragma unroll
            for (int mt = 0; mt < 2; mt++) {
                uint32_t ao = swz(rA[mt], cA0 + 2*kh);
                ldm4(ah[mt], Ah_s + ao);
                if (twopass) ldm4(al[mt], Al_s + ao);
            }
            #pragma unroll
            for (int ntp = 0; ntp < 4; ntp++) {
                uint32_t bo = swz(rB[ntp], cB0 + 2*kh);
                uint32_t bh[4];
                ldm4(bh, W_s + bo);
                int nt0 = ntp*2, nt1 = ntp*2 + 1;
                // pass hi
                mma_f16(acc[0][nt0], ah[0], bh[0], bh[1]);
                mma_f16(acc[1][nt0], ah[1], bh[0], bh[1]);
                mma_f16(acc[0][nt1], ah[0], bh[2], bh[3]);
                mma_f16(acc[1][nt1], ah[1], bh[2], bh[3]);
                // pass lo
                if (twopass) {
                    mma_f16(acc[0][nt0], al[0], bh[0], bh[1]);
                    mma_f16(acc[1][nt0], al[1], bh[0], bh[1]);
                    mma_f16(acc[0][nt1], al[0], bh[2], bh[3]);
                    mma_f16(acc[1][nt1], al[1], bh[2], bh[3]);
                }
            }
        }

        cpwait<1>();
        __syncthreads();
        slot = (slot + 1 == NSTG) ? 0 : slot + 1;
    }

    // ---- epilogue ----
    if (epi == 3) {
        // fused GLU: tile cols 0-63 = w1 (a), 64-127 = w2 (q); output cols co..co+63
        const int co = blockIdx.x * 64;
        float* qs = (float*)smc;
        if (warpN == 1) {
            #pragma unroll
            for (int mt = 0; mt < 2; mt++)
                #pragma unroll
                for (int nt = 0; nt < 8; nt++) {
                    int r0 = warpM*32 + mt*16 + g, r1 = r0 + 8;
                    int c  = nt*8 + t2*2;
                    float bb0 = bias1[co + c], bb1 = bias1[co + c + 1];
                    qs[r0*QS + c]     = acc[mt][nt][0] + bb0;
                    qs[r0*QS + c + 1] = acc[mt][nt][1] + bb1;
                    qs[r1*QS + c]     = acc[mt][nt][2] + bb0;
                    qs[r1*QS + c + 1] = acc[mt][nt][3] + bb1;
                }
        }
        __syncthreads();
        if (warpN == 0) {
            #pragma unroll
            for (int mt = 0; mt < 2; mt++)
                #pragma unroll
                for (int nt = 0; nt < 8; nt++) {
                    int r0 = warpM*32 + mt*16 + g, r1 = r0 + 8;
                    int c  = nt*8 + t2*2;
                    float bb0 = bias0[co + c], bb1 = bias0[co + c + 1];
                    float a00 = acc[mt][nt][0] + bb0, a01 = acc[mt][nt][1] + bb1;
                    float a10 = acc[mt][nt][2] + bb0, a11 = acc[mt][nt][3] + bb1;
                    float q00 = qs[r0*QS + c], q01 = qs[r0*QS + c + 1];
                    float q10 = qs[r1*QS + c], q11 = qs[r1*QS + c + 1];
                    float* x0 = Cf + (size_t)(m0 + r0) * DD + co + c;
                    float* x1 = Cf + (size_t)(m0 + r1) * DD + co + c;
                    float2 v0 = *(float2*)x0, v1 = *(float2*)x1;
                    v0.x = fmaf(a00, 1.f/(1.f + expf(-q00)), v0.x);
                    v0.y = fmaf(a01, 1.f/(1.f + expf(-q01)), v0.y);
                    v1.x = fmaf(a10, 1.f/(1.f + expf(-q10)), v1.x);
                    v1.y = fmaf(a11, 1.f/(1.f + expf(-q11)), v1.y);
                    *(float2*)x0 = v0;
                    *(float2*)x1 = v1;
                }
        }
        return;
    }
    #pragma unroll
    for (int mt = 0; mt < 2; mt++) {
        #pragma unroll
        for (int nt = 0; nt < 8; nt++) {
            int row0 = m0 + warpM*32 + mt*16 + g;
            int row1 = row0 + 8;
            int col  = n0 + warpN*64 + nt*8 + t2*2;
            float c0 = acc[mt][nt][0], c1 = acc[mt][nt][1];
            float c2 = acc[mt][nt][2], c3 = acc[mt][nt][3];
            if (epi == 0) {
                float b0v = bias0[col], b1v = bias0[col + 1];
                *(float2*)(Cf + (size_t)row0 * ldc + col) = make_float2(c0 + b0v, c1 + b1v);
                *(float2*)(Cf + (size_t)row1 * ldc + col) = make_float2(c2 + b0v, c3 + b1v);
            } else if (epi == 1) {
                float e0 = epi_n[col & (HH-1)], e1 = epi_n[(col+1) & (HH-1)];
                *(float2*)(Cf + (size_t)row0 * ldc + col) = make_float2(c0*e0, c1*e1);
                *(float2*)(Cf + (size_t)row1 * ldc + col) = make_float2(c2*e0, c3*e1);
            } else {
                float d0 = epi_n[col], d1 = epi_n[col+1];
                // reconstruct xn = xn_h + xn_l (fp16 pair, exact to ~2^-22)
                __half2 xh0 = *(const __half2*)(epi_mh + (size_t)row0 * DD + col);
                __half2 xl0 = *(const __half2*)(epi_ml + (size_t)row0 * DD + col);
                __half2 xh1 = *(const __half2*)(epi_mh + (size_t)row1 * DD + col);
                __half2 xl1 = *(const __half2*)(epi_ml + (size_t)row1 * DD + col);
                float m00 = __half2float(xh0.x) + __half2float(xl0.x);
                float m01 = __half2float(xh0.y) + __half2float(xl0.y);
                float m10 = __half2float(xh1.x) + __half2float(xl1.x);
                float m11 = __half2float(xh1.y) + __half2float(xl1.y);
                float v0 = gelu_exact(c0 + m00 * d0);
                float v1 = gelu_exact(c1 + m01 * d1);
                float v2 = gelu_exact(c2 + m10 * d0);
                float v3 = gelu_exact(c3 + m11 * d1);
                __half2 ph0(__float2half_rn(v0), __float2half_rn(v1));
                __half2 ph1(__float2half_rn(v2), __float2half_rn(v3));
                *(uint32_t*)(Ch + (size_t)row0 * ldc + col) = *(uint32_t*)&ph0;
                *(uint32_t*)(Ch + (size_t)row1 * ldc + col) = *(uint32_t*)&ph1;
            }
        }
    }
}

// ---------------- parameter prep ----------------
__global__ void prep_kernel(const float* __restrict__ nu_log,
                            const float* __restrict__ theta_log) {
    int i = blockIdx.x * blockDim.x + threadIdx.x;
    float nu = expf(nu_log[i]);
    float th = expf(theta_log[i]);
    float r  = expf(-nu);
    g_lam_re[i] = r * cosf(th);
    g_lam_im[i] = r * sinf(th);
    g_gam[i]    = sqrtf(1.0f - expf(-2.0f * nu) + 1e-5f);
}

// ---------------- input splitter ----------------
__global__ void split_in_kernel(const float* __restrict__ s) {
    int i = blockIdx.x * 256 + threadIdx.x;
    f16 h, l;
    split2h(s[i], h, l);
    g_in_h[i] = h; g_in_l[i] = l;
}

// ---------------- all-weights converter (single fp16 plane) ----------------
#define NW  (DD*FF)
#define NB  (LNUM*2*HH*DD)
#define NC  (LNUM*DD*2*HH)
#define NG  (LNUM*2*DD*DD)
__global__ void split_wts_kernel(const float* __restrict__ W_in,
                                 const float* __restrict__ B_re,
                                 const float* __restrict__ B_im,
                                 const float* __restrict__ C_re,
                                 const float* __restrict__ C_im,
                                 const float* __restrict__ w1,
                                 const float* __restrict__ w2) {
    int idx = blockIdx.x * 256 + threadIdx.x;
    float v;
    if (idx < NW) {
        g_win[idx] = __float2half_rn(W_in[idx]);
        return;
    }
    idx -= NW;
    if (idx < NB) {
        int l_ = idx / (2*HH*DD);
        int r  = idx - l_ * (2*HH*DD);
        v = (r < HH*DD) ? B_re[(size_t)l_*HH*DD + r] : B_im[(size_t)l_*HH*DD + r - HH*DD];
        g_bw[idx] = __float2half_rn(v);
        return;
    }
    idx -= NB;
    if (idx < NC) {
        int l_ = idx / (DD*2*HH);
        int t  = idx - l_ * (DD*2*HH);
        int r  = t >> 11, c = t & 2047;
        if (c < HH) v = C_re[(size_t)l_*DD*HH + r*HH + c];
        else        v = -C_im[(size_t)l_*DD*HH + r*HH + (c - HH)];
        g_cw[idx] = __float2half_rn(v);
        return;
    }
    idx -= NC;
    {
        int l_ = idx / (2*DD*DD);
        int t  = idx - l_ * (2*DD*DD);
        int np = t >> 10, c = t & 1023;
        int blk = np >> 7, off = np & 127;
        if (off < 64) v = w1[(size_t)l_*DD*DD + (blk*64 + off)*DD + c];
        else          v = w2[(size_t)l_*DD*DD + (blk*64 + off - 64)*DD + c];
        g_gw[idx] = __float2half_rn(v);
    }
}

// ---------------- layernorm (fp16 split outputs only) ----------------
__global__ void ln_kernel(const float* __restrict__ x,
                          const float* __restrict__ sc,
                          const float* __restrict__ bi,
                          f16* __restrict__ oh, f16* __restrict__ ol) {
    __shared__ float red[16];
    int row = blockIdx.x;
    int tid = threadIdx.x;
    const float* xr = x + (size_t)row * DD;
    float4 v = *(const float4*)(xr + tid * 4);
    float s  = v.x + v.y + v.z + v.w;
    float ss = v.x*v.x + v.y*v.y + v.z*v.z + v.w*v.w;
    #pragma unroll
    for (int off = 16; off; off >>= 1) {
        s  += __shfl_xor_sync(0xffffffffu, s,  off);
        ss += __shfl_xor_sync(0xffffffffu, ss, off);
    }
    int wid = tid >> 5;
    if ((tid & 31) == 0) { red[wid] = s; red[8 + wid] = ss; }
    __syncthreads();
    float S = 0.f, SS = 0.f;
    #pragma unroll
    for (int w = 0; w < 8; w++) { S += red[w]; SS += red[8 + w]; }
    float mu  = S * (1.0f / DD);
    float var = SS * (1.0f / DD) - mu * mu;
    float rstd = rsqrtf(var + 1e-5f);
    float4 s4 = *(const float4*)(sc + tid * 4);
    float4 b4 = *(const float4*)(bi + tid * 4);
    float ov[4];
    ov[0] = (v.x - mu) * rstd * s4.x + b4.x;
    ov[1] = (v.y - mu) * rstd * s4.y + b4.y;
    ov[2] = (v.z - mu) * rstd * s4.z + b4.z;
    ov[3] = (v.w - mu) * rstd * s4.w + b4.w;
    f16 h[4], l[4];
    #pragma unroll
    for (int j = 0; j < 4; j++) split2h(ov[j], h[j], l[j]);
    *(uint2*)(oh + (size_t)row * DD + tid * 4) = *(uint2*)h;
    *(uint2*)(ol + (size_t)row * DD + tid * 4) = *(uint2*)l;
}

// ---------------- scan ----------------
__global__ void scan_sum_kernel(const float* __restrict__ bu, int loff) {
    int h = blockIdx.x * blockDim.x + threadIdx.x;
    int c = blockIdx.y, b = blockIdx.z;
    float lre = g_lam_re[loff + h], lim = g_lam_im[loff + h];
    size_t base = ((size_t)(b * TT + c * CL)) * (2 * HH) + h;
    float are = 0.f, aim = 0.f;
    #pragma unroll 8
    for (int j = 0; j < CL; j++) {
        float ure = bu[base], uim = bu[base + HH];
        float nr = fmaf(are, lre, fmaf(-aim, lim, ure));
        float ni = fmaf(are, lim, fmaf(aim, lre, uim));
        are = nr; aim = ni;
        base += 2 * HH;
    }
    int o = (b * NCHUNK + c) * HH + h;
    g_sum_re[o] = are; g_sum_im[o] = aim;
}

__global__ void scan_carry_kernel(int loff) {
    int idx = blockIdx.x * blockDim.x + threadIdx.x;
    int b = idx >> 10, h = idx & (HH - 1);
    float lre = g_lam_re[loff + h], lim = g_lam_im[loff + h];
    float pre = lre, pim = lim;
    #pragma unroll
    for (int i = 0; i < 7; i++) {
        float nr = pre*pre - pim*pim;
        float ni = 2.f*pre*pim;
        pre = nr; pim = ni;
    }
    float cre = 0.f, cim = 0.f;
    #pragma unroll
    for (int c = 0; c < NCHUNK; c++) {
        int o = (b * NCHUNK + c) * HH + h;
        g_car_re[o] = cre; g_car_im[o] = cim;
        float sre = g_sum_re[o], sim = g_sum_im[o];
        float nr = cre*pre - cim*pim + sre;
        float ni = cre*pim + cim*pre + sim;
        cre = nr; cim = ni;
    }
}

__global__ void scan_apply_kernel(const float* __restrict__ bu,
                                  f16* __restrict__ hsh, f16* __restrict__ hsl,
                                  int loff) {
    int h = blockIdx.x * blockDim.x + threadIdx.x;
    int c = blockIdx.y, b = blockIdx.z;
    float lre = g_lam_re[loff + h], lim = g_lam_im[loff + h];
    int o = (b * NCHUNK + c) * HH + h;
    float are = g_car_re[o], aim = g_car_im[o];
    size_t base = ((size_t)(b * TT + c * CL)) * (2 * HH) + h;
    #pragma unroll 4
    for (int j = 0; j < CL; j++) {
        float ure = bu[base], uim = bu[base + HH];
        float nr = fmaf(are, lre, fmaf(-aim, lim, ure));
        float ni = fmaf(are, lim, fmaf(aim, lre, uim));
        are = nr; aim = ni;
        f16 hh, ll;
        split2h(are, hh, ll);
        hsh[base] = hh; hsl[base] = ll;
        split2h(aim, hh, ll);
        hsh[base + HH] = hh; hsl[base + HH] = ll;
        base += 2 * HH;
    }
}

// ---------------- launch ----------------
extern "C" void kernel_launch(void* const* d_in, const int* in_sizes, int n_in,
                              void* d_out, int out_size) {
    const float* inputs    = (const float*)d_in[0];
    const float* W_in      = (const float*)d_in[1];
    const float* b_in      = (const float*)d_in[2];
    const float* nu_log    = (const float*)d_in[3];
    const float* theta_log = (const float*)d_in[4];
    const float* B_re      = (const float*)d_in[5];
    const float* B_im      = (const float*)d_in[6];
    const float* C_re      = (const float*)d_in[7];
    const float* C_im      = (const float*)d_in[8];
    const float* D_diag    = (const float*)d_in[9];
    const float* ln_scale  = (const float*)d_in[10];
    const float* ln_bias   = (const float*)d_in[11];
    const float* w1        = (const float*)d_in[12];
    const float* b1        = (const float*)d_in[13];
    const float* w2        = (const float*)d_in[14];
    const float* b2        = (const float*)d_in[15];
    float* x = (float*)d_out;

    cudaFuncSetAttribute(gemm_mma, cudaFuncAttributeMaxDynamicSharedMemorySize, SMEMB);

    float *p_bu, *p_gam;
    f16 *p_xnh, *p_xnl, *p_inh, *p_inl, *p_hsh, *p_hsl, *p_yh;
    f16 *p_win, *p_bw, *p_cw, *p_gw;
    cudaGetSymbolAddress((void**)&p_bu,  g_bu);
    cudaGetSymbolAddress((void**)&p_gam, g_gam);
    cudaGetSymbolAddress((void**)&p_xnh, g_xn_h);
    cudaGetSymbolAddress((void**)&p_xnl, g_xn_l);
    cudaGetSymbolAddress((void**)&p_inh, g_in_h);
    cudaGetSymbolAddress((void**)&p_inl, g_in_l);
    cudaGetSymbolAddress((void**)&p_hsh, g_hs_h);
    cudaGetSymbolAddress((void**)&p_hsl, g_hs_l);
    cudaGetSymbolAddress((void**)&p_yh,  g_y_h);
    cudaGetSymbolAddress((void**)&p_win, g_win);
    cudaGetSymbolAddress((void**)&p_bw,  g_bw);
    cudaGetSymbolAddress((void**)&p_cw,  g_cw);
    cudaGetSymbolAddress((void**)&p_gw,  g_gw);

    // params, split inputs, convert all weights
    prep_kernel<<<(LNUM * HH) / 256, 256>>>(nu_log, theta_log);
    split_in_kernel<<<(MTOT*FF)/256, 256>>>(inputs);
    split_wts_kernel<<<(NW + NB + NC + NG)/256, 256>>>(
        W_in, B_re, B_im, C_re, C_im, w1, w2);

    // input projection: x = inputs @ W_in^T + b_in  (2-pass)
    gemm_mma<<<dim3(DD/128, MTOT/128), 256, SMEMB>>>(
        p_inh, p_inl, FF, p_win,
        x, nullptr, DD, FF, 0,
        b_in, nullptr, nullptr, nullptr, nullptr);

    for (int l = 0; l < LNUM; l++) {
        // layernorm -> fp16 split planes
        ln_kernel<<<MTOT, 256>>>(x, ln_scale + l*DD, ln_bias + l*DD, p_xnh, p_xnl);

        // Bu = gamma * (xn @ [B_re;B_im]^T)  (2-pass)
        gemm_mma<<<dim3(2*HH/128, MTOT/128), 256, SMEMB>>>(
            p_xnh, p_xnl, DD,
            p_bw + (size_t)l*2*HH*DD,
            p_bu, nullptr, 2*HH, DD, 1,
            nullptr, nullptr, nullptr, nullptr, p_gam + l*HH);

        scan_sum_kernel  <<<dim3(HH/256, NCHUNK, BB), 256>>>(p_bu, l*HH);
        scan_carry_kernel<<<(BB*HH)/256, 256>>>(l*HH);
        scan_apply_kernel<<<dim3(HH/256, NCHUNK, BB), 256>>>(p_bu, p_hsh, p_hsl, l*HH);

        // y = gelu( hs @ [C_re | -C_im]^T + xn * D_diag )  (2-pass, fp16 out)
        gemm_mma<<<dim3(DD/128, MTOT/128), 256, SMEMB>>>(
            p_hsh, p_hsl, 2*HH,
            p_cw + (size_t)l*DD*2*HH,
            nullptr, p_yh, DD, 2*HH, 2,
            nullptr, nullptr, p_xnh, p_xnl, D_diag + l*DD);

        // fused GLU + residual (1-pass): x += (y@w1^T + b1) * sigmoid(y@w2^T + b2)
        gemm_mma<<<dim3(2*DD/128, MTOT/128), 256, SMEMB>>>(
            p_yh, nullptr, DD,
            p_gw + (size_t)l*2*DD*DD,
            x, nullptr, DD, DD, 3,
            b1 + l*DD, b2 + l*DD, nullptr, nullptr, nullptr);
    }
    (void)in_sizes; (void)n_in; (void)out_size;
}

// round 11
// speedup vs baseline: 4.0934x; 1.0060x over previous
#include <cuda_runtime.h>
#include <cuda_fp16.h>
#include <math.h>
#include <stdint.h>

// ---------------- problem constants ----------------
#define LNUM 4
#define BB   4
#define TT   2048
#define DD   1024
#define HH   1024
#define FF   256
#define MTOT (BB*TT)          // 8192
#define NCHUNK 16
#define CL   (TT/NCHUNK)      // 128

// ---------------- mma GEMM config ----------------
#define BKC   32                      // k elements per stage
#define MATB  (128*64)                // 128 rows x 64B (swizzled, no pad)
#define STAGEB (3*MATB)               // Ah, Al, W = 24 KB
#define NSTG  3
#define SMEMB (NSTG*STAGEB)           // 73728 B -> 2 CTAs/SM
#define QS    72                      // fused-GLU smem staging stride (floats)
#define SS    132                     // Bu-scan smem staging stride (floats)

typedef __half f16;

// ---------------- scratch (device globals; no allocs allowed) ----------------
__device__ __align__(16) f16   g_xn_h[MTOT*DD];
__device__ __align__(16) f16   g_xn_l[MTOT*DD];
__device__ __align__(16) f16   g_in_h[MTOT*FF];
__device__ __align__(16) f16   g_in_l[MTOT*FF];
__device__ __align__(16) float g_bu[MTOT*2*HH];
__device__ __align__(16) f16   g_hs_h[MTOT*2*HH];
__device__ __align__(16) f16   g_hs_l[MTOT*2*HH];
__device__ __align__(16) f16   g_y_h[MTOT*DD];
__device__ __align__(16) f16   g_win[DD*FF];
__device__ __align__(16) f16   g_bw[LNUM*2*HH*DD];
__device__ __align__(16) f16   g_cw[LNUM*DD*2*HH];
__device__ __align__(16) f16   g_gw[LNUM*2*DD*DD];
__device__ float g_lam_re[LNUM*HH];
__device__ float g_lam_im[LNUM*HH];
__device__ float g_gam  [LNUM*HH];
__device__ float g_sum_re[BB*NCHUNK*HH];
__device__ float g_sum_im[BB*NCHUNK*HH];
__device__ float g_car_re[BB*NCHUNK*HH];
__device__ float g_car_im[BB*NCHUNK*HH];

// ---------------- helpers ----------------
__device__ __forceinline__ float gelu_exact(float v) {
    return 0.5f * v * (1.0f + erff(v * 0.70710678118654752f));
}
__device__ __forceinline__ void split2h(float v, f16& h, f16& l) {
    h = __float2half_rn(v);
    l = __float2half_rn(v - __half2float(h));
}
__device__ __forceinline__ void cp16(uint32_t d, const void* s) {
    asm volatile("cp.async.cg.shared.global [%0], [%1], 16;" :: "r"(d), "l"(s));
}
__device__ __forceinline__ void cpcommit() {
    asm volatile("cp.async.commit_group;" ::: "memory");
}
template<int N> __device__ __forceinline__ void cpwait() {
    asm volatile("cp.async.wait_group %0;" :: "n"(N) : "memory");
}
__device__ __forceinline__ void mma_f16(float* c, const uint32_t* a,
                                        uint32_t b0, uint32_t b1) {
    asm volatile("mma.sync.aligned.m16n8k16.row.col.f32.f16.f16.f32 "
        "{%0,%1,%2,%3}, {%4,%5,%6,%7}, {%8,%9}, {%0,%1,%2,%3};"
        : "+f"(c[0]), "+f"(c[1]), "+f"(c[2]), "+f"(c[3])
        : "r"(a[0]), "r"(a[1]), "r"(a[2]), "r"(a[3]), "r"(b0), "r"(b1));
}
__device__ __forceinline__ void ldm4(uint32_t* r, uint32_t a) {
    asm volatile("ldmatrix.sync.aligned.m8n8.x4.shared.b16 {%0,%1,%2,%3}, [%4];"
        : "=r"(r[0]), "=r"(r[1]), "=r"(r[2]), "=r"(r[3]) : "r"(a));
}

// swizzled chunk offset: row r (64B rows), 16B-chunk c
__device__ __forceinline__ uint32_t swz(int r, int c) {
    return (uint32_t)(r * 64 + ((c ^ ((r >> 1) & 3)) << 4));
}

// load one K-stage: Ah (+Al if two) rows m0.., W rows n0..
__device__ __forceinline__ void ldstage(uint32_t sb, int slot,
        const f16* Ah, const f16* Al, int lda,
        const f16* W, int ldw,
        int m0, int n0, int kb, int tid, bool two) {
    uint32_t st = sb + (uint32_t)slot * STAGEB;
    #pragma unroll
    for (int j = 0; j < 2; j++) {
        int chunk = tid + j * 256;
        int row   = chunk >> 2;
        int c     = chunk & 3;
        uint32_t d = st + swz(row, c);
        int ke = kb + c * 8;
        cp16(d,           Ah + (size_t)(m0+row)*lda + ke);
        if (two) cp16(d + MATB, Al + (size_t)(m0+row)*lda + ke);
        cp16(d + 2*MATB,  W  + (size_t)(n0+row)*ldw + ke);
    }
    cpcommit();
}

// ---------------- split-fp16 tensor-core GEMM ----------------
// C[m,n] = sum_k A[m,k]*W[n,k];  A = Ah(+Al if Al!=null), W = fp16 (rn)
// epi 0: Cf = acc + bias0(n)
// epi 2: Ch = half(gelu(acc + (epi_mh+epi_ml)[m,n]*epi_n[n]))
// epi 3: fused GLU: W interleaved [w1|w2] per 128-tile; x += (a+b1)*sigmoid(q+b2)
// epi 4: Bu + chunk-scan: W interleaved [re|im] per 128-tile; Cf = acc*gamma,
//        then 128-step chunk scan over rows -> g_sum_re/im
__global__ __launch_bounds__(256, 2)
void gemm_mma(const f16* __restrict__ Ah, const f16* __restrict__ Al, int lda,
              const f16* __restrict__ W,
              float* __restrict__ Cf, f16* __restrict__ Ch,
              int ldc, int K, int epi,
              const float* __restrict__ bias0, const float* __restrict__ bias1,
              const f16* __restrict__ epi_mh, const f16* __restrict__ epi_ml,
              const float* __restrict__ epi_n, int loff) {
    extern __shared__ __align__(16) char smc[];
    uint32_t sb = (uint32_t)__cvta_generic_to_shared(smc);
    const int tid  = threadIdx.x;
    const int wid  = tid >> 5, lane = tid & 31;
    const int g    = lane >> 2, t2 = lane & 3;
    const int warpM = wid & 3;
    const int warpN = wid >> 2;
    const int m0 = blockIdx.y * 128;
    const int n0 = blockIdx.x * 128;
    const int NCH = K / BKC;
    const bool twopass = (Al != nullptr);

    // ldmatrix per-lane rows / chunk bases
    const int grp = lane >> 3, rr = lane & 7;
    const int cA0 = grp >> 1;           // A chunk base (0/1)
    const int cB0 = grp & 1;            // B chunk base (0/1)
    int  rA[2], rB[4];
    #pragma unroll
    for (int mt = 0; mt < 2; mt++) rA[mt] = warpM*32 + mt*16 + rr + (grp & 1)*8;
    #pragma unroll
    for (int ntp = 0; ntp < 4; ntp++) rB[ntp] = warpN*64 + ntp*16 + rr + (grp >> 1)*8;

    float acc[2][8][4];
    #pragma unroll
    for (int i = 0; i < 2; i++)
        #pragma unroll
        for (int j = 0; j < 8; j++)
            #pragma unroll
            for (int q = 0; q < 4; q++) acc[i][j][q] = 0.f;

    // prologue: stages 0,1 in flight; wait stage 0, publish
    ldstage(sb, 0, Ah, Al, lda, W, K, m0, n0, 0,   tid, twopass);
    ldstage(sb, 1, Ah, Al, lda, W, K, m0, n0, BKC, tid, twopass);
    cpwait<1>();
    __syncthreads();

    int slot = 0;
    for (int t = 0; t < NCH; t++) {
        // issue loads for stage t+2 first (overlap with compute below)
        if (t + 2 < NCH)
            ldstage(sb, (t + 2) % NSTG, Ah, Al, lda, W, K, m0, n0, (t+2)*BKC, tid, twopass);
        else
            cpcommit();

        uint32_t st   = sb + (uint32_t)slot * STAGEB;
        uint32_t Ah_s = st, Al_s = st + MATB, W_s = st + 2*MATB;

        #pragma unroll
        for (int kh = 0; kh < 2; kh++) {
            uint32_t ah[2][4], al[2][4];
            #pragma unroll
            for (int mt = 0; mt < 2; mt++) {
                uint32_t ao = swz(rA[mt], cA0 + 2*kh);
                ldm4(ah[mt], Ah_s + ao);
                if (twopass) ldm4(al[mt], Al_s + ao);
            }
            #pragma unroll
            for (int ntp = 0; ntp < 4; ntp++) {
                uint32_t bo = swz(rB[ntp], cB0 + 2*kh);
                uint32_t bh[4];
                ldm4(bh, W_s + bo);
                int nt0 = ntp*2, nt1 = ntp*2 + 1;
                // pass hi
                mma_f16(acc[0][nt0], ah[0], bh[0], bh[1]);
                mma_f16(acc[1][nt0], ah[1], bh[0], bh[1]);
                mma_f16(acc[0][nt1], ah[0], bh[2], bh[3]);
                mma_f16(acc[1][nt1], ah[1], bh[2], bh[3]);
                // pass lo
                if (twopass) {
                    mma_f16(acc[0][nt0], al[0], bh[0], bh[1]);
                    mma_f16(acc[1][nt0], al[1], bh[0], bh[1]);
                    mma_f16(acc[0][nt1], al[0], bh[2], bh[3]);
                    mma_f16(acc[1][nt1], al[1], bh[2], bh[3]);
                }
            }
        }

        cpwait<1>();
        __syncthreads();
        slot = (slot + 1 == NSTG) ? 0 : slot + 1;
    }

    // ---- epilogue ----
    if (epi == 4) {
        // Bu (gamma-scaled, interleaved re/im columns) + in-tile chunk scan.
        // tile cols: 0-63 = re(h=j*64..), 64-127 = im of same h
        const int j = n0 >> 7;
        float* sm = (float*)smc;
        #pragma unroll
        for (int mt = 0; mt < 2; mt++)
            #pragma unroll
            for (int nt = 0; nt < 8; nt++) {
                int r0 = warpM*32 + mt*16 + g, r1 = r0 + 8;
                int nn = warpN*64 + nt*8 + t2*2;
                int hI = j*64 + (nn & 63);
                float e0 = epi_n[hI], e1 = epi_n[hI + 1];
                float c0 = acc[mt][nt][0]*e0, c1 = acc[mt][nt][1]*e1;
                float c2 = acc[mt][nt][2]*e0, c3 = acc[mt][nt][3]*e1;
                *(float2*)(Cf + (size_t)(m0 + r0) * ldc + n0 + nn) = make_float2(c0, c1);
                *(float2*)(Cf + (size_t)(m0 + r1) * ldc + n0 + nn) = make_float2(c2, c3);
                sm[r0*SS + nn] = c0;  sm[r0*SS + nn + 1] = c1;
                sm[r1*SS + nn] = c2;  sm[r1*SS + nn + 1] = c3;
            }
        __syncthreads();
        if (tid < 64) {
            int h = j*64 + tid;
            float lre = g_lam_re[loff + h], lim = g_lam_im[loff + h];
            float are = 0.f, aim = 0.f;
            #pragma unroll 4
            for (int r = 0; r < 128; r++) {
                float ure = sm[r*SS + (tid & 63)];
                float uim = sm[r*SS + 64 + (tid & 63)];
                float nr = fmaf(are, lre, fmaf(-aim, lim, ure));
                float ni = fmaf(are, lim, fmaf(aim, lre, uim));
                are = nr; aim = ni;
            }
            int b = m0 >> 11;
            int chunk = (m0 & (TT - 1)) >> 7;
            int o = (b * NCHUNK + chunk) * HH + h;
            g_sum_re[o] = are; g_sum_im[o] = aim;
        }
        return;
    }
    if (epi == 3) {
        // fused GLU: tile cols 0-63 = w1 (a), 64-127 = w2 (q); output cols co..co+63
        const int co = blockIdx.x * 64;
        float* qs = (float*)smc;
        if (warpN == 1) {
            #pragma unroll
            for (int mt = 0; mt < 2; mt++)
                #pragma unroll
                for (int nt = 0; nt < 8; nt++) {
                    int r0 = warpM*32 + mt*16 + g, r1 = r0 + 8;
                    int c  = nt*8 + t2*2;
                    float bb0 = bias1[co + c], bb1 = bias1[co + c + 1];
                    qs[r0*QS + c]     = acc[mt][nt][0] + bb0;
                    qs[r0*QS + c + 1] = acc[mt][nt][1] + bb1;
                    qs[r1*QS + c]     = acc[mt][nt][2] + bb0;
                    qs[r1*QS + c + 1] = acc[mt][nt][3] + bb1;
                }
        }
        __syncthreads();
        if (warpN == 0) {
            #pragma unroll
            for (int mt = 0; mt < 2; mt++)
                #pragma unroll
                for (int nt = 0; nt < 8; nt++) {
                    int r0 = warpM*32 + mt*16 + g, r1 = r0 + 8;
                    int c  = nt*8 + t2*2;
                    float bb0 = bias0[co + c], bb1 = bias0[co + c + 1];
                    float a00 = acc[mt][nt][0] + bb0, a01 = acc[mt][nt][1] + bb1;
                    float a10 = acc[mt][nt][2] + bb0, a11 = acc[mt][nt][3] + bb1;
                    float q00 = qs[r0*QS + c], q01 = qs[r0*QS + c + 1];
                    float q10 = qs[r1*QS + c], q11 = qs[r1*QS + c + 1];
                    float* x0 = Cf + (size_t)(m0 + r0) * DD + co + c;
                    float* x1 = Cf + (size_t)(m0 + r1) * DD + co + c;
                    float2 v0 = *(float2*)x0, v1 = *(float2*)x1;
                    v0.x = fmaf(a00, 1.f/(1.f + expf(-q00)), v0.x);
                    v0.y = fmaf(a01, 1.f/(1.f + expf(-q01)), v0.y);
                    v1.x = fmaf(a10, 1.f/(1.f + expf(-q10)), v1.x);
                    v1.y = fmaf(a11, 1.f/(1.f + expf(-q11)), v1.y);
                    *(float2*)x0 = v0;
                    *(float2*)x1 = v1;
                }
        }
        return;
    }
    #pragma unroll
    for (int mt = 0; mt < 2; mt++) {
        #pragma unroll
        for (int nt = 0; nt < 8; nt++) {
            int row0 = m0 + warpM*32 + mt*16 + g;
            int row1 = row0 + 8;
            int col  = n0 + warpN*64 + nt*8 + t2*2;
            float c0 = acc[mt][nt][0], c1 = acc[mt][nt][1];
            float c2 = acc[mt][nt][2], c3 = acc[mt][nt][3];
            if (epi == 0) {
                float b0v = bias0[col], b1v = bias0[col + 1];
                *(float2*)(Cf + (size_t)row0 * ldc + col) = make_float2(c0 + b0v, c1 + b1v);
                *(float2*)(Cf + (size_t)row1 * ldc + col) = make_float2(c2 + b0v, c3 + b1v);
            } else {
                float d0 = epi_n[col], d1 = epi_n[col+1];
                // reconstruct xn = xn_h + xn_l (fp16 pair, exact to ~2^-22)
                __half2 xh0 = *(const __half2*)(epi_mh + (size_t)row0 * DD + col);
                __half2 xl0 = *(const __half2*)(epi_ml + (size_t)row0 * DD + col);
                __half2 xh1 = *(const __half2*)(epi_mh + (size_t)row1 * DD + col);
                __half2 xl1 = *(const __half2*)(epi_ml + (size_t)row1 * DD + col);
                float m00 = __half2float(xh0.x) + __half2float(xl0.x);
                float m01 = __half2float(xh0.y) + __half2float(xl0.y);
                float m10 = __half2float(xh1.x) + __half2float(xl1.x);
                float m11 = __half2float(xh1.y) + __half2float(xl1.y);
                float v0 = gelu_exact(c0 + m00 * d0);
                float v1 = gelu_exact(c1 + m01 * d1);
                float v2 = gelu_exact(c2 + m10 * d0);
                float v3 = gelu_exact(c3 + m11 * d1);
                __half2 ph0(__float2half_rn(v0), __float2half_rn(v1));
                __half2 ph1(__float2half_rn(v2), __float2half_rn(v3));
                *(uint32_t*)(Ch + (size_t)row0 * ldc + col) = *(uint32_t*)&ph0;
                *(uint32_t*)(Ch + (size_t)row1 * ldc + col) = *(uint32_t*)&ph1;
            }
        }
    }
}

// ---------------- parameter prep ----------------
__global__ void prep_kernel(const float* __restrict__ nu_log,
                            const float* __restrict__ theta_log) {
    int i = blockIdx.x * blockDim.x + threadIdx.x;
    float nu = expf(nu_log[i]);
    float th = expf(theta_log[i]);
    float r  = expf(-nu);
    g_lam_re[i] = r * cosf(th);
    g_lam_im[i] = r * sinf(th);
    g_gam[i]    = sqrtf(1.0f - expf(-2.0f * nu) + 1e-5f);
}

// ---------------- input splitter ----------------
__global__ void split_in_kernel(const float* __restrict__ s) {
    int i = blockIdx.x * 256 + threadIdx.x;
    f16 h, l;
    split2h(s[i], h, l);
    g_in_h[i] = h; g_in_l[i] = l;
}

// ---------------- all-weights converter (single fp16 plane) ----------------
#define NW  (DD*FF)
#define NB  (LNUM*2*HH*DD)
#define NC  (LNUM*DD*2*HH)
#define NG  (LNUM*2*DD*DD)
__global__ void split_wts_kernel(const float* __restrict__ W_in,
                                 const float* __restrict__ B_re,
                                 const float* __restrict__ B_im,
                                 const float* __restrict__ C_re,
                                 const float* __restrict__ C_im,
                                 const float* __restrict__ w1,
                                 const float* __restrict__ w2) {
    int idx = blockIdx.x * 256 + threadIdx.x;
    float v;
    if (idx < NW) {
        g_win[idx] = __float2half_rn(W_in[idx]);
        return;
    }
    idx -= NW;
    if (idx < NB) {
        // interleaved [re|im] per 128-row tile: n' = j*128+o, o<64 -> re h=j*64+o
        int l_ = idx / (2*HH*DD);
        int t  = idx - l_ * (2*HH*DD);
        int np = t >> 10, c = t & 1023;
        int j = np >> 7, o = np & 127;
        if (o < 64) v = B_re[(size_t)l_*HH*DD + (j*64 + o)*DD + c];
        else        v = B_im[(size_t)l_*HH*DD + (j*64 + o - 64)*DD + c];
        g_bw[idx] = __float2half_rn(v);
        return;
    }
    idx -= NB;
    if (idx < NC) {
        // k interleaved to match hs layout: k = j*128+o, o<64 -> re h=j*64+o
        int l_ = idx / (DD*2*HH);
        int t  = idx - l_ * (DD*2*HH);
        int r  = t >> 11, k = t & 2047;
        int j = k >> 7, o = k & 127;
        if (o < 64) v = C_re[(size_t)l_*DD*HH + r*HH + (j*64 + o)];
        else        v = -C_im[(size_t)l_*DD*HH + r*HH + (j*64 + o - 64)];
        g_cw[idx] = __float2half_rn(v);
        return;
    }
    idx -= NC;
    {
        int l_ = idx / (2*DD*DD);
        int t  = idx - l_ * (2*DD*DD);
        int np = t >> 10, c = t & 1023;
        int blk = np >> 7, off = np & 127;
        if (off < 64) v = w1[(size_t)l_*DD*DD + (blk*64 + off)*DD + c];
        else          v = w2[(size_t)l_*DD*DD + (blk*64 + off - 64)*DD + c];
        g_gw[idx] = __float2half_rn(v);
    }
}

// ---------------- layernorm (fp16 split outputs only) ----------------
__global__ void ln_kernel(const float* __restrict__ x,
                          const float* __restrict__ sc,
                          const float* __restrict__ bi,
                          f16* __restrict__ oh, f16* __restrict__ ol) {
    __shared__ float red[16];
    int row = blockIdx.x;
    int tid = threadIdx.x;
    const float* xr = x + (size_t)row * DD;
    float4 v = *(const float4*)(xr + tid * 4);
    float s  = v.x + v.y + v.z + v.w;
    float ss = v.x*v.x + v.y*v.y + v.z*v.z + v.w*v.w;
    #pragma unroll
    for (int off = 16; off; off >>= 1) {
        s  += __shfl_xor_sync(0xffffffffu, s,  off);
        ss += __shfl_xor_sync(0xffffffffu, ss, off);
    }
    int wid = tid >> 5;
    if ((tid & 31) == 0) { red[wid] = s; red[8 + wid] = ss; }
    __syncthreads();
    float S = 0.f, SS_ = 0.f;
    #pragma unroll
    for (int w = 0; w < 8; w++) { S += red[w]; SS_ += red[8 + w]; }
    float mu  = S * (1.0f / DD);
    float var = SS_ * (1.0f / DD) - mu * mu;
    float rstd = rsqrtf(var + 1e-5f);
    float4 s4 = *(const float4*)(sc + tid * 4);
    float4 b4 = *(const float4*)(bi + tid * 4);
    float ov[4];
    ov[0] = (v.x - mu) * rstd * s4.x + b4.x;
    ov[1] = (v.y - mu) * rstd * s4.y + b4.y;
    ov[2] = (v.z - mu) * rstd * s4.z + b4.z;
    ov[3] = (v.w - mu) * rstd * s4.w + b4.w;
    f16 h[4], l[4];
    #pragma unroll
    for (int j = 0; j < 4; j++) split2h(ov[j], h[j], l[j]);
    *(uint2*)(oh + (size_t)row * DD + tid * 4) = *(uint2*)h;
    *(uint2*)(ol + (size_t)row * DD + tid * 4) = *(uint2*)l;
}

// ---------------- scan carry (over chunk summaries) ----------------
__global__ void scan_carry_kernel(int loff) {
    int idx = blockIdx.x * blockDim.x + threadIdx.x;
    int b = idx >> 10, h = idx & (HH - 1);
    float lre = g_lam_re[loff + h], lim = g_lam_im[loff + h];
    float pre = lre, pim = lim;
    #pragma unroll
    for (int i = 0; i < 7; i++) {
        float nr = pre*pre - pim*pim;
        float ni = 2.f*pre*pim;
        pre = nr; pim = ni;
    }
    float cre = 0.f, cim = 0.f;
    #pragma unroll
    for (int c = 0; c < NCHUNK; c++) {
        int o = (b * NCHUNK + c) * HH + h;
        g_car_re[o] = cre; g_car_im[o] = cim;
        float sre = g_sum_re[o], sim = g_sum_im[o];
        float nr = cre*pre - cim*pim + sre;
        float ni = cre*pim + cim*pre + sim;
        cre = nr; cim = ni;
    }
}

// ---------------- scan apply (interleaved bu layout) ----------------
__global__ void scan_apply_kernel(const float* __restrict__ bu,
                                  f16* __restrict__ hsh, f16* __restrict__ hsl,
                                  int loff) {
    int h = blockIdx.x * blockDim.x + threadIdx.x;
    int c = blockIdx.y, b = blockIdx.z;
    float lre = g_lam_re[loff + h], lim = g_lam_im[loff + h];
    int o = (b * NCHUNK + c) * HH + h;
    float are = g_car_re[o], aim = g_car_im[o];
    int col = ((h >> 6) << 7) + (h & 63);   // interleaved re col; im at +64
    size_t base = ((size_t)(b * TT + c * CL)) * (2 * HH) + col;
    #pragma unroll 4
    for (int j = 0; j < CL; j++) {
        float ure = bu[base], uim = bu[base + 64];
        float nr = fmaf(are, lre, fmaf(-aim, lim, ure));
        float ni = fmaf(are, lim, fmaf(aim, lre, uim));
        are = nr; aim = ni;
        f16 hh, ll;
        split2h(are, hh, ll);
        hsh[base] = hh; hsl[base] = ll;
        split2h(aim, hh, ll);
        hsh[base + 64] = hh; hsl[base + 64] = ll;
        base += 2 * HH;
    }
}

// ---------------- launch ----------------
extern "C" void kernel_launch(void* const* d_in, const int* in_sizes, int n_in,
                              void* d_out, int out_size) {
    const float* inputs    = (const float*)d_in[0];
    const float* W_in      = (const float*)d_in[1];
    const float* b_in      = (const float*)d_in[2];
    const float* nu_log    = (const float*)d_in[3];
    const float* theta_log = (const float*)d_in[4];
    const float* B_re      = (const float*)d_in[5];
    const float* B_im      = (const float*)d_in[6];
    const float* C_re      = (const float*)d_in[7];
    const float* C_im      = (const float*)d_in[8];
    const float* D_diag    = (const float*)d_in[9];
    const float* ln_scale  = (const float*)d_in[10];
    const float* ln_bias   = (const float*)d_in[11];
    const float* w1        = (const float*)d_in[12];
    const float* b1        = (const float*)d_in[13];
    const float* w2        = (const float*)d_in[14];
    const float* b2        = (const float*)d_in[15];
    float* x = (float*)d_out;

    cudaFuncSetAttribute(gemm_mma, cudaFuncAttributeMaxDynamicSharedMemorySize, SMEMB);

    float *p_bu, *p_gam;
    f16 *p_xnh, *p_xnl, *p_inh, *p_inl, *p_hsh, *p_hsl, *p_yh;
    f16 *p_win, *p_bw, *p_cw, *p_gw;
    cudaGetSymbolAddress((void**)&p_bu,  g_bu);
    cudaGetSymbolAddress((void**)&p_gam, g_gam);
    cudaGetSymbolAddress((void**)&p_xnh, g_xn_h);
    cudaGetSymbolAddress((void**)&p_xnl, g_xn_l);
    cudaGetSymbolAddress((void**)&p_inh, g_in_h);
    cudaGetSymbolAddress((void**)&p_inl, g_in_l);
    cudaGetSymbolAddress((void**)&p_hsh, g_hs_h);
    cudaGetSymbolAddress((void**)&p_hsl, g_hs_l);
    cudaGetSymbolAddress((void**)&p_yh,  g_y_h);
    cudaGetSymbolAddress((void**)&p_win, g_win);
    cudaGetSymbolAddress((void**)&p_bw,  g_bw);
    cudaGetSymbolAddress((void**)&p_cw,  g_cw);
    cudaGetSymbolAddress((void**)&p_gw,  g_gw);

    // params, split inputs, convert all weights
    prep_kernel<<<(LNUM * HH) / 256, 256>>>(nu_log, theta_log);
    split_in_kernel<<<(MTOT*FF)/256, 256>>>(inputs);
    split_wts_kernel<<<(NW + NB + NC + NG)/256, 256>>>(
        W_in, B_re, B_im, C_re, C_im, w1, w2);

    // input projection: x = inputs @ W_in^T + b_in  (2-pass)
    gemm_mma<<<dim3(DD/128, MTOT/128), 256, SMEMB>>>(
        p_inh, p_inl, FF, p_win,
        x, nullptr, DD, FF, 0,
        b_in, nullptr, nullptr, nullptr, nullptr, 0);

    for (int l = 0; l < LNUM; l++) {
        // layernorm -> fp16 split planes
        ln_kernel<<<MTOT, 256>>>(x, ln_scale + l*DD, ln_bias + l*DD, p_xnh, p_xnl);

        // Bu = gamma * (xn @ Bw^T) with fused chunk-scan summaries (2-pass)
        gemm_mma<<<dim3(2*HH/128, MTOT/128), 256, SMEMB>>>(
            p_xnh, p_xnl, DD,
            p_bw + (size_t)l*2*HH*DD,
            p_bu, nullptr, 2*HH, DD, 4,
            nullptr, nullptr, nullptr, nullptr, p_gam + l*HH, l*HH);

        scan_carry_kernel<<<(BB*HH)/256, 256>>>(l*HH);
        scan_apply_kernel<<<dim3(HH/256, NCHUNK, BB), 256>>>(p_bu, p_hsh, p_hsl, l*HH);

        // y = gelu( hs @ Cw^T + xn * D_diag )  (2-pass, fp16 out)
        gemm_mma<<<dim3(DD/128, MTOT/128), 256, SMEMB>>>(
            p_hsh, p_hsl, 2*HH,
            p_cw + (size_t)l*DD*2*HH,
            nullptr, p_yh, DD, 2*HH, 2,
            nullptr, nullptr, p_xnh, p_xnl, D_diag + l*DD, 0);

        // fused GLU + residual (1-pass): x += (y@w1^T + b1) * sigmoid(y@w2^T + b2)
        gemm_mma<<<dim3(2*DD/128, MTOT/128), 256, SMEMB>>>(
            p_yh, nullptr, DD,
            p_gw + (size_t)l*2*DD*DD,
            x, nullptr, DD, DD, 3,
            b1 + l*DD, b2 + l*DD, nullptr, nullptr, nullptr, 0);
    }
    (void)in_sizes; (void)n_in; (void)out_size;
}

// round 13
// speedup vs baseline: 4.3448x; 1.0614x over previous
#include <cuda_runtime.h>
#include <cuda_fp16.h>
#include <math.h>
#include <stdint.h>

// ---------------- problem constants ----------------
#define LNUM 4
#define BB   4
#define TT   2048
#define DD   1024
#define HH   1024
#define FF   256
#define MTOT (BB*TT)          // 8192
#define NCHUNK 16
#define CL   (TT/NCHUNK)      // 128

// ---------------- mma GEMM config ----------------
#define BKC   64                      // k elements per stage
#define MATB  (128*128)               // 128 rows x 128B (swizzled)
#define STAGEB (3*MATB)               // Ah, Al, W = 48 KB
#define NSTG  2
#define SMEMB (NSTG*STAGEB)           // 98304 B -> 2 CTAs/SM
#define QS    72                      // fused-GLU smem staging stride (floats)
#define SS    132                     // Bu-scan smem staging stride (floats)

typedef __half f16;

// ---------------- scratch (device globals; no allocs allowed) ----------------
__device__ __align__(16) f16   g_xn_h[MTOT*DD];
__device__ __align__(16) f16   g_xn_l[MTOT*DD];
__device__ __align__(16) f16   g_in_h[MTOT*FF];
__device__ __align__(16) f16   g_in_l[MTOT*FF];
__device__ __align__(16) float g_bu[MTOT*2*HH];
__device__ __align__(16) f16   g_hs_h[MTOT*2*HH];
__device__ __align__(16) f16   g_hs_l[MTOT*2*HH];
__device__ __align__(16) f16   g_y_h[MTOT*DD];
__device__ __align__(16) f16   g_win[DD*FF];
__device__ __align__(16) f16   g_bw[LNUM*2*HH*DD];
__device__ __align__(16) f16   g_cw[LNUM*DD*2*HH];
__device__ __align__(16) f16   g_gw[LNUM*2*DD*DD];
__device__ float g_lam_re[LNUM*HH];
__device__ float g_lam_im[LNUM*HH];
__device__ float g_gam  [LNUM*HH];
__device__ float g_sum_re[BB*NCHUNK*HH];
__device__ float g_sum_im[BB*NCHUNK*HH];
__device__ float g_car_re[BB*NCHUNK*HH];
__device__ float g_car_im[BB*NCHUNK*HH];

// ---------------- helpers ----------------
__device__ __forceinline__ float gelu_exact(float v) {
    return 0.5f * v * (1.0f + erff(v * 0.70710678118654752f));
}
__device__ __forceinline__ void split2h(float v, f16& h, f16& l) {
    h = __float2half_rn(v);
    l = __float2half_rn(v - __half2float(h));
}
__device__ __forceinline__ void cp16(uint32_t d, const void* s) {
    asm volatile("cp.async.cg.shared.global [%0], [%1], 16;" :: "r"(d), "l"(s));
}
__device__ __forceinline__ void cpcommit() {
    asm volatile("cp.async.commit_group;" ::: "memory");
}
template<int N> __device__ __forceinline__ void cpwait() {
    asm volatile("cp.async.wait_group %0;" :: "n"(N) : "memory");
}
__device__ __forceinline__ void mma_f16(float* c, const uint32_t* a,
                                        uint32_t b0, uint32_t b1) {
    asm volatile("mma.sync.aligned.m16n8k16.row.col.f32.f16.f16.f32 "
        "{%0,%1,%2,%3}, {%4,%5,%6,%7}, {%8,%9}, {%0,%1,%2,%3};"
        : "+f"(c[0]), "+f"(c[1]), "+f"(c[2]), "+f"(c[3])
        : "r"(a[0]), "r"(a[1]), "r"(a[2]), "r"(a[3]), "r"(b0), "r"(b1));
}
__device__ __forceinline__ void ldm4(uint32_t* r, uint32_t a) {
    asm volatile("ldmatrix.sync.aligned.m8n8.x4.shared.b16 {%0,%1,%2,%3}, [%4];"
        : "=r"(r[0]), "=r"(r[1]), "=r"(r[2]), "=r"(r[3]) : "r"(a));
}

// swizzled chunk offset: row r (128B rows), 16B-chunk c (0..7)
__device__ __forceinline__ uint32_t swz(int r, int c) {
    return (uint32_t)(r * 128 + ((c ^ (r & 7)) << 4));
}

// load one K-stage: Ah (+Al if two) rows m0.., W rows n0..  (128 rows x 128B each)
__device__ __forceinline__ void ldstage(uint32_t sb, int slot,
        const f16* Ah, const f16* Al, int lda,
        const f16* W, int ldw,
        int m0, int n0, int kb, int tid, bool two) {
    uint32_t st = sb + (uint32_t)slot * STAGEB;
    #pragma unroll
    for (int j = 0; j < 4; j++) {
        int chunk = tid + j * 256;
        int row   = chunk >> 3;
        int c     = chunk & 7;
        uint32_t d = st + swz(row, c);
        int ke = kb + c * 8;
        cp16(d,           Ah + (size_t)(m0+row)*lda + ke);
        if (two) cp16(d + MATB, Al + (size_t)(m0+row)*lda + ke);
        cp16(d + 2*MATB,  W  + (size_t)(n0+row)*ldw + ke);
    }
    cpcommit();
}

// ---------------- split-fp16 tensor-core GEMM ----------------
// C[m,n] = sum_k A[m,k]*W[n,k];  A = Ah(+Al if Al!=null), W = fp16 (rn)
// epi 0: Cf = acc + bias0(n)
// epi 2: Ch = half(gelu(acc + (epi_mh+epi_ml)[m,n]*epi_n[n]))
// epi 3: fused GLU: W interleaved [w1|w2] per 128-tile; x += (a+b1)*sigmoid(q+b2)
// epi 4: Bu + chunk-scan: W interleaved [re|im] per 128-tile; Cf = acc*gamma,
//        then 128-step chunk scan over rows -> g_sum_re/im
__global__ __launch_bounds__(256, 2)
void gemm_mma(const f16* __restrict__ Ah, const f16* __restrict__ Al, int lda,
              const f16* __restrict__ W,
              float* __restrict__ Cf, f16* __restrict__ Ch,
              int ldc, int K, int epi,
              const float* __restrict__ bias0, const float* __restrict__ bias1,
              const f16* __restrict__ epi_mh, const f16* __restrict__ epi_ml,
              const float* __restrict__ epi_n, int loff) {
    extern __shared__ __align__(16) char smc[];
    uint32_t sb = (uint32_t)__cvta_generic_to_shared(smc);
    const int tid  = threadIdx.x;
    const int wid  = tid >> 5, lane = tid & 31;
    const int g    = lane >> 2, t2 = lane & 3;
    const int warpM = wid & 3;
    const int warpN = wid >> 2;
    const int m0 = blockIdx.y * 128;
    const int n0 = blockIdx.x * 128;
    const int NCH = K / BKC;
    const bool twopass = (Al != nullptr);

    // ldmatrix per-lane rows / chunk bases
    const int grp = lane >> 3, rr = lane & 7;
    const int cA0 = grp >> 1;           // A chunk base within 2-chunk group (0/1)
    const int cB0 = grp & 1;            // B chunk base (0/1)
    int  rA[2], rB[4];
    #pragma unroll
    for (int mt = 0; mt < 2; mt++) rA[mt] = warpM*32 + mt*16 + rr + (grp & 1)*8;
    #pragma unroll
    for (int ntp = 0; ntp < 4; ntp++) rB[ntp] = warpN*64 + ntp*16 + rr + (grp >> 1)*8;

    float acc[2][8][4];
    #pragma unroll
    for (int i = 0; i < 2; i++)
        #pragma unroll
        for (int j = 0; j < 8; j++)
            #pragma unroll
            for (int q = 0; q < 4; q++) acc[i][j][q] = 0.f;

    // prologue: stages 0,1 in flight; wait stage 0, publish
    ldstage(sb, 0, Ah, Al, lda, W, K, m0, n0, 0,   tid, twopass);
    ldstage(sb, 1, Ah, Al, lda, W, K, m0, n0, BKC, tid, twopass);
    cpwait<1>();
    __syncthreads();

    for (int t = 0; t < NCH; t++) {
        const int slot = t & 1;
        uint32_t st   = sb + (uint32_t)slot * STAGEB;
        uint32_t Ah_s = st, Al_s = st + MATB, W_s = st + 2*MATB;

        #pragma unroll
        for (int kh = 0; kh < 4; kh++) {
            uint32_t ah[2][4], al[2][4];
            #pragma unroll
            for (int mt = 0; mt < 2; mt++) {
                uint32_t ao = swz(rA[mt], cA0 + 2*kh);
                ldm4(ah[mt], Ah_s + ao);
                if (twopass) ldm4(al[mt], Al_s + ao);
            }
            #pragma unroll
            for (int ntp = 0; ntp < 4; ntp++) {
                uint32_t bo = swz(rB[ntp], cB0 + 2*kh);
                uint32_t bh[4];
                ldm4(bh, W_s + bo);
                int nt0 = ntp*2, nt1 = ntp*2 + 1;
                // pass hi
                mma_f16(acc[0][nt0], ah[0], bh[0], bh[1]);
                mma_f16(acc[1][nt0], ah[1], bh[0], bh[1]);
                mma_f16(acc[0][nt1], ah[0], bh[2], bh[3]);
                mma_f16(acc[1][nt1], ah[1], bh[2], bh[3]);
                // pass lo
                if (twopass) {
                    mma_f16(acc[0][nt0], al[0], bh[0], bh[1]);
                    mma_f16(acc[1][nt0], al[1], bh[0], bh[1]);
                    mma_f16(acc[0][nt1], al[0], bh[2], bh[3]);
                    mma_f16(acc[1][nt1], al[1], bh[2], bh[3]);
                }
            }
        }

        // WAR guard: all warps must finish reading this slot before refill
        __syncthreads();
        // refill the slot we just consumed with stage t+2 (lands during stage t+1)
        if (t + 2 < NCH)
            ldstage(sb, slot, Ah, Al, lda, W, K, m0, n0, (t+2)*BKC, tid, twopass);
        else
            cpcommit();
        cpwait<1>();       // stage t+1 resident
        __syncthreads();   // publish stage t+1 CTA-wide
    }

    // ---- epilogue ----
    if (epi == 4) {
        // Bu (gamma-scaled, interleaved re/im columns) + in-tile chunk scan.
        const int j = n0 >> 7;
        float* sm = (float*)smc;
        #pragma unroll
        for (int mt = 0; mt < 2; mt++)
            #pragma unroll
            for (int nt = 0; nt < 8; nt++) {
                int r0 = warpM*32 + mt*16 + g, r1 = r0 + 8;
                int nn = warpN*64 + nt*8 + t2*2;
                int hI = j*64 + (nn & 63);
                float e0 = epi_n[hI], e1 = epi_n[hI + 1];
                float c0 = acc[mt][nt][0]*e0, c1 = acc[mt][nt][1]*e1;
                float c2 = acc[mt][nt][2]*e0, c3 = acc[mt][nt][3]*e1;
                *(float2*)(Cf + (size_t)(m0 + r0) * ldc + n0 + nn) = make_float2(c0, c1);
                *(float2*)(Cf + (size_t)(m0 + r1) * ldc + n0 + nn) = make_float2(c2, c3);
                sm[r0*SS + nn] = c0;  sm[r0*SS + nn + 1] = c1;
                sm[r1*SS + nn] = c2;  sm[r1*SS + nn + 1] = c3;
            }
        __syncthreads();
        if (tid < 64) {
            int h = j*64 + tid;
            float lre = g_lam_re[loff + h], lim = g_lam_im[loff + h];
            float are = 0.f, aim = 0.f;
            #pragma unroll 4
            for (int r = 0; r < 128; r++) {
                float ure = sm[r*SS + (tid & 63)];
                float uim = sm[r*SS + 64 + (tid & 63)];
                float nr = fmaf(are, lre, fmaf(-aim, lim, ure));
                float ni = fmaf(are, lim, fmaf(aim, lre, uim));
                are = nr; aim = ni;
            }
            int b = m0 >> 11;
            int chunk = (m0 & (TT - 1)) >> 7;
            int o = (b * NCHUNK + chunk) * HH + h;
            g_sum_re[o] = are; g_sum_im[o] = aim;
        }
        return;
    }
    if (epi == 3) {
        // fused GLU: tile cols 0-63 = w1 (a), 64-127 = w2 (q); output cols co..co+63
        const int co = blockIdx.x * 64;
        float* qs = (float*)smc;
        if (warpN == 1) {
            #pragma unroll
            for (int mt = 0; mt < 2; mt++)
                #pragma unroll
                for (int nt = 0; nt < 8; nt++) {
                    int r0 = warpM*32 + mt*16 + g, r1 = r0 + 8;
                    int c  = nt*8 + t2*2;
                    float bb0 = bias1[co + c], bb1 = bias1[co + c + 1];
                    qs[r0*QS + c]     = acc[mt][nt][0] + bb0;
                    qs[r0*QS + c + 1] = acc[mt][nt][1] + bb1;
                    qs[r1*QS + c]     = acc[mt][nt][2] + bb0;
                    qs[r1*QS + c + 1] = acc[mt][nt][3] + bb1;
                }
        }
        __syncthreads();
        if (warpN == 0) {
            #pragma unroll
            for (int mt = 0; mt < 2; mt++)
                #pragma unroll
                for (int nt = 0; nt < 8; nt++) {
                    int r0 = warpM*32 + mt*16 + g, r1 = r0 + 8;
                    int c  = nt*8 + t2*2;
                    float bb0 = bias0[co + c], bb1 = bias0[co + c + 1];
                    float a00 = acc[mt][nt][0] + bb0, a01 = acc[mt][nt][1] + bb1;
                    float a10 = acc[mt][nt][2] + bb0, a11 = acc[mt][nt][3] + bb1;
                    float q00 = qs[r0*QS + c], q01 = qs[r0*QS + c + 1];
                    float q10 = qs[r1*QS + c], q11 = qs[r1*QS + c + 1];
                    float* x0 = Cf + (size_t)(m0 + r0) * DD + co + c;
                    float* x1 = Cf + (size_t)(m0 + r1) * DD + co + c;
                    float2 v0 = *(float2*)x0, v1 = *(float2*)x1;
                    v0.x = fmaf(a00, 1.f/(1.f + expf(-q00)), v0.x);
                    v0.y = fmaf(a01, 1.f/(1.f + expf(-q01)), v0.y);
                    v1.x = fmaf(a10, 1.f/(1.f + expf(-q10)), v1.x);
                    v1.y = fmaf(a11, 1.f/(1.f + expf(-q11)), v1.y);
                    *(float2*)x0 = v0;
                    *(float2*)x1 = v1;
                }
        }
        return;
    }
    #pragma unroll
    for (int mt = 0; mt < 2; mt++) {
        #pragma unroll
        for (int nt = 0; nt < 8; nt++) {
            int row0 = m0 + warpM*32 + mt*16 + g;
            int row1 = row0 + 8;
            int col  = n0 + warpN*64 + nt*8 + t2*2;
            float c0 = acc[mt][nt][0], c1 = acc[mt][nt][1];
            float c2 = acc[mt][nt][2], c3 = acc[mt][nt][3];
            if (epi == 0) {
                float b0v = bias0[col], b1v = bias0[col + 1];
                *(float2*)(Cf + (size_t)row0 * ldc + col) = make_float2(c0 + b0v, c1 + b1v);
                *(float2*)(Cf + (size_t)row1 * ldc + col) = make_float2(c2 + b0v, c3 + b1v);
            } else {
                float d0 = epi_n[col], d1 = epi_n[col+1];
                __half2 xh0 = *(const __half2*)(epi_mh + (size_t)row0 * DD + col);
                __half2 xl0 = *(const __half2*)(epi_ml + (size_t)row0 * DD + col);
                __half2 xh1 = *(const __half2*)(epi_mh + (size_t)row1 * DD + col);
                __half2 xl1 = *(const __half2*)(epi_ml + (size_t)row1 * DD + col);
                float m00 = __half2float(xh0.x) + __half2float(xl0.x);
                float m01 = __half2float(xh0.y) + __half2float(xl0.y);
                float m10 = __half2float(xh1.x) + __half2float(xl1.x);
                float m11 = __half2float(xh1.y) + __half2float(xl1.y);
                float v0 = gelu_exact(c0 + m00 * d0);
                float v1 = gelu_exact(c1 + m01 * d1);
                float v2 = gelu_exact(c2 + m10 * d0);
                float v3 = gelu_exact(c3 + m11 * d1);
                __half2 ph0(__float2half_rn(v0), __float2half_rn(v1));
                __half2 ph1(__float2half_rn(v2), __float2half_rn(v3));
                *(uint32_t*)(Ch + (size_t)row0 * ldc + col) = *(uint32_t*)&ph0;
                *(uint32_t*)(Ch + (size_t)row1 * ldc + col) = *(uint32_t*)&ph1;
            }
        }
    }
}

// ---------------- parameter prep ----------------
__global__ void prep_kernel(const float* __restrict__ nu_log,
                            const float* __restrict__ theta_log) {
    int i = blockIdx.x * blockDim.x + threadIdx.x;
    float nu = expf(nu_log[i]);
    float th = expf(theta_log[i]);
    float r  = expf(-nu);
    g_lam_re[i] = r * cosf(th);
    g_lam_im[i] = r * sinf(th);
    g_gam[i]    = sqrtf(1.0f - expf(-2.0f * nu) + 1e-5f);
}

// ---------------- input splitter ----------------
__global__ void split_in_kernel(const float* __restrict__ s) {
    int i = blockIdx.x * 256 + threadIdx.x;
    f16 h, l;
    split2h(s[i], h, l);
    g_in_h[i] = h; g_in_l[i] = l;
}

// ---------------- all-weights converter (single fp16 plane) ----------------
#define NW  (DD*FF)
#define NB  (LNUM*2*HH*DD)
#define NC  (LNUM*DD*2*HH)
#define NG  (LNUM*2*DD*DD)
__global__ void split_wts_kernel(const float* __restrict__ W_in,
                                 const float* __restrict__ B_re,
                                 const float* __restrict__ B_im,
                                 const float* __restrict__ C_re,
                                 const float* __restrict__ C_im,
                                 const float* __restrict__ w1,
                                 const float* __restrict__ w2) {
    int idx = blockIdx.x * 256 + threadIdx.x;
    float v;
    if (idx < NW) {
        g_win[idx] = __float2half_rn(W_in[idx]);
        return;
    }
    idx -= NW;
    if (idx < NB) {
        int l_ = idx / (2*HH*DD);
        int t  = idx - l_ * (2*HH*DD);
        int np = t >> 10, c = t & 1023;
        int j = np >> 7, o = np & 127;
        if (o < 64) v = B_re[(size_t)l_*HH*DD + (j*64 + o)*DD + c];
        else        v = B_im[(size_t)l_*HH*DD + (j*64 + o - 64)*DD + c];
        g_bw[idx] = __float2half_rn(v);
        return;
    }
    idx -= NB;
    if (idx < NC) {
        int l_ = idx / (DD*2*HH);
        int t  = idx - l_ * (DD*2*HH);
        int r  = t >> 11, k = t & 2047;
        int j = k >> 7, o = k & 127;
        if (o < 64) v = C_re[(size_t)l_*DD*HH + r*HH + (j*64 + o)];
        else        v = -C_im[(size_t)l_*DD*HH + r*HH + (j*64 + o - 64)];
        g_cw[idx] = __float2half_rn(v);
        return;
    }
    idx -= NC;
    {
        int l_ = idx / (2*DD*DD);
        int t  = idx - l_ * (2*DD*DD);
        int np = t >> 10, c = t & 1023;
        int blk = np >> 7, off = np & 127;
        if (off < 64) v = w1[(size_t)l_*DD*DD + (blk*64 + off)*DD + c];
        else          v = w2[(size_t)l_*DD*DD + (blk*64 + off - 64)*DD + c];
        g_gw[idx] = __float2half_rn(v);
    }
}

// ---------------- layernorm (fp16 split outputs only) ----------------
__global__ void ln_kernel(const float* __restrict__ x,
                          const float* __restrict__ sc,
                          const float* __restrict__ bi,
                          f16* __restrict__ oh, f16* __restrict__ ol) {
    __shared__ float red[16];
    int row = blockIdx.x;
    int tid = threadIdx.x;
    const float* xr = x + (size_t)row * DD;
    float4 v = *(const float4*)(xr + tid * 4);
    float s  = v.x + v.y + v.z + v.w;
    float ss = v.x*v.x + v.y*v.y + v.z*v.z + v.w*v.w;
    #pragma unroll
    for (int off = 16; off; off >>= 1) {
        s  += __shfl_xor_sync(0xffffffffu, s,  off);
        ss += __shfl_xor_sync(0xffffffffu, ss, off);
    }
    int wid = tid >> 5;
    if ((tid & 31) == 0) { red[wid] = s; red[8 + wid] = ss; }
    __syncthreads();
    float S = 0.f, SS_ = 0.f;
    #pragma unroll
    for (int w = 0; w < 8; w++) { S += red[w]; SS_ += red[8 + w]; }
    float mu  = S * (1.0f / DD);
    float var = SS_ * (1.0f / DD) - mu * mu;
    float rstd = rsqrtf(var + 1e-5f);
    float4 s4 = *(const float4*)(sc + tid * 4);
    float4 b4 = *(const float4*)(bi + tid * 4);
    float ov[4];
    ov[0] = (v.x - mu) * rstd * s4.x + b4.x;
    ov[1] = (v.y - mu) * rstd * s4.y + b4.y;
    ov[2] = (v.z - mu) * rstd * s4.z + b4.z;
    ov[3] = (v.w - mu) * rstd * s4.w + b4.w;
    f16 h[4], l[4];
    #pragma unroll
    for (int j = 0; j < 4; j++) split2h(ov[j], h[j], l[j]);
    *(uint2*)(oh + (size_t)row * DD + tid * 4) = *(uint2*)h;
    *(uint2*)(ol + (size_t)row * DD + tid * 4) = *(uint2*)l;
}

// ---------------- scan carry (over chunk summaries) ----------------
__global__ void scan_carry_kernel(int loff) {
    int idx = blockIdx.x * blockDim.x + threadIdx.x;
    int b = idx >> 10, h = idx & (HH - 1);
    float lre = g_lam_re[loff + h], lim = g_lam_im[loff + h];
    float pre = lre, pim = lim;
    #pragma unroll
    for (int i = 0; i < 7; i++) {
        float nr = pre*pre - pim*pim;
        float ni = 2.f*pre*pim;
        pre = nr; pim = ni;
    }
    float cre = 0.f, cim = 0.f;
    #pragma unroll
    for (int c = 0; c < NCHUNK; c++) {
        int o = (b * NCHUNK + c) * HH + h;
        g_car_re[o] = cre; g_car_im[o] = cim;
        float sre = g_sum_re[o], sim = g_sum_im[o];
        float nr = cre*pre - cim*pim + sre;
        float ni = cre*pim + cim*pre + sim;
        cre = nr; cim = ni;
    }
}

// ---------------- scan apply (interleaved bu layout) ----------------
__global__ void scan_apply_kernel(const float* __restrict__ bu,
                                  f16* __restrict__ hsh, f16* __restrict__ hsl,
                                  int loff) {
    int h = blockIdx.x * blockDim.x + threadIdx.x;
    int c = blockIdx.y, b = blockIdx.z;
    float lre = g_lam_re[loff + h], lim = g_lam_im[loff + h];
    int o = (b * NCHUNK + c) * HH + h;
    float are = g_car_re[o], aim = g_car_im[o];
    int col = ((h >> 6) << 7) + (h & 63);   // interleaved re col; im at +64
    size_t base = ((size_t)(b * TT + c * CL)) * (2 * HH) + col;
    #pragma unroll 4
    for (int j = 0; j < CL; j++) {
        float ure = bu[base], uim = bu[base + 64];
        float nr = fmaf(are, lre, fmaf(-aim, lim, ure));
        float ni = fmaf(are, lim, fmaf(aim, lre, uim));
        are = nr; aim = ni;
        f16 hh, ll;
        split2h(are, hh, ll);
        hsh[base] = hh; hsl[base] = ll;
        split2h(aim, hh, ll);
        hsh[base + 64] = hh; hsl[base + 64] = ll;
        base += 2 * HH;
    }
}

// ---------------- launch ----------------
extern "C" void kernel_launch(void* const* d_in, const int* in_sizes, int n_in,
                              void* d_out, int out_size) {
    const float* inputs    = (const float*)d_in[0];
    const float* W_in      = (const float*)d_in[1];
    const float* b_in      = (const float*)d_in[2];
    const float* nu_log    = (const float*)d_in[3];
    const float* theta_log = (const float*)d_in[4];
    const float* B_re      = (const float*)d_in[5];
    const float* B_im      = (const float*)d_in[6];
    const float* C_re      = (const float*)d_in[7];
    const float* C_im      = (const float*)d_in[8];
    const float* D_diag    = (const float*)d_in[9];
    const float* ln_scale  = (const float*)d_in[10];
    const float* ln_bias   = (const float*)d_in[11];
    const float* w1        = (const float*)d_in[12];
    const float* b1        = (const float*)d_in[13];
    const float* w2        = (const float*)d_in[14];
    const float* b2        = (const float*)d_in[15];
    float* x = (float*)d_out;

    cudaFuncSetAttribute(gemm_mma, cudaFuncAttributeMaxDynamicSharedMemorySize, SMEMB);

    float *p_bu, *p_gam;
    f16 *p_xnh, *p_xnl, *p_inh, *p_inl, *p_hsh, *p_hsl, *p_yh;
    f16 *p_win, *p_bw, *p_cw, *p_gw;
    cudaGetSymbolAddress((void**)&p_bu,  g_bu);
    cudaGetSymbolAddress((void**)&p_gam, g_gam);
    cudaGetSymbolAddress((void**)&p_xnh, g_xn_h);
    cudaGetSymbolAddress((void**)&p_xnl, g_xn_l);
    cudaGetSymbolAddress((void**)&p_inh, g_in_h);
    cudaGetSymbolAddress((void**)&p_inl, g_in_l);
    cudaGetSymbolAddress((void**)&p_hsh, g_hs_h);
    cudaGetSymbolAddress((void**)&p_hsl, g_hs_l);
    cudaGetSymbolAddress((void**)&p_yh,  g_y_h);
    cudaGetSymbolAddress((void**)&p_win, g_win);
    cudaGetSymbolAddress((void**)&p_bw,  g_bw);
    cudaGetSymbolAddress((void**)&p_cw,  g_cw);
    cudaGetSymbolAddress((void**)&p_gw,  g_gw);

    // params, split inputs, convert all weights
    prep_kernel<<<(LNUM * HH) / 256, 256>>>(nu_log, theta_log);
    split_in_kernel<<<(MTOT*FF)/256, 256>>>(inputs);
    split_wts_kernel<<<(NW + NB + NC + NG)/256, 256>>>(
        W_in, B_re, B_im, C_re, C_im, w1, w2);

    // input projection: x = inputs @ W_in^T + b_in  (2-pass)
    gemm_mma<<<dim3(DD/128, MTOT/128), 256, SMEMB>>>(
        p_inh, p_inl, FF, p_win,
        x, nullptr, DD, FF, 0,
        b_in, nullptr, nullptr, nullptr, nullptr, 0);

    for (int l = 0; l < LNUM; l++) {
        // layernorm -> fp16 split planes
        ln_kernel<<<MTOT, 256>>>(x, ln_scale + l*DD, ln_bias + l*DD, p_xnh, p_xnl);

        // Bu = gamma * (xn @ Bw^T) with fused chunk-scan summaries (2-pass)
        gemm_mma<<<dim3(2*HH/128, MTOT/128), 256, SMEMB>>>(
            p_xnh, p_xnl, DD,
            p_bw + (size_t)l*2*HH*DD,
            p_bu, nullptr, 2*HH, DD, 4,
            nullptr, nullptr, nullptr, nullptr, p_gam + l*HH, l*HH);

        scan_carry_kernel<<<(BB*HH)/256, 256>>>(l*HH);
        scan_apply_kernel<<<dim3(HH/256, NCHUNK, BB), 256>>>(p_bu, p_hsh, p_hsl, l*HH);

        // y = gelu( hs @ Cw^T + xn * D_diag )  (2-pass, fp16 out)
        gemm_mma<<<dim3(DD/128, MTOT/128), 256, SMEMB>>>(
            p_hsh, p_hsl, 2*HH,
            p_cw + (size_t)l*DD*2*HH,
            nullptr, p_yh, DD, 2*HH, 2,
            nullptr, nullptr, p_xnh, p_xnl, D_diag + l*DD, 0);

        // fused GLU + residual (1-pass): x += (y@w1^T + b1) * sigmoid(y@w2^T + b2)
        gemm_mma<<<dim3(2*DD/128, MTOT/128), 256, SMEMB>>>(
            p_yh, nullptr, DD,
            p_gw + (size_t)l*2*DD*DD,
            x, nullptr, DD, DD, 3,
            b1 + l*DD, b2 + l*DD, nullptr, nullptr, nullptr, 0);
    }
    (void)in_sizes; (void)n_in; (void)out_size;
}

// round 14
// speedup vs baseline: 4.4394x; 1.0218x over previous
#include <cuda_runtime.h>
#include <cuda_fp16.h>
#include <math.h>
#include <stdint.h>

// ---------------- problem constants ----------------
#define LNUM 4
#define BB   4
#define TT   2048
#define DD   1024
#define HH   1024
#define FF   256
#define MTOT (BB*TT)          // 8192
#define NCHUNK 16
#define CL   (TT/NCHUNK)      // 128

// ---------------- mma GEMM config ----------------
#define BKC   64                      // k elements per stage
#define MATB  (128*128)               // 128 rows x 128B (swizzled)
#define STAGEB (3*MATB)               // Ah, Al, W = 48 KB
#define NSTG  2
#define SMEMB (NSTG*STAGEB)           // 98304 B -> 2 CTAs/SM
#define QS    72                      // fused-GLU smem staging stride (floats)
#define SS    132                     // Bu-scan smem staging stride (floats)

typedef __half f16;

// ---------------- scratch (device globals; no allocs allowed) ----------------
__device__ __align__(16) f16   g_xn_h[MTOT*DD];
__device__ __align__(16) f16   g_xn_l[MTOT*DD];
__device__ __align__(16) f16   g_in_h[MTOT*FF];
__device__ __align__(16) f16   g_in_l[MTOT*FF];
__device__ __align__(16) float g_bu[MTOT*2*HH];
__device__ __align__(16) f16   g_hs_h[MTOT*2*HH];
__device__ __align__(16) f16   g_y_h[MTOT*DD];
__device__ __align__(16) f16   g_win[DD*FF];
__device__ __align__(16) f16   g_bw[LNUM*2*HH*DD];
__device__ __align__(16) f16   g_cw[LNUM*DD*2*HH];
__device__ __align__(16) f16   g_gw[LNUM*2*DD*DD];
__device__ float g_lam_re[LNUM*HH];
__device__ float g_lam_im[LNUM*HH];
__device__ float g_gam  [LNUM*HH];
__device__ float g_sum_re[BB*NCHUNK*HH];
__device__ float g_sum_im[BB*NCHUNK*HH];
__device__ float g_car_re[BB*NCHUNK*HH];
__device__ float g_car_im[BB*NCHUNK*HH];

// ---------------- helpers ----------------
__device__ __forceinline__ float gelu_exact(float v) {
    return 0.5f * v * (1.0f + erff(v * 0.70710678118654752f));
}
__device__ __forceinline__ void split2h(float v, f16& h, f16& l) {
    h = __float2half_rn(v);
    l = __float2half_rn(v - __half2float(h));
}
__device__ __forceinline__ void cp16(uint32_t d, const void* s) {
    asm volatile("cp.async.cg.shared.global [%0], [%1], 16;" :: "r"(d), "l"(s));
}
__device__ __forceinline__ void cpcommit() {
    asm volatile("cp.async.commit_group;" ::: "memory");
}
template<int N> __device__ __forceinline__ void cpwait() {
    asm volatile("cp.async.wait_group %0;" :: "n"(N) : "memory");
}
__device__ __forceinline__ void mma_f16(float* c, const uint32_t* a,
                                        uint32_t b0, uint32_t b1) {
    asm volatile("mma.sync.aligned.m16n8k16.row.col.f32.f16.f16.f32 "
        "{%0,%1,%2,%3}, {%4,%5,%6,%7}, {%8,%9}, {%0,%1,%2,%3};"
        : "+f"(c[0]), "+f"(c[1]), "+f"(c[2]), "+f"(c[3])
        : "r"(a[0]), "r"(a[1]), "r"(a[2]), "r"(a[3]), "r"(b0), "r"(b1));
}
__device__ __forceinline__ void ldm4(uint32_t* r, uint32_t a) {
    asm volatile("ldmatrix.sync.aligned.m8n8.x4.shared.b16 {%0,%1,%2,%3}, [%4];"
        : "=r"(r[0]), "=r"(r[1]), "=r"(r[2]), "=r"(r[3]) : "r"(a));
}

// swizzled chunk offset: row r (128B rows), 16B-chunk c (0..7)
__device__ __forceinline__ uint32_t swz(int r, int c) {
    return (uint32_t)(r * 128 + ((c ^ (r & 7)) << 4));
}

// load one K-stage: Ah (+Al if two) rows m0.., W rows n0..  (128 rows x 128B each)
__device__ __forceinline__ void ldstage(uint32_t sb, int slot,
        const f16* Ah, const f16* Al, int lda,
        const f16* W, int ldw,
        int m0, int n0, int kb, int tid, bool two) {
    uint32_t st = sb + (uint32_t)slot * STAGEB;
    #pragma unroll
    for (int j = 0; j < 4; j++) {
        int chunk = tid + j * 256;
        int row   = chunk >> 3;
        int c     = chunk & 7;
        uint32_t d = st + swz(row, c);
        int ke = kb + c * 8;
        cp16(d,           Ah + (size_t)(m0+row)*lda + ke);
        if (two) cp16(d + MATB, Al + (size_t)(m0+row)*lda + ke);
        cp16(d + 2*MATB,  W  + (size_t)(n0+row)*ldw + ke);
    }
    cpcommit();
}

// ---------------- split-fp16 tensor-core GEMM ----------------
// C[m,n] = sum_k A[m,k]*W[n,k];  A = Ah(+Al if Al!=null), W = fp16 (rn)
// epi 0: Cf = acc + bias0(n)
// epi 2: Ch = half(gelu(acc + (epi_mh+epi_ml)[m,n]*epi_n[n]))
// epi 3: fused GLU: W interleaved [w1|w2] per 128-tile; x += (a+b1)*sigmoid(q+b2)
// epi 4: Bu + chunk-scan: W interleaved [re|im] per 128-tile; Cf = acc*gamma,
//        then 128-step chunk scan over rows -> g_sum_re/im
__global__ __launch_bounds__(256, 2)
void gemm_mma(const f16* __restrict__ Ah, const f16* __restrict__ Al, int lda,
              const f16* __restrict__ W,
              float* __restrict__ Cf, f16* __restrict__ Ch,
              int ldc, int K, int epi,
              const float* __restrict__ bias0, const float* __restrict__ bias1,
              const f16* __restrict__ epi_mh, const f16* __restrict__ epi_ml,
              const float* __restrict__ epi_n, int loff) {
    extern __shared__ __align__(16) char smc[];
    uint32_t sb = (uint32_t)__cvta_generic_to_shared(smc);
    const int tid  = threadIdx.x;
    const int wid  = tid >> 5, lane = tid & 31;
    const int g    = lane >> 2, t2 = lane & 3;
    const int warpM = wid & 3;
    const int warpN = wid >> 2;
    const int m0 = blockIdx.y * 128;
    const int n0 = blockIdx.x * 128;
    const int NCH = K / BKC;
    const bool twopass = (Al != nullptr);

    // ldmatrix per-lane rows / chunk bases
    const int grp = lane >> 3, rr = lane & 7;
    const int cA0 = grp >> 1;           // A chunk base within 2-chunk group (0/1)
    const int cB0 = grp & 1;            // B chunk base (0/1)
    int  rA[2], rB[4];
    #pragma unroll
    for (int mt = 0; mt < 2; mt++) rA[mt] = warpM*32 + mt*16 + rr + (grp & 1)*8;
    #pragma unroll
    for (int ntp = 0; ntp < 4; ntp++) rB[ntp] = warpN*64 + ntp*16 + rr + (grp >> 1)*8;

    float acc[2][8][4];
    #pragma unroll
    for (int i = 0; i < 2; i++)
        #pragma unroll
        for (int j = 0; j < 8; j++)
            #pragma unroll
            for (int q = 0; q < 4; q++) acc[i][j][q] = 0.f;

    // prologue: stages 0,1 in flight; wait stage 0, publish
    ldstage(sb, 0, Ah, Al, lda, W, K, m0, n0, 0,   tid, twopass);
    ldstage(sb, 1, Ah, Al, lda, W, K, m0, n0, BKC, tid, twopass);
    cpwait<1>();
    __syncthreads();

    for (int t = 0; t < NCH; t++) {
        const int slot = t & 1;
        uint32_t st   = sb + (uint32_t)slot * STAGEB;
        uint32_t Ah_s = st, Al_s = st + MATB, W_s = st + 2*MATB;

        #pragma unroll
        for (int kh = 0; kh < 4; kh++) {
            uint32_t ah[2][4], al[2][4];
            #pragma unroll
            for (int mt = 0; mt < 2; mt++) {
                uint32_t ao = swz(rA[mt], cA0 + 2*kh);
                ldm4(ah[mt], Ah_s + ao);
                if (twopass) ldm4(al[mt], Al_s + ao);
            }
            #pragma unroll
            for (int ntp = 0; ntp < 4; ntp++) {
                uint32_t bo = swz(rB[ntp], cB0 + 2*kh);
                uint32_t bh[4];
                ldm4(bh, W_s + bo);
                int nt0 = ntp*2, nt1 = ntp*2 + 1;
                // pass hi
                mma_f16(acc[0][nt0], ah[0], bh[0], bh[1]);
                mma_f16(acc[1][nt0], ah[1], bh[0], bh[1]);
                mma_f16(acc[0][nt1], ah[0], bh[2], bh[3]);
                mma_f16(acc[1][nt1], ah[1], bh[2], bh[3]);
                // pass lo
                if (twopass) {
                    mma_f16(acc[0][nt0], al[0], bh[0], bh[1]);
                    mma_f16(acc[1][nt0], al[1], bh[0], bh[1]);
                    mma_f16(acc[0][nt1], al[0], bh[2], bh[3]);
                    mma_f16(acc[1][nt1], al[1], bh[2], bh[3]);
                }
            }
        }

        // WAR guard: all warps must finish reading this slot before refill
        __syncthreads();
        // refill the slot we just consumed with stage t+2 (lands during stage t+1)
        if (t + 2 < NCH)
            ldstage(sb, slot, Ah, Al, lda, W, K, m0, n0, (t+2)*BKC, tid, twopass);
        else
            cpcommit();
        cpwait<1>();       // stage t+1 resident
        __syncthreads();   // publish stage t+1 CTA-wide
    }

    // ---- epilogue ----
    if (epi == 4) {
        // Bu (gamma-scaled, interleaved re/im columns) + in-tile chunk scan.
        const int j = n0 >> 7;
        float* sm = (float*)smc;
        #pragma unroll
        for (int mt = 0; mt < 2; mt++)
            #pragma unroll
            for (int nt = 0; nt < 8; nt++) {
                int r0 = warpM*32 + mt*16 + g, r1 = r0 + 8;
                int nn = warpN*64 + nt*8 + t2*2;
                int hI = j*64 + (nn & 63);
                float e0 = epi_n[hI], e1 = epi_n[hI + 1];
                float c0 = acc[mt][nt][0]*e0, c1 = acc[mt][nt][1]*e1;
                float c2 = acc[mt][nt][2]*e0, c3 = acc[mt][nt][3]*e1;
                *(float2*)(Cf + (size_t)(m0 + r0) * ldc + n0 + nn) = make_float2(c0, c1);
                *(float2*)(Cf + (size_t)(m0 + r1) * ldc + n0 + nn) = make_float2(c2, c3);
                sm[r0*SS + nn] = c0;  sm[r0*SS + nn + 1] = c1;
                sm[r1*SS + nn] = c2;  sm[r1*SS + nn + 1] = c3;
            }
        __syncthreads();
        if (tid < 64) {
            int h = j*64 + tid;
            float lre = g_lam_re[loff + h], lim = g_lam_im[loff + h];
            float are = 0.f, aim = 0.f;
            #pragma unroll 4
            for (int r = 0; r < 128; r++) {
                float ure = sm[r*SS + (tid & 63)];
                float uim = sm[r*SS + 64 + (tid & 63)];
                float nr = fmaf(are, lre, fmaf(-aim, lim, ure));
                float ni = fmaf(are, lim, fmaf(aim, lre, uim));
                are = nr; aim = ni;
            }
            int b = m0 >> 11;
            int chunk = (m0 & (TT - 1)) >> 7;
            int o = (b * NCHUNK + chunk) * HH + h;
            g_sum_re[o] = are; g_sum_im[o] = aim;
        }
        return;
    }
    if (epi == 3) {
        // fused GLU: tile cols 0-63 = w1 (a), 64-127 = w2 (q); output cols co..co+63
        const int co = blockIdx.x * 64;
        float* qs = (float*)smc;
        if (warpN == 1) {
            #pragma unroll
            for (int mt = 0; mt < 2; mt++)
                #pragma unroll
                for (int nt = 0; nt < 8; nt++) {
                    int r0 = warpM*32 + mt*16 + g, r1 = r0 + 8;
                    int c  = nt*8 + t2*2;
                    float bb0 = bias1[co + c], bb1 = bias1[co + c + 1];
                    qs[r0*QS + c]     = acc[mt][nt][0] + bb0;
                    qs[r0*QS + c + 1] = acc[mt][nt][1] + bb1;
                    qs[r1*QS + c]     = acc[mt][nt][2] + bb0;
                    qs[r1*QS + c + 1] = acc[mt][nt][3] + bb1;
                }
        }
        __syncthreads();
        if (warpN == 0) {
            #pragma unroll
            for (int mt = 0; mt < 2; mt++)
                #pragma unroll
                for (int nt = 0; nt < 8; nt++) {
                    int r0 = warpM*32 + mt*16 + g, r1 = r0 + 8;
                    int c  = nt*8 + t2*2;
                    float bb0 = bias0[co + c], bb1 = bias0[co + c + 1];
                    float a00 = acc[mt][nt][0] + bb0, a01 = acc[mt][nt][1] + bb1;
                    float a10 = acc[mt][nt][2] + bb0, a11 = acc[mt][nt][3] + bb1;
                    float q00 = qs[r0*QS + c], q01 = qs[r0*QS + c + 1];
                    float q10 = qs[r1*QS + c], q11 = qs[r1*QS + c + 1];
                    float* x0 = Cf + (size_t)(m0 + r0) * DD + co + c;
                    float* x1 = Cf + (size_t)(m0 + r1) * DD + co + c;
                    float2 v0 = *(float2*)x0, v1 = *(float2*)x1;
                    v0.x = fmaf(a00, 1.f/(1.f + expf(-q00)), v0.x);
                    v0.y = fmaf(a01, 1.f/(1.f + expf(-q01)), v0.y);
                    v1.x = fmaf(a10, 1.f/(1.f + expf(-q10)), v1.x);
                    v1.y = fmaf(a11, 1.f/(1.f + expf(-q11)), v1.y);
                    *(float2*)x0 = v0;
                    *(float2*)x1 = v1;
                }
        }
        return;
    }
    #pragma unroll
    for (int mt = 0; mt < 2; mt++) {
        #pragma unroll
        for (int nt = 0; nt < 8; nt++) {
            int row0 = m0 + warpM*32 + mt*16 + g;
            int row1 = row0 + 8;
            int col  = n0 + warpN*64 + nt*8 + t2*2;
            float c0 = acc[mt][nt][0], c1 = acc[mt][nt][1];
            float c2 = acc[mt][nt][2], c3 = acc[mt][nt][3];
            if (epi == 0) {
                float b0v = bias0[col], b1v = bias0[col + 1];
                *(float2*)(Cf + (size_t)row0 * ldc + col) = make_float2(c0 + b0v, c1 + b1v);
                *(float2*)(Cf + (size_t)row1 * ldc + col) = make_float2(c2 + b0v, c3 + b1v);
            } else {
                float d0 = epi_n[col], d1 = epi_n[col+1];
                __half2 xh0 = *(const __half2*)(epi_mh + (size_t)row0 * DD + col);
                __half2 xl0 = *(const __half2*)(epi_ml + (size_t)row0 * DD + col);
                __half2 xh1 = *(const __half2*)(epi_mh + (size_t)row1 * DD + col);
                __half2 xl1 = *(const __half2*)(epi_ml + (size_t)row1 * DD + col);
                float m00 = __half2float(xh0.x) + __half2float(xl0.x);
                float m01 = __half2float(xh0.y) + __half2float(xl0.y);
                float m10 = __half2float(xh1.x) + __half2float(xl1.x);
                float m11 = __half2float(xh1.y) + __half2float(xl1.y);
                float v0 = gelu_exact(c0 + m00 * d0);
                float v1 = gelu_exact(c1 + m01 * d1);
                float v2 = gelu_exact(c2 + m10 * d0);
                float v3 = gelu_exact(c3 + m11 * d1);
                __half2 ph0(__float2half_rn(v0), __float2half_rn(v1));
                __half2 ph1(__float2half_rn(v2), __float2half_rn(v3));
                *(uint32_t*)(Ch + (size_t)row0 * ldc + col) = *(uint32_t*)&ph0;
                *(uint32_t*)(Ch + (size_t)row1 * ldc + col) = *(uint32_t*)&ph1;
            }
        }
    }
}

// ---------------- parameter prep ----------------
__global__ void prep_kernel(const float* __restrict__ nu_log,
                            const float* __restrict__ theta_log) {
    int i = blockIdx.x * blockDim.x + threadIdx.x;
    float nu = expf(nu_log[i]);
    float th = expf(theta_log[i]);
    float r  = expf(-nu);
    g_lam_re[i] = r * cosf(th);
    g_lam_im[i] = r * sinf(th);
    g_gam[i]    = sqrtf(1.0f - expf(-2.0f * nu) + 1e-5f);
}

// ---------------- input splitter ----------------
__global__ void split_in_kernel(const float* __restrict__ s) {
    int i = blockIdx.x * 256 + threadIdx.x;
    f16 h, l;
    split2h(s[i], h, l);
    g_in_h[i] = h; g_in_l[i] = l;
}

// ---------------- all-weights converter (single fp16 plane) ----------------
#define NW  (DD*FF)
#define NB  (LNUM*2*HH*DD)
#define NC  (LNUM*DD*2*HH)
#define NG  (LNUM*2*DD*DD)
__global__ void split_wts_kernel(const float* __restrict__ W_in,
                                 const float* __restrict__ B_re,
                                 const float* __restrict__ B_im,
                                 const float* __restrict__ C_re,
                                 const float* __restrict__ C_im,
                                 const float* __restrict__ w1,
                                 const float* __restrict__ w2) {
    int idx = blockIdx.x * 256 + threadIdx.x;
    float v;
    if (idx < NW) {
        g_win[idx] = __float2half_rn(W_in[idx]);
        return;
    }
    idx -= NW;
    if (idx < NB) {
        int l_ = idx / (2*HH*DD);
        int t  = idx - l_ * (2*HH*DD);
        int np = t >> 10, c = t & 1023;
        int j = np >> 7, o = np & 127;
        if (o < 64) v = B_re[(size_t)l_*HH*DD + (j*64 + o)*DD + c];
        else        v = B_im[(size_t)l_*HH*DD + (j*64 + o - 64)*DD + c];
        g_bw[idx] = __float2half_rn(v);
        return;
    }
    idx -= NB;
    if (idx < NC) {
        int l_ = idx / (DD*2*HH);
        int t  = idx - l_ * (DD*2*HH);
        int r  = t >> 11, k = t & 2047;
        int j = k >> 7, o = k & 127;
        if (o < 64) v = C_re[(size_t)l_*DD*HH + r*HH + (j*64 + o)];
        else        v = -C_im[(size_t)l_*DD*HH + r*HH + (j*64 + o - 64)];
        g_cw[idx] = __float2half_rn(v);
        return;
    }
    idx -= NC;
    {
        int l_ = idx / (2*DD*DD);
        int t  = idx - l_ * (2*DD*DD);
        int np = t >> 10, c = t & 1023;
        int blk = np >> 7, off = np & 127;
        if (off < 64) v = w1[(size_t)l_*DD*DD + (blk*64 + off)*DD + c];
        else          v = w2[(size_t)l_*DD*DD + (blk*64 + off - 64)*DD + c];
        g_gw[idx] = __float2half_rn(v);
    }
}

// ---------------- layernorm (fp16 split outputs only) ----------------
__global__ void ln_kernel(const float* __restrict__ x,
                          const float* __restrict__ sc,
                          const float* __restrict__ bi,
                          f16* __restrict__ oh, f16* __restrict__ ol) {
    __shared__ float red[16];
    int row = blockIdx.x;
    int tid = threadIdx.x;
    const float* xr = x + (size_t)row * DD;
    float4 v = *(const float4*)(xr + tid * 4);
    float s  = v.x + v.y + v.z + v.w;
    float ss = v.x*v.x + v.y*v.y + v.z*v.z + v.w*v.w;
    #pragma unroll
    for (int off = 16; off; off >>= 1) {
        s  += __shfl_xor_sync(0xffffffffu, s,  off);
        ss += __shfl_xor_sync(0xffffffffu, ss, off);
    }
    int wid = tid >> 5;
    if ((tid & 31) == 0) { red[wid] = s; red[8 + wid] = ss; }
    __syncthreads();
    float S = 0.f, SS_ = 0.f;
    #pragma unroll
    for (int w = 0; w < 8; w++) { S += red[w]; SS_ += red[8 + w]; }
    float mu  = S * (1.0f / DD);
    float var = SS_ * (1.0f / DD) - mu * mu;
    float rstd = rsqrtf(var + 1e-5f);
    float4 s4 = *(const float4*)(sc + tid * 4);
    float4 b4 = *(const float4*)(bi + tid * 4);
    float ov[4];
    ov[0] = (v.x - mu) * rstd * s4.x + b4.x;
    ov[1] = (v.y - mu) * rstd * s4.y + b4.y;
    ov[2] = (v.z - mu) * rstd * s4.z + b4.z;
    ov[3] = (v.w - mu) * rstd * s4.w + b4.w;
    f16 h[4], l[4];
    #pragma unroll
    for (int j = 0; j < 4; j++) split2h(ov[j], h[j], l[j]);
    *(uint2*)(oh + (size_t)row * DD + tid * 4) = *(uint2*)h;
    *(uint2*)(ol + (size_t)row * DD + tid * 4) = *(uint2*)l;
}

// ---------------- scan carry (over chunk summaries) ----------------
__global__ void scan_carry_kernel(int loff) {
    int idx = blockIdx.x * blockDim.x + threadIdx.x;
    int b = idx >> 10, h = idx & (HH - 1);
    float lre = g_lam_re[loff + h], lim = g_lam_im[loff + h];
    float pre = lre, pim = lim;
    #pragma unroll
    for (int i = 0; i < 7; i++) {
        float nr = pre*pre - pim*pim;
        float ni = 2.f*pre*pim;
        pre = nr; pim = ni;
    }
    float cre = 0.f, cim = 0.f;
    #pragma unroll
    for (int c = 0; c < NCHUNK; c++) {
        int o = (b * NCHUNK + c) * HH + h;
        g_car_re[o] = cre; g_car_im[o] = cim;
        float sre = g_sum_re[o], sim = g_sum_im[o];
        float nr = cre*pre - cim*pim + sre;
        float ni = cre*pim + cim*pre + sim;
        cre = nr; cim = ni;
    }
}

// ---------------- scan apply (interleaved bu layout; single fp16 hs plane) ----------------
__global__ void scan_apply_kernel(const float* __restrict__ bu,
                                  f16* __restrict__ hsh, int loff) {
    int h = blockIdx.x * blockDim.x + threadIdx.x;
    int c = blockIdx.y, b = blockIdx.z;
    float lre = g_lam_re[loff + h], lim = g_lam_im[loff + h];
    int o = (b * NCHUNK + c) * HH + h;
    float are = g_car_re[o], aim = g_car_im[o];
    int col = ((h >> 6) << 7) + (h & 63);   // interleaved re col; im at +64
    size_t base = ((size_t)(b * TT + c * CL)) * (2 * HH) + col;
    #pragma unroll 4
    for (int j = 0; j < CL; j++) {
        float ure = bu[base], uim = bu[base + 64];
        float nr = fmaf(are, lre, fmaf(-aim, lim, ure));
        float ni = fmaf(are, lim, fmaf(aim, lre, uim));
        are = nr; aim = ni;
        hsh[base]      = __float2half_rn(are);
        hsh[base + 64] = __float2half_rn(aim);
        base += 2 * HH;
    }
}

// ---------------- launch ----------------
extern "C" void kernel_launch(void* const* d_in, const int* in_sizes, int n_in,
                              void* d_out, int out_size) {
    const float* inputs    = (const float*)d_in[0];
    const float* W_in      = (const float*)d_in[1];
    const float* b_in      = (const float*)d_in[2];
    const float* nu_log    = (const float*)d_in[3];
    const float* theta_log = (const float*)d_in[4];
    const float* B_re      = (const float*)d_in[5];
    const float* B_im      = (const float*)d_in[6];
    const float* C_re      = (const float*)d_in[7];
    const float* C_im      = (const float*)d_in[8];
    const float* D_diag    = (const float*)d_in[9];
    const float* ln_scale  = (const float*)d_in[10];
    const float* ln_bias   = (const float*)d_in[11];
    const float* w1        = (const float*)d_in[12];
    const float* b1        = (const float*)d_in[13];
    const float* w2        = (const float*)d_in[14];
    const float* b2        = (const float*)d_in[15];
    float* x = (float*)d_out;

    cudaFuncSetAttribute(gemm_mma, cudaFuncAttributeMaxDynamicSharedMemorySize, SMEMB);

    float *p_bu, *p_gam;
    f16 *p_xnh, *p_xnl, *p_inh, *p_inl, *p_hsh, *p_yh;
    f16 *p_win, *p_bw, *p_cw, *p_gw;
    cudaGetSymbolAddress((void**)&p_bu,  g_bu);
    cudaGetSymbolAddress((void**)&p_gam, g_gam);
    cudaGetSymbolAddress((void**)&p_xnh, g_xn_h);
    cudaGetSymbolAddress((void**)&p_xnl, g_xn_l);
    cudaGetSymbolAddress((void**)&p_inh, g_in_h);
    cudaGetSymbolAddress((void**)&p_inl, g_in_l);
    cudaGetSymbolAddress((void**)&p_hsh, g_hs_h);
    cudaGetSymbolAddress((void**)&p_yh,  g_y_h);
    cudaGetSymbolAddress((void**)&p_win, g_win);
    cudaGetSymbolAddress((void**)&p_bw,  g_bw);
    cudaGetSymbolAddress((void**)&p_cw,  g_cw);
    cudaGetSymbolAddress((void**)&p_gw,  g_gw);

    // params, split inputs, convert all weights
    prep_kernel<<<(LNUM * HH) / 256, 256>>>(nu_log, theta_log);
    split_in_kernel<<<(MTOT*FF)/256, 256>>>(inputs);
    split_wts_kernel<<<(NW + NB + NC + NG)/256, 256>>>(
        W_in, B_re, B_im, C_re, C_im, w1, w2);

    // input projection: x = inputs @ W_in^T + b_in  (2-pass)
    gemm_mma<<<dim3(DD/128, MTOT/128), 256, SMEMB>>>(
        p_inh, p_inl, FF, p_win,
        x, nullptr, DD, FF, 0,
        b_in, nullptr, nullptr, nullptr, nullptr, 0);

    for (int l = 0; l < LNUM; l++) {
        // layernorm -> fp16 split planes
        ln_kernel<<<MTOT, 256>>>(x, ln_scale + l*DD, ln_bias + l*DD, p_xnh, p_xnl);

        // Bu = gamma * (xn @ Bw^T) with fused chunk-scan summaries (2-pass)
        gemm_mma<<<dim3(2*HH/128, MTOT/128), 256, SMEMB>>>(
            p_xnh, p_xnl, DD,
            p_bw + (size_t)l*2*HH*DD,
            p_bu, nullptr, 2*HH, DD, 4,
            nullptr, nullptr, nullptr, nullptr, p_gam + l*HH, l*HH);

        scan_carry_kernel<<<(BB*HH)/256, 256>>>(l*HH);
        scan_apply_kernel<<<dim3(HH/256, NCHUNK, BB), 256>>>(p_bu, p_hsh, l*HH);

        // y = gelu( hs @ Cw^T + xn * D_diag )  (1-pass, fp16 out)
        gemm_mma<<<dim3(DD/128, MTOT/128), 256, SMEMB>>>(
            p_hsh, nullptr, 2*HH,
            p_cw + (size_t)l*DD*2*HH,
            nullptr, p_yh, DD, 2*HH, 2,
            nullptr, nullptr, p_xnh, p_xnl, D_diag + l*DD, 0);

        // fused GLU + residual (1-pass): x += (y@w1^T + b1) * sigmoid(y@w2^T + b2)
        gemm_mma<<<dim3(2*DD/128, MTOT/128), 256, SMEMB>>>(
            p_yh, nullptr, DD,
            p_gw + (size_t)l*2*DD*DD,
            x, nullptr, DD, DD, 3,
            b1 + l*DD, b2 + l*DD, nullptr, nullptr, nullptr, 0);
    }
    (void)in_sizes; (void)n_in; (void)out_size;
}